// round 14
// baseline (speedup 1.0000x reference)
#include <cuda_runtime.h>
#include <cuda_bf16.h>
#include <cstdint>

#define B_SZ 2
#define SEQ 2048
#define ROWS (B_SZ * SEQ)          // 4096
#define D_MODEL 128
#define D_INNER 1024
#define NHEADS 8
#define HEADDIM 128
#define D_STATE 128
#define CONV_DIM (D_INNER + 2 * D_STATE)   // 1280
#define D_IN_PROJ (2 * D_INNER + 2 * D_STATE + NHEADS)  // 2312
#define EPS 1e-5f

#define QC 64
#define NCH (SEQ / QC)             // 32
#define NBH (B_SZ * NHEADS)        // 16

#define NT1 38                     // 38*64 = 2432 >= 2312; 19 tiles of 128

// prep (wstage + ln1) fused block ranges
#define WIN_BLK  ((NT1 * 64 * 64) / 256)     // 608
#define WOUT_BLK ((2 * 64 * 512) / 256)      // 256
#define WMLP_BLK ((2 * 64 * 64) / 256)       // 32
#define W_TOTAL  (WIN_BLK + WOUT_BLK + WMLP_BLK)   // 896
#define LN1_BLK  (ROWS / 8)                  // 512

// conv+dt fused block ranges (conv: 4ch x 4t per thread)
#define CONV_BLK ((B_SZ * (SEQ / 4) * (CONV_DIM / 4)) / 256)   // 1280
#define DT_BLK   ((NBH * NCH) / 4)                              // 128

#if defined(__CUDA_ARCH_FEAT_SM103_ALL) || defined(__CUDA_ARCH_FEAT_SM100_ALL) || defined(__CUDA_ARCH_FEAT_SM101_ALL)
#define HAS_TC 1
#else
#define HAS_TC 0
#endif

// ---------------- scratch ----------------
__device__ float g_zx[ROWS * D_IN_PROJ];
__device__ float g_xbc[ROWS * CONV_DIM];
__device__ float g_dtT[NBH * SEQ];
__device__ float g_cs[NBH * SEQ];
__device__ float g_G[B_SZ * NCH * QC * QC];
__device__ float g_T[NBH * NCH * HEADDIM * D_STATE];
__device__ float g_Sp[NBH * NCH * HEADDIM * D_STATE];
__device__ float g_Lam[NBH * NCH];
__device__ float g_y[ROWS * D_INNER];
__device__ float g_res2[ROWS * D_MODEL];

__device__ __nv_bfloat16 g_af1h[ROWS * D_MODEL];
__device__ __nv_bfloat16 g_af1l[ROWS * D_MODEL];
__device__ __nv_bfloat16 g_aggh[ROWS * D_INNER];
__device__ __nv_bfloat16 g_aggl[ROWS * D_INNER];
__device__ __nv_bfloat16 g_ah2h[ROWS * D_MODEL];
__device__ __nv_bfloat16 g_ah2l[ROWS * D_MODEL];
__device__ __nv_bfloat16 g_bwinh[NT1 * 64 * D_MODEL];
__device__ __nv_bfloat16 g_bwinl[NT1 * 64 * D_MODEL];
__device__ __nv_bfloat16 g_bwouth[2 * 8 * 64 * 128];
__device__ __nv_bfloat16 g_bwoutl[2 * 8 * 64 * 128];
__device__ __nv_bfloat16 g_bwmlph[2 * 64 * 128];
__device__ __nv_bfloat16 g_bwmlpl[2 * 64 * 128];

__device__ __forceinline__ float siluf(float v) {
    return v / (1.0f + expf(-v));
}

__device__ __forceinline__ int toff128(int r, int c) {
    int off = ((r >> 3) + (c >> 6) * 16) * 1024 + (r & 7) * 128 + (c & 63) * 2;
    return off ^ ((off >> 3) & 0x70);
}
__device__ __forceinline__ int toff64(int r, int c) {
    int off = ((r >> 3) + (c >> 6) * 8) * 1024 + (r & 7) * 128 + (c & 63) * 2;
    return off ^ ((off >> 3) & 0x70);
}

__device__ __forceinline__ void bf16_split(float v, uint32_t& hb, uint32_t& lb) {
    __nv_bfloat16 h = __float2bfloat16(v);
    float hf = __bfloat162float(h);
    __nv_bfloat16 l = __float2bfloat16(v - hf);
    hb = (uint32_t)__bfloat16_as_ushort(h);
    lb = (uint32_t)__bfloat16_as_ushort(l);
}

__device__ __forceinline__ void cp_async16(void* smem_dst, const void* gsrc) {
    unsigned saddr = (unsigned)__cvta_generic_to_shared(smem_dst);
    asm volatile("cp.async.cg.shared.global [%0], [%1], 16;" :: "r"(saddr), "l"(gsrc));
}
__device__ __forceinline__ void cp_commit() {
    asm volatile("cp.async.commit_group;");
}
template<int N>
__device__ __forceinline__ void cp_wait() {
    asm volatile("cp.async.wait_group %0;" :: "n"(N));
}

#if HAS_TC
__device__ __forceinline__ bool elect1() {
    uint32_t p;
    asm volatile("{\n\t.reg .pred p;\n\telect.sync _|p, 0xFFFFFFFF;\n\t"
                 "selp.b32 %0, 1, 0, p;\n\t}" : "=r"(p));
    return p != 0;
}
__device__ __forceinline__ void tc_alloc(uint32_t smem_res, uint32_t ncols) {
    asm volatile("tcgen05.alloc.cta_group::1.sync.aligned.shared::cta.b32 [%0], %1;"
                 :: "r"(smem_res), "r"(ncols) : "memory");
}
__device__ __forceinline__ void tc_dealloc(uint32_t tmem, uint32_t ncols) {
    asm volatile("tcgen05.dealloc.cta_group::1.sync.aligned.b32 %0, %1;"
                 :: "r"(tmem), "r"(ncols));
}
__device__ __forceinline__ void mbar_init(uint32_t mbar, uint32_t cnt) {
    asm volatile("mbarrier.init.shared.b64 [%0], %1;" :: "r"(mbar), "r"(cnt) : "memory");
}
__device__ __forceinline__ void mbar_wait(uint32_t mbar, uint32_t parity) {
    uint32_t done = 0;
    while (!done) {
        asm volatile(
            "{\n\t.reg .pred p;\n\t"
            "mbarrier.try_wait.parity.acquire.cta.shared::cta.b64 p, [%1], %2, 0x989680;\n\t"
            "selp.b32 %0, 1, 0, p;\n\t}"
            : "=r"(done) : "r"(mbar), "r"(parity) : "memory");
    }
}
__device__ __forceinline__ void tc_commit(uint32_t mbar) {
    asm volatile(
        "tcgen05.commit.cta_group::1.mbarrier::arrive::one.shared::cluster.b64 [%0];"
        :: "r"(mbar) : "memory");
}
__device__ __forceinline__ void mma_f16_ss(uint32_t d, uint64_t ad, uint64_t bd,
                                           uint32_t idesc, uint32_t en) {
    asm volatile(
        "{\n\t.reg .pred p;\n\tsetp.ne.u32 p, %5, 0;\n\t"
        "tcgen05.mma.cta_group::1.kind::f16 [%0], %1, %2, %3, {%4,%4,%4,%4}, p;\n\t}"
        :: "r"(d), "l"(ad), "l"(bd), "r"(idesc), "r"(0u), "r"(en) : "memory");
}
__device__ __forceinline__ uint64_t mk_desc(uint32_t saddr) {
    return ((uint64_t)2 << 61) | ((uint64_t)1 << 46) | ((uint64_t)64 << 32)
         | ((uint64_t)1 << 16) | (uint64_t)((saddr >> 4) & 0x3FFF);
}
__device__ __forceinline__ void ldtm_x32(uint32_t* r, uint32_t addr) {
    asm volatile(
        "tcgen05.ld.sync.aligned.32x32b.x32.b32 "
        "{%0,%1,%2,%3,%4,%5,%6,%7,%8,%9,%10,%11,%12,%13,%14,%15,"
        "%16,%17,%18,%19,%20,%21,%22,%23,%24,%25,%26,%27,%28,%29,%30,%31}, [%32];"
        : "=r"(r[0]), "=r"(r[1]), "=r"(r[2]), "=r"(r[3]),
          "=r"(r[4]), "=r"(r[5]), "=r"(r[6]), "=r"(r[7]),
          "=r"(r[8]), "=r"(r[9]), "=r"(r[10]), "=r"(r[11]),
          "=r"(r[12]), "=r"(r[13]), "=r"(r[14]), "=r"(r[15]),
          "=r"(r[16]), "=r"(r[17]), "=r"(r[18]), "=r"(r[19]),
          "=r"(r[20]), "=r"(r[21]), "=r"(r[22]), "=r"(r[23]),
          "=r"(r[24]), "=r"(r[25]), "=r"(r[26]), "=r"(r[27]),
          "=r"(r[28]), "=r"(r[29]), "=r"(r[30]), "=r"(r[31])
        : "r"(addr));
}
#endif // HAS_TC

#define TC_IDESC 0x8100490u
#define BUF_STRIDE 98304

// ---- gemm1: N=128 per CTA, KT=1; shares A tile across two N=64 MMA groups -
__global__ __launch_bounds__(256) void tc_gemm1(
    const __nv_bfloat16* __restrict__ Ah_, const __nv_bfloat16* __restrict__ Al_,
    const __nv_bfloat16* __restrict__ Bh_, const __nv_bfloat16* __restrict__ Bl_,
    float* __restrict__ C, int ldc, int N)
{
    extern __shared__ char smem[];
    const int tid = threadIdx.x;
    const int ntile = blockIdx.x, mtile = blockIdx.y;
    const uint32_t sbase = (uint32_t)__cvta_generic_to_shared(smem);

    const char* gAh = (const char*)Ah_ + (size_t)mtile * 32768;
    const char* gAl = (const char*)Al_ + (size_t)mtile * 32768;
    const char* gBh = (const char*)Bh_ + (size_t)(ntile * 2) * 16384;
    const char* gBl = (const char*)Bl_ + (size_t)(ntile * 2) * 16384;

#if HAS_TC
    const int wid = tid >> 5;
    const int lane = tid & 31;
    const uint32_t mbar = sbase + 8;

    if (wid == 0) tc_alloc(sbase, 128);
    if (tid == 0) mbar_init(mbar, 1);
    __syncthreads();
    uint32_t tmem;
    asm volatile("ld.shared.b32 %0, [%1];" : "=r"(tmem) : "r"(sbase));

    char* base = smem + 1024;
    #pragma unroll 4
    for (int i = tid; i < 2048; i += 256) {
        cp_async16(base + i * 16, gAh + i * 16);
        cp_async16(base + 32768 + i * 16, gAl + i * 16);
    }
    #pragma unroll 4
    for (int i = tid; i < 2048; i += 256) {   // B0H|B0L|B1H|B1L
        int half = i >> 10;
        int j = i & 1023;
        cp_async16(base + 65536 + half * 32768 + j * 16, gBh + (half ? 16384 : 0) + j * 16);
        cp_async16(base + 81920 + half * 32768 + j * 16, gBl + (half ? 16384 : 0) + j * 16);
    }
    cp_commit();
    cp_wait<0>();
    __syncthreads();
    asm volatile("fence.proxy.async.shared::cta;" ::: "memory");

    if (wid == 0) {
        asm volatile("tcgen05.fence::after_thread_sync;" ::: "memory");
        if (elect1()) {
            uint64_t dAh = mk_desc(sbase + 1024);
            uint64_t dAl = mk_desc(sbase + 1024 + 32768);
            uint64_t dB0h = mk_desc(sbase + 1024 + 65536);
            uint64_t dB0l = mk_desc(sbase + 1024 + 81920);
            uint64_t dB1h = mk_desc(sbase + 1024 + 98304);
            uint64_t dB1l = mk_desc(sbase + 1024 + 114688);
            #pragma unroll
            for (int ks = 0; ks < 8; ks++) {
                uint64_t oA = (ks < 4) ? (uint64_t)(ks * 2) : (uint64_t)(1024 + (ks - 4) * 2);
                uint64_t oB = (ks < 4) ? (uint64_t)(ks * 2) : (uint64_t)(512 + (ks - 4) * 2);
                uint32_t en = ks ? 1u : 0u;
                mma_f16_ss(tmem, dAh + oA, dB0h + oB, TC_IDESC, en);
                mma_f16_ss(tmem, dAh + oA, dB0l + oB, TC_IDESC, 1u);
                mma_f16_ss(tmem, dAl + oA, dB0h + oB, TC_IDESC, 1u);
                mma_f16_ss(tmem + 64, dAh + oA, dB1h + oB, TC_IDESC, en);
                mma_f16_ss(tmem + 64, dAh + oA, dB1l + oB, TC_IDESC, 1u);
                mma_f16_ss(tmem + 64, dAl + oA, dB1h + oB, TC_IDESC, 1u);
            }
            tc_commit(mbar);
        }
    }
    mbar_wait(mbar, 0);
    asm volatile("tcgen05.fence::after_thread_sync;" ::: "memory");

    uint32_t d0[32], d1[32];
    int chalf = (wid >> 2) * 32;
    ldtm_x32(d0, tmem + chalf);
    ldtm_x32(d1, tmem + 64 + chalf);
    asm volatile("tcgen05.wait::ld.sync.aligned;" ::: "memory");

    int row = mtile * 128 + (wid & 3) * 32 + lane;
    #pragma unroll
    for (int g = 0; g < 2; g++) {
        uint32_t* d = g ? d1 : d0;
        int col0 = ntile * 128 + g * 64 + chalf;
        float* cp = C + (size_t)row * ldc + col0;
        #pragma unroll
        for (int c = 0; c < 32; c += 4) {
            int col = col0 + c;
            if (col < N) {
                float4 v = make_float4(__uint_as_float(d[c]), __uint_as_float(d[c + 1]),
                                       __uint_as_float(d[c + 2]), __uint_as_float(d[c + 3]));
                *(float4*)(cp + c) = v;
            }
        }
    }
    __syncthreads();
    if (wid == 0) tc_dealloc(tmem, 128);
#else
    const int half = tid >> 7;
    const int r128 = tid & 127;
    char* base = smem + 1024;
    #pragma unroll 4
    for (int i = tid; i < 2048; i += 256) {
        cp_async16(base + i * 16, gAh + i * 16);
        cp_async16(base + 32768 + i * 16, gAl + i * 16);
    }
    for (int i = tid; i < 2048; i += 256) {
        int hh = i >> 10;
        int j = i & 1023;
        cp_async16(base + 65536 + hh * 32768 + j * 16, gBh + (hh ? 16384 : 0) + j * 16);
        cp_async16(base + 81920 + hh * 32768 + j * 16, gBl + (hh ? 16384 : 0) + j * 16);
    }
    cp_commit();
    cp_wait<0>();
    __syncthreads();

    for (int g = 0; g < 2; g++) {
        float vals[32];
        #pragma unroll
        for (int c = 0; c < 32; c++) vals[c] = 0.f;
        char* bB = base + 65536 + g * 32768;
        for (int k = 0; k < 128; k++) {
            int ao = toff128(r128, k);
            float a = __bfloat162float(*(const __nv_bfloat16*)(base + ao))
                    + __bfloat162float(*(const __nv_bfloat16*)(base + 32768 + ao));
            for (int n = 0; n < 32; n++) {
                int bo = toff64(half * 32 + n, k);
                float b = __bfloat162float(*(const __nv_bfloat16*)(bB + bo))
                        + __bfloat162float(*(const __nv_bfloat16*)(bB + 16384 + bo));
                vals[n] = fmaf(a, b, vals[n]);
            }
        }
        int row = mtile * 128 + r128;
        int col0 = ntile * 128 + g * 64 + half * 32;
        float* cp = C + (size_t)row * ldc + col0;
        for (int c = 0; c < 32; c++) {
            int col = col0 + c;
            if (col < N) cp[c] = vals[c];
        }
    }
#endif
}

// ---------------- GEMM (N=64/CTA): gemm2 (KT=8, dbuf) & gemm3 (KT=1) -------
template<bool RESID, bool BIAS, int KT>
__global__ __launch_bounds__(256) void tc_gemm(
    const __nv_bfloat16* __restrict__ Ah_, const __nv_bfloat16* __restrict__ Al_,
    const __nv_bfloat16* __restrict__ Bh_, const __nv_bfloat16* __restrict__ Bl_,
    float* __restrict__ C, int ldc, int N,
    const float* __restrict__ resid, const float* __restrict__ bias)
{
    extern __shared__ char smem[];
    const int tid = threadIdx.x;
    const int ntile = blockIdx.x, mtile = blockIdx.y;
    const uint32_t sbase = (uint32_t)__cvta_generic_to_shared(smem);

    const char* gAh = (const char*)Ah_ + (size_t)(mtile * KT) * 32768;
    const char* gAl = (const char*)Al_ + (size_t)(mtile * KT) * 32768;
    const char* gBh = (const char*)Bh_ + (size_t)(ntile * KT) * 16384;
    const char* gBl = (const char*)Bl_ + (size_t)(ntile * KT) * 16384;

    auto load_tile = [&](int kt, int buf) {
        char* base = smem + 1024 + buf * BUF_STRIDE;
        const char* ah = gAh + (size_t)kt * 32768;
        const char* al = gAl + (size_t)kt * 32768;
        const char* bh = gBh + (size_t)kt * 16384;
        const char* bl = gBl + (size_t)kt * 16384;
        #pragma unroll 4
        for (int i = tid; i < 2048; i += 256) {
            cp_async16(base + i * 16, ah + i * 16);
            cp_async16(base + 32768 + i * 16, al + i * 16);
        }
        #pragma unroll 2
        for (int i = tid; i < 1024; i += 256) {
            cp_async16(base + 65536 + i * 16, bh + i * 16);
            cp_async16(base + 81920 + i * 16, bl + i * 16);
        }
        cp_commit();
    };

#if HAS_TC
    const int wid = tid >> 5;
    const int lane = tid & 31;
    const uint32_t mbar = sbase + 8;

    if (wid == 0) tc_alloc(sbase, 64);
    if (tid == 0) mbar_init(mbar, 1);
    __syncthreads();
    uint32_t tmem;
    asm volatile("ld.shared.b32 %0, [%1];" : "=r"(tmem) : "r"(sbase));

    load_tile(0, 0);
    #pragma unroll 1
    for (int kt = 0; kt < KT; kt++) {
        int buf = (KT > 1) ? (kt & 1) : 0;
        if (KT > 1 && kt + 1 < KT) {
            load_tile(kt + 1, buf ^ 1);
            cp_wait<1>();
        } else {
            cp_wait<0>();
        }
        __syncthreads();
        asm volatile("fence.proxy.async.shared::cta;" ::: "memory");

        if (wid == 0) {
            asm volatile("tcgen05.fence::after_thread_sync;" ::: "memory");
            if (elect1()) {
                uint32_t bb = sbase + 1024 + buf * BUF_STRIDE;
                uint64_t dAh = mk_desc(bb);
                uint64_t dAl = mk_desc(bb + 32768);
                uint64_t dBh = mk_desc(bb + 65536);
                uint64_t dBl = mk_desc(bb + 81920);
                #pragma unroll
                for (int ks = 0; ks < 8; ks++) {
                    uint64_t oA = (ks < 4) ? (uint64_t)(ks * 2) : (uint64_t)(1024 + (ks - 4) * 2);
                    uint64_t oB = (ks < 4) ? (uint64_t)(ks * 2) : (uint64_t)(512 + (ks - 4) * 2);
                    uint32_t en = (kt || ks) ? 1u : 0u;
                    mma_f16_ss(tmem, dAh + oA, dBh + oB, TC_IDESC, en);
                    mma_f16_ss(tmem, dAh + oA, dBl + oB, TC_IDESC, 1u);
                    mma_f16_ss(tmem, dAl + oA, dBh + oB, TC_IDESC, 1u);
                }
                tc_commit(mbar);
            }
        }
        mbar_wait(mbar, kt & 1);
    }
    asm volatile("tcgen05.fence::after_thread_sync;" ::: "memory");

    uint32_t d[32];
    int chalf = (wid >> 2) * 32;
    ldtm_x32(d, tmem + chalf);
    asm volatile("tcgen05.wait::ld.sync.aligned;" ::: "memory");

    int row = mtile * 128 + (wid & 3) * 32 + lane;
    int col0 = ntile * 64 + chalf;
    float* cp = C + (size_t)row * ldc + col0;
    #pragma unroll
    for (int c = 0; c < 32; c += 4) {
        int col = col0 + c;
        if (col < N) {
            float4 v = make_float4(__uint_as_float(d[c]), __uint_as_float(d[c + 1]),
                                   __uint_as_float(d[c + 2]), __uint_as_float(d[c + 3]));
            if (RESID) {
                float4 r = *(const float4*)(resid + (size_t)row * ldc + col);
                v.x += r.x; v.y += r.y; v.z += r.z; v.w += r.w;
            }
            if (BIAS) {
                float4 b = *(const float4*)(bias + col);
                v.x += b.x; v.y += b.y; v.z += b.z; v.w += b.w;
            }
            *(float4*)(cp + c) = v;
        }
    }
    __syncthreads();
    if (wid == 0) tc_dealloc(tmem, 64);
#else
    const int half = tid >> 7;
    const int r128 = tid & 127;
    float vals[32];
    #pragma unroll
    for (int c = 0; c < 32; c++) vals[c] = 0.f;

    for (int kt = 0; kt < KT; kt++) {
        load_tile(kt, 0);
        cp_wait<0>();
        __syncthreads();
        char* base = smem + 1024;
        for (int k = 0; k < 128; k++) {
            int ao = toff128(r128, k);
            float a = __bfloat162float(*(const __nv_bfloat16*)(base + ao))
                    + __bfloat162float(*(const __nv_bfloat16*)(base + 32768 + ao));
            for (int n = 0; n < 32; n++) {
                int bo = toff64(half * 32 + n, k);
                float b = __bfloat162float(*(const __nv_bfloat16*)(base + 65536 + bo))
                        + __bfloat162float(*(const __nv_bfloat16*)(base + 81920 + bo));
                vals[n] = fmaf(a, b, vals[n]);
            }
        }
        __syncthreads();
    }
    int row = mtile * 128 + r128;
    int col0 = ntile * 64 + half * 32;
    float* cp = C + (size_t)row * ldc + col0;
    for (int c = 0; c < 32; c++) {
        int col = col0 + c;
        if (col < N) {
            float v = vals[c];
            if (RESID) v += resid[(size_t)row * ldc + col];
            if (BIAS)  v += bias[col];
            cp[c] = v;
        }
    }
#endif
}

// ------ LayerNorm body (warp-per-row) ------
__device__ __forceinline__ void ln_row(
    const float* __restrict__ x, const float* __restrict__ w,
    const float* __restrict__ b, __nv_bfloat16* __restrict__ Ah,
    __nv_bfloat16* __restrict__ Al, int row, int lane)
{
    const int c0 = lane * 4;
    float4 v = *(const float4*)(x + (size_t)row * D_MODEL + c0);
    float s = v.x + v.y + v.z + v.w;
    #pragma unroll
    for (int o = 16; o; o >>= 1) s += __shfl_xor_sync(0xffffffffu, s, o);
    float mean = s * (1.0f / 128.0f);

    float d0 = v.x - mean, d1 = v.y - mean, d2 = v.z - mean, d3 = v.w - mean;
    float q = d0 * d0 + d1 * d1 + d2 * d2 + d3 * d3;
    #pragma unroll
    for (int o = 16; o; o >>= 1) q += __shfl_xor_sync(0xffffffffu, q, o);
    float inv = rsqrtf(q * (1.0f / 128.0f) + EPS);

    float4 wv = *(const float4*)(w + c0);
    float4 bv = *(const float4*)(b + c0);
    float o0 = fmaf(d0 * inv, wv.x, bv.x);
    float o1 = fmaf(d1 * inv, wv.y, bv.y);
    float o2 = fmaf(d2 * inv, wv.z, bv.z);
    float o3 = fmaf(d3 * inv, wv.w, bv.w);

    uint32_t h0, l0, h1, l1, h2, l2, h3, l3;
    bf16_split(o0, h0, l0);
    bf16_split(o1, h1, l1);
    bf16_split(o2, h2, l2);
    bf16_split(o3, h3, l3);

    size_t tb = (size_t)(row >> 7) * 32768;
    int r = row & 127;
    int off0 = toff128(r, c0);
    int off1 = toff128(r, c0 + 2);
    *(uint32_t*)((char*)Ah + tb + off0) = h0 | (h1 << 16);
    *(uint32_t*)((char*)Al + tb + off0) = l0 | (l1 << 16);
    *(uint32_t*)((char*)Ah + tb + off1) = h2 | (h3 << 16);
    *(uint32_t*)((char*)Al + tb + off1) = l2 | (l3 << 16);
}

__global__ __launch_bounds__(256) void ln_stage_kernel(
    const float* __restrict__ x, const float* __restrict__ w,
    const float* __restrict__ b, __nv_bfloat16* __restrict__ Ah,
    __nv_bfloat16* __restrict__ Al)
{
    ln_row(x, w, b, Ah, Al, blockIdx.x * 8 + (threadIdx.x >> 5), threadIdx.x & 31);
}

// ------- W staging helper -------
__device__ __forceinline__ void wstage_do(
    const float* __restrict__ W, int Nreal, int K, int idx,
    __nv_bfloat16* __restrict__ Bh, __nv_bfloat16* __restrict__ Bl)
{
    int pairs_per_row = K >> 1;
    int n = idx / pairs_per_row;
    int k0 = (idx - n * pairs_per_row) * 2;
    float v0 = (n < Nreal) ? W[(size_t)n * K + k0] : 0.f;
    float v1 = (n < Nreal) ? W[(size_t)n * K + k0 + 1] : 0.f;
    uint32_t h0, l0, h1, l1;
    bf16_split(v0, h0, l0);
    bf16_split(v1, h1, l1);
    int ktiles = K >> 7;
    size_t tb = (size_t)((n >> 6) * ktiles + (k0 >> 7)) * 16384;
    int off = toff64(n & 63, k0 & 127);
    *(uint32_t*)((char*)Bh + tb + off) = h0 | (h1 << 16);
    *(uint32_t*)((char*)Bl + tb + off) = l0 | (l1 << 16);
}

// ---- prep: fused wstage x3 + ln1 ----
__global__ __launch_bounds__(256) void prep_kernel(
    const float* __restrict__ w_in, const float* __restrict__ w_out,
    const float* __restrict__ mlp_w,
    __nv_bfloat16* __restrict__ winh, __nv_bfloat16* __restrict__ winl,
    __nv_bfloat16* __restrict__ wouth, __nv_bfloat16* __restrict__ woutl,
    __nv_bfloat16* __restrict__ wmlph, __nv_bfloat16* __restrict__ wmlpl,
    const float* __restrict__ hidden, const float* __restrict__ ln1_w,
    const float* __restrict__ ln1_b,
    __nv_bfloat16* __restrict__ af1h, __nv_bfloat16* __restrict__ af1l)
{
    int bx = blockIdx.x;
    if (bx < WIN_BLK) {
        wstage_do(w_in, D_IN_PROJ, D_MODEL, bx * 256 + threadIdx.x, winh, winl);
    } else if (bx < WIN_BLK + WOUT_BLK) {
        wstage_do(w_out, D_MODEL, D_INNER, (bx - WIN_BLK) * 256 + threadIdx.x,
                  wouth, woutl);
    } else if (bx < W_TOTAL) {
        wstage_do(mlp_w, D_MODEL, D_MODEL, (bx - WIN_BLK - WOUT_BLK) * 256 + threadIdx.x,
                  wmlph, wmlpl);
    } else {
        int row = (bx - W_TOTAL) * 8 + (threadIdx.x >> 5);
        ln_row(hidden, ln1_w, ln1_b, af1h, af1l, row, threadIdx.x & 31);
    }
}

// ---- fused: conv (4ch x 4t float4) + [dt softplus + chunk cumsum] ----
__global__ __launch_bounds__(256) void conv_dt_kernel(
    const float* __restrict__ zx, const float* __restrict__ cw,
    const float* __restrict__ cb, float* __restrict__ out,
    const float* __restrict__ dt_bias, const float* __restrict__ A_log,
    float* __restrict__ dt_out, float* __restrict__ cs_out)
{
    __shared__ float s[4][QC];
    int bx = blockIdx.x;
    if (bx < CONV_BLK) {
        int idx = bx * 256 + threadIdx.x;
        int c4 = (idx % (CONV_DIM / 4)) * 4;
        int r = idx / (CONV_DIM / 4);
        int tq = r & ((SEQ / 4) - 1);
        int b = r / (SEQ / 4);
        int t0 = tq * 4;

        const float* col = zx + (size_t)b * SEQ * D_IN_PROJ + D_INNER + c4;
        float4 xv[7];
        #pragma unroll
        for (int k = 0; k < 7; k++) {
            int t = t0 - 3 + k;
            xv[k] = (t >= 0) ? *(const float4*)(col + (size_t)t * D_IN_PROJ)
                             : make_float4(0.f, 0.f, 0.f, 0.f);
        }
        float4 w[4];
        #pragma unroll
        for (int l = 0; l < 4; l++) w[l] = *(const float4*)(cw + (c4 + l) * 4);
        float4 bias4 = *(const float4*)(cb + c4);

        float* ob = out + ((size_t)(b * SEQ + t0)) * CONV_DIM + c4;
        #pragma unroll
        for (int j = 0; j < 4; j++) {
            float4 o;
            #pragma unroll
            for (int l = 0; l < 4; l++) {
                float acc = (&bias4.x)[l];
                acc = fmaf(w[l].x, (&xv[j].x)[l], acc);
                acc = fmaf(w[l].y, (&xv[j + 1].x)[l], acc);
                acc = fmaf(w[l].z, (&xv[j + 2].x)[l], acc);
                acc = fmaf(w[l].w, (&xv[j + 3].x)[l], acc);
                (&o.x)[l] = siluf(acc);
            }
            *(float4*)(ob + (size_t)j * CONV_DIM) = o;
        }
    } else {
        int g = threadIdx.x >> 6;
        int t = threadIdx.x & 63;
        int blk4 = (bx - CONV_BLK) * 4 + g;
        int bh = blk4 >> 5;
        int ch = blk4 & (NCH - 1);
        int b = bh >> 3;
        int h = bh & 7;

        int row = b * SEQ + ch * QC + t;
        float raw = zx[(size_t)row * D_IN_PROJ + (D_IN_PROJ - NHEADS) + h] + dt_bias[h];
        float dt = (raw > 20.0f) ? raw : log1pf(expf(raw));
        float A = -expf(A_log[h]);
        size_t o = (size_t)bh * SEQ + ch * QC + t;
        dt_out[o] = dt;
        s[g][t] = dt * A;
        __syncthreads();
        #pragma unroll
        for (int off = 1; off < QC; off <<= 1) {
            float v = (t >= off) ? s[g][t - off] : 0.f;
            __syncthreads();
            s[g][t] += v;
            __syncthreads();
        }
        cs_out[o] = s[g][t];
    }
}

// ---------- K_G: 4x parallel (grid = NCH x 4 x B_SZ), i-quarter per block --
// smem: Bn[128n][68] transposed B, Cn[128n][20] transposed quarter-C
__global__ __launch_bounds__(256) void ssd_g_kernel(
    const float* __restrict__ xbc, float* __restrict__ G)
{
    extern __shared__ float sm[];
    float* Bn = sm;                   // [128][68]
    float* Cn = sm + 128 * 68;        // [128][20]

    int c = blockIdx.x, iq = blockIdx.y, b = blockIdx.z;
    int tid = threadIdx.x;
    int t0 = c * QC;

    // load B transposed: all 64 rows
    for (int q = tid; q < QC * 32; q += 256) {
        int t = q >> 5;
        int n4 = (q & 31) * 4;
        const float* row = xbc + (size_t)(b * SEQ + t0 + t) * CONV_DIM + D_INNER;
        float4 bv = *(const float4*)(row + n4);
        #pragma unroll
        for (int l = 0; l < 4; l++) Bn[(n4 + l) * 68 + t] = (&bv.x)[l];
    }
    // load C transposed: 16-row quarter
    for (int q = tid; q < 16 * 32; q += 256) {
        int i = q >> 5;
        int n4 = (q & 31) * 4;
        const float* row = xbc + (size_t)(b * SEQ + t0 + iq * 16 + i) * CONV_DIM
                         + D_INNER + D_STATE;
        float4 cv = *(const float4*)(row + n4);
        #pragma unroll
        for (int l = 0; l < 4; l++) Cn[(n4 + l) * 20 + i] = (&cv.x)[l];
    }
    __syncthreads();

    int ty = tid >> 4, tx = tid & 15;    // ty = i (16), tx*4 = j0
    int j0 = tx * 4;
    float acc[4] = {0.f, 0.f, 0.f, 0.f};

    #pragma unroll 4
    for (int n = 0; n < D_STATE; n++) {
        float cf = Cn[n * 20 + ty];
        float4 bv = *(const float4*)&Bn[n * 68 + j0];
        acc[0] = fmaf(cf, bv.x, acc[0]);
        acc[1] = fmaf(cf, bv.y, acc[1]);
        acc[2] = fmaf(cf, bv.z, acc[2]);
        acc[3] = fmaf(cf, bv.w, acc[3]);
    }

    float* Gp = G + (size_t)(b * NCH + c) * QC * QC;
    float4 v = make_float4(acc[0], acc[1], acc[2], acc[3]);
    *(float4*)(Gp + (iq * 16 + ty) * QC + j0) = v;
}

// ------------ K_intra: 2 chunks per block ------------
__global__ __launch_bounds__(256) void ssd_intra_kernel(
    const float* __restrict__ xbc, const float* __restrict__ dt_t,
    const float* __restrict__ cs_g, const float* __restrict__ G,
    const float* __restrict__ D_skip,
    float* __restrict__ y_out, float* __restrict__ T_out,
    float* __restrict__ Lam_out)
{
    extern __shared__ float sm[];
    float* Wt = sm;
    float* Xj = Wt + QC * 68;
    float* Bj = Xj + QC * 132;
    float* s_cs = Bj + QC * 132;
    float* s_dt = s_cs + QC;
    float* s_el = s_dt + QC;

    int h = blockIdx.y, b = blockIdx.z;
    int tid = threadIdx.x;
    int bh = b * NHEADS + h;
    int ty = tid >> 4, tx = tid & 15;
    float Dsk = D_skip[h];

    for (int cc = 0; cc < 2; cc++) {
        int c = blockIdx.x + cc * 16;
        int t0 = c * QC;
        if (cc) __syncthreads();

        if (tid < QC) {
            s_cs[tid] = cs_g[(size_t)bh * SEQ + t0 + tid];
            s_dt[tid] = dt_t[(size_t)bh * SEQ + t0 + tid];
        }
        __syncthreads();
        if (tid < QC) s_el[tid] = __expf(s_cs[QC - 1] - s_cs[tid]) * s_dt[tid];
        if (tid == 0) Lam_out[bh * NCH + c] = __expf(s_cs[QC - 1]);

        for (int q = tid; q < QC * 32; q += 256) {
            int t = q >> 5;
            int n4 = (q & 31) * 4;
            const float* row = xbc + (size_t)(b * SEQ + t0 + t) * CONV_DIM;
            *(float4*)&Xj[t * 132 + n4] = *(const float4*)(row + h * HEADDIM + n4);
            *(float4*)&Bj[t * 132 + n4] = *(const float4*)(row + D_INNER + n4);
        }
        __syncthreads();

        {
            int i0 = ty * 4, j0 = tx * 4;
            const float* Gp = G + (size_t)(b * NCH + c) * QC * QC;
            #pragma unroll
            for (int ii = 0; ii < 4; ii++) {
                int i = i0 + ii;
                float4 gv = *(const float4*)(Gp + i * QC + j0);
                float gf[4] = {gv.x, gv.y, gv.z, gv.w};
                #pragma unroll
                for (int jj = 0; jj < 4; jj++) {
                    int j = j0 + jj;
                    float w = 0.f;
                    if (j <= i) w = __expf(s_cs[i] - s_cs[j]) * s_dt[j] * gf[jj];
                    Wt[j * 68 + i] = w;
                }
            }
        }
        __syncthreads();

        {
            int i0 = ty * 4, p0 = tx * 8;
            float acc[4][8];
            #pragma unroll
            for (int i = 0; i < 4; i++)
                #pragma unroll
                for (int p = 0; p < 8; p++) acc[i][p] = 0.f;

            int jmax = i0 + 4;
            for (int j = 0; j < jmax; j++) {
                float4 wv = *(const float4*)&Wt[j * 68 + i0];
                float4 xa = *(const float4*)&Xj[j * 132 + p0];
                float4 xb = *(const float4*)&Xj[j * 132 + p0 + 4];
                float wf[4] = {wv.x, wv.y, wv.z, wv.w};
                float xf[8] = {xa.x, xa.y, xa.z, xa.w, xb.x, xb.y, xb.z, xb.w};
                #pragma unroll
                for (int i = 0; i < 4; i++)
                    #pragma unroll
                    for (int p = 0; p < 8; p++)
                        acc[i][p] = fmaf(wf[i], xf[p], acc[i][p]);
            }
            #pragma unroll
            for (int ii = 0; ii < 4; ii++) {
                int i = i0 + ii;
                size_t row = (size_t)(b * SEQ + t0 + i);
                float* yp = y_out + row * D_INNER + h * HEADDIM + p0;
                float4 x0 = *(const float4*)&Xj[i * 132 + p0];
                float4 x1 = *(const float4*)&Xj[i * 132 + p0 + 4];
                float4 o0 = make_float4(fmaf(Dsk, x0.x, acc[ii][0]),
                                        fmaf(Dsk, x0.y, acc[ii][1]),
                                        fmaf(Dsk, x0.z, acc[ii][2]),
                                        fmaf(Dsk, x0.w, acc[ii][3]));
                float4 o1 = make_float4(fmaf(Dsk, x1.x, acc[ii][4]),
                                        fmaf(Dsk, x1.y, acc[ii][5]),
                                        fmaf(Dsk, x1.z, acc[ii][6]),
                                        fmaf(Dsk, x1.w, acc[ii][7]));
                *(float4*)yp = o0;
                *(float4*)(yp + 4) = o1;
            }
        }

        {
            int p0 = ty * 8, n0 = tx * 8;
            float acc[8][8];
            #pragma unroll
            for (int p = 0; p < 8; p++)
                #pragma unroll
                for (int n = 0; n < 8; n++) acc[p][n] = 0.f;

            #pragma unroll 2
            for (int j = 0; j < QC; j++) {
                float el = s_el[j];
                float4 xa = *(const float4*)&Xj[j * 132 + p0];
                float4 xb = *(const float4*)&Xj[j * 132 + p0 + 4];
                float4 ba = *(const float4*)&Bj[j * 132 + n0];
                float4 bb = *(const float4*)&Bj[j * 132 + n0 + 4];
                float xf[8] = {el * xa.x, el * xa.y, el * xa.z, el * xa.w,
                               el * xb.x, el * xb.y, el * xb.z, el * xb.w};
                float bf[8] = {ba.x, ba.y, ba.z, ba.w, bb.x, bb.y, bb.z, bb.w};
                #pragma unroll
                for (int p = 0; p < 8; p++)
                    #pragma unroll
                    for (int n = 0; n < 8; n++)
                        acc[p][n] = fmaf(xf[p], bf[n], acc[p][n]);
            }
            float* Tp = T_out + ((size_t)bh * NCH + c) * (HEADDIM * D_STATE);
            #pragma unroll
            for (int pp = 0; pp < 8; pp++) {
                float4 v0 = make_float4(acc[pp][0], acc[pp][1], acc[pp][2], acc[pp][3]);
                float4 v1 = make_float4(acc[pp][4], acc[pp][5], acc[pp][6], acc[pp][7]);
                *(float4*)(Tp + (p0 + pp) * D_STATE + n0) = v0;
                *(float4*)(Tp + (p0 + pp) * D_STATE + n0 + 4) = v1;
            }
        }
    }
}

// ---------------- K_inter ----------------
__global__ __launch_bounds__(256) void ssd_inter_kernel(
    const float* __restrict__ T, const float* __restrict__ Lam,
    float* __restrict__ Sp)
{
    int gid = blockIdx.x * 256 + threadIdx.x;
    int bh = gid >> 12;
    int pn = gid & 4095;
    const float4* Tb = (const float4*)(T + ((size_t)bh << 19)) + pn;
    float4* Sb = (float4*)(Sp + ((size_t)bh << 19)) + pn;
    const float* Lb = Lam + bh * NCH;

    float4 S = make_float4(0.f, 0.f, 0.f, 0.f);
    #pragma unroll 4
    for (int c = 0; c < NCH; c++) {
        if (c) Sb[(size_t)c << 12] = S;
        float4 Tv = Tb[(size_t)c << 12];
        float lam = Lb[c];
        S.x = fmaf(lam, S.x, Tv.x);
        S.y = fmaf(lam, S.y, Tv.y);
        S.z = fmaf(lam, S.z, Tv.z);
        S.w = fmaf(lam, S.w, Tv.w);
    }
}

// ------------ K_out: 2 chunks per block ------------
__global__ __launch_bounds__(256) void ssd_out_kernel(
    const float* __restrict__ xbc, const float* __restrict__ cs_g,
    const float* __restrict__ Sp, float* __restrict__ y_out)
{
    extern __shared__ float sm[];
    float* Cn = sm;
    float* Spn = Cn + 128 * 68;
    float* s_cs = Spn + 128 * 132;

    int h = blockIdx.y, b = blockIdx.z;
    int tid = threadIdx.x;
    int bh = b * NHEADS + h;
    int ty = tid >> 4, tx = tid & 15;
    int i0 = ty * 4, p0 = tx * 8;

    for (int cc = 0; cc < 2; cc++) {
        int c = blockIdx.x + 1 + cc * 16;
        if (c >= NCH) break;
        int t0 = c * QC;
        if (cc) __syncthreads();

        if (tid < QC) s_cs[tid] = cs_g[(size_t)bh * SEQ + t0 + tid];

        for (int q = tid; q < QC * 32; q += 256) {
            int t = q >> 5;
            int n4 = (q & 31) * 4;
            const float* row = xbc + (size_t)(b * SEQ + t0 + t) * CONV_DIM
                             + D_INNER + D_STATE;
            float4 v = *(const float4*)(row + n4);
            #pragma unroll
            for (int l = 0; l < 4; l++) Cn[(n4 + l) * 68 + t] = (&v.x)[l];
        }
        const float* Spsrc = Sp + ((size_t)bh * NCH + c) * (HEADDIM * D_STATE);
        for (int q = tid; q < HEADDIM * 32; q += 256) {
            int p = q >> 5;
            int n4 = (q & 31) * 4;
            float4 v = *(const float4*)(Spsrc + p * D_STATE + n4);
            #pragma unroll
            for (int l = 0; l < 4; l++) Spn[(n4 + l) * 132 + p] = (&v.x)[l];
        }
        __syncthreads();

        float acc[4][8];
        #pragma unroll
        for (int i = 0; i < 4; i++)
            #pragma unroll
            for (int p = 0; p < 8; p++) acc[i][p] = 0.f;

        #pragma unroll 2
        for (int n = 0; n < D_STATE; n++) {
            float4 cv = *(const float4*)&Cn[n * 68 + i0];
            float4 sa = *(const float4*)&Spn[n * 132 + p0];
            float4 sb = *(const float4*)&Spn[n * 132 + p0 + 4];
            float cf[4] = {cv.x, cv.y, cv.z, cv.w};
            float sf[8] = {sa.x, sa.y, sa.z, sa.w, sb.x, sb.y, sb.z, sb.w};
            #pragma unroll
            for (int i = 0; i < 4; i++)
                #pragma unroll
                for (int p = 0; p < 8; p++)
                    acc[i][p] = fmaf(cf[i], sf[p], acc[i][p]);
        }

        #pragma unroll
        for (int ii = 0; ii < 4; ii++) {
            int i = i0 + ii;
            float e = __expf(s_cs[i]);
            size_t row = (size_t)(b * SEQ + t0 + i);
            float* yp = y_out + row * D_INNER + h * HEADDIM + p0;
            float4 y0 = *(const float4*)yp;
            float4 y1 = *(const float4*)(yp + 4);
            y0.x = fmaf(e, acc[ii][0], y0.x);
            y0.y = fmaf(e, acc[ii][1], y0.y);
            y0.z = fmaf(e, acc[ii][2], y0.z);
            y0.w = fmaf(e, acc[ii][3], y0.w);
            y1.x = fmaf(e, acc[ii][4], y1.x);
            y1.y = fmaf(e, acc[ii][5], y1.y);
            y1.z = fmaf(e, acc[ii][6], y1.z);
            y1.w = fmaf(e, acc[ii][7], y1.w);
            *(float4*)yp = y0;
            *(float4*)(yp + 4) = y1;
        }
    }
}

// ---- gate + RMSNorm -> bf16 hi/lo A-tiles (K=1024) -----------
__global__ __launch_bounds__(256) void gate_stage_kernel(
    const float* __restrict__ y, const float* __restrict__ zx,
    const float* __restrict__ gw, __nv_bfloat16* __restrict__ Ah,
    __nv_bfloat16* __restrict__ Al)
{
    int row = blockIdx.x;
    int tid = threadIdx.x;
    int d = tid * 4;
    __shared__ float sm[8];

    float4 y4 = *(const float4*)(y + (size_t)row * D_INNER + d);
    float4 z4 = *(const float4*)(zx + (size_t)row * D_IN_PROJ + d);
    float g0 = y4.x * siluf(z4.x);
    float g1 = y4.y * siluf(z4.y);
    float g2 = y4.z * siluf(z4.z);
    float g3 = y4.w * siluf(z4.w);

    float ss = g0 * g0 + g1 * g1 + g2 * g2 + g3 * g3;
    #pragma unroll
    for (int o = 16; o; o >>= 1) ss += __shfl_xor_sync(0xffffffffu, ss, o);
    if ((tid & 31) == 0) sm[tid >> 5] = ss;
    __syncthreads();
    float tot = 0.f;
    #pragma unroll
    for (int i = 0; i < 8; i++) tot += sm[i];
    float scale = rsqrtf(tot * (1.0f / (float)D_INNER) + EPS);

    float4 w4 = *(const float4*)(gw + d);
    float v0 = g0 * scale * w4.x, v1 = g1 * scale * w4.y;
    float v2 = g2 * scale * w4.z, v3 = g3 * scale * w4.w;

    uint32_t h0, l0, h1, l1, h2, l2, h3, l3;
    bf16_split(v0, h0, l0);
    bf16_split(v1, h1, l1);
    bf16_split(v2, h2, l2);
    bf16_split(v3, h3, l3);

    int ktile = d >> 7;
    int cl = d & 127;
    size_t tb = (size_t)((row >> 7) * 8 + ktile) * 32768;
    int r = row & 127;
    int off0 = toff128(r, cl);
    int off1 = toff128(r, cl + 2);
    *(uint32_t*)((char*)Ah + tb + off0) = h0 | (h1 << 16);
    *(uint32_t*)((char*)Al + tb + off0) = l0 | (l1 << 16);
    *(uint32_t*)((char*)Ah + tb + off1) = h2 | (h3 << 16);
    *(uint32_t*)((char*)Al + tb + off1) = l2 | (l3 << 16);
}

// ---------------- launch ----------------
extern "C" void kernel_launch(void* const* d_in, const int* in_sizes, int n_in,
                              void* d_out, int out_size)
{
    const float* hidden  = (const float*)d_in[0];
    const float* w_in    = (const float*)d_in[1];
    const float* conv_w  = (const float*)d_in[2];
    const float* conv_b  = (const float*)d_in[3];
    const float* dt_bias = (const float*)d_in[4];
    const float* A_log   = (const float*)d_in[5];
    const float* D_skip  = (const float*)d_in[6];
    const float* gnorm_w = (const float*)d_in[7];
    const float* w_out   = (const float*)d_in[8];
    const float* ln1_w   = (const float*)d_in[9];
    const float* ln1_b   = (const float*)d_in[10];
    const float* ln2_w   = (const float*)d_in[11];
    const float* ln2_b   = (const float*)d_in[12];
    const float* mlp_w   = (const float*)d_in[13];
    const float* mlp_b   = (const float*)d_in[14];
    float* outp = (float*)d_out;

    float *zx, *xbc, *dtT, *csv, *Gm, *Tm, *Spm, *Lam, *y, *res2;
    __nv_bfloat16 *af1h, *af1l, *aggh, *aggl, *ah2h, *ah2l;
    __nv_bfloat16 *bwinh, *bwinl, *bwouth, *bwoutl, *bwmlph, *bwmlpl;
    cudaGetSymbolAddress((void**)&zx,   g_zx);
    cudaGetSymbolAddress((void**)&xbc,  g_xbc);
    cudaGetSymbolAddress((void**)&dtT,  g_dtT);
    cudaGetSymbolAddress((void**)&csv,  g_cs);
    cudaGetSymbolAddress((void**)&Gm,   g_G);
    cudaGetSymbolAddress((void**)&Tm,   g_T);
    cudaGetSymbolAddress((void**)&Spm,  g_Sp);
    cudaGetSymbolAddress((void**)&Lam,  g_Lam);
    cudaGetSymbolAddress((void**)&y,    g_y);
    cudaGetSymbolAddress((void**)&res2, g_res2);
    cudaGetSymbolAddress((void**)&af1h, g_af1h);
    cudaGetSymbolAddress((void**)&af1l, g_af1l);
    cudaGetSymbolAddress((void**)&aggh, g_aggh);
    cudaGetSymbolAddress((void**)&aggl, g_aggl);
    cudaGetSymbolAddress((void**)&ah2h, g_ah2h);
    cudaGetSymbolAddress((void**)&ah2l, g_ah2l);
    cudaGetSymbolAddress((void**)&bwinh, g_bwinh);
    cudaGetSymbolAddress((void**)&bwinl, g_bwinl);
    cudaGetSymbolAddress((void**)&bwouth, g_bwouth);
    cudaGetSymbolAddress((void**)&bwoutl, g_bwoutl);
    cudaGetSymbolAddress((void**)&bwmlph, g_bwmlph);
    cudaGetSymbolAddress((void**)&bwmlpl, g_bwmlpl);

    const int smem_gemm1n = 1024 + 65536 + 65536;    // 132096
    const int smem_gemm1  = 1024 + BUF_STRIDE;       // 99328
    const int smem_gemm2  = 1024 + 2 * BUF_STRIDE;   // 197632
    const int smem_g      = (128 * 68 + 128 * 20) * 4;   // 45056
    const int smem_intra  = (QC * 68 + QC * 132 * 2 + 3 * QC) * 4;
    const int smem_out    = (128 * 68 + 128 * 132 + QC) * 4;
    cudaFuncSetAttribute(tc_gemm1,
        cudaFuncAttributeMaxDynamicSharedMemorySize, smem_gemm1n);
    cudaFuncSetAttribute(tc_gemm<true, false, 8>,
        cudaFuncAttributeMaxDynamicSharedMemorySize, smem_gemm2);
    cudaFuncSetAttribute(tc_gemm<false, true, 1>,
        cudaFuncAttributeMaxDynamicSharedMemorySize, smem_gemm1);
    cudaFuncSetAttribute(ssd_g_kernel,
        cudaFuncAttributeMaxDynamicSharedMemorySize, smem_g);
    cudaFuncSetAttribute(ssd_intra_kernel,
        cudaFuncAttributeMaxDynamicSharedMemorySize, smem_intra);
    cudaFuncSetAttribute(ssd_out_kernel,
        cudaFuncAttributeMaxDynamicSharedMemorySize, smem_out);

    // 0) prep: fused weight stages + ln1
    prep_kernel<<<W_TOTAL + LN1_BLK, 256>>>(
        w_in, w_out, mlp_w, bwinh, bwinl, bwouth, bwoutl, bwmlph, bwmlpl,
        hidden, ln1_w, ln1_b, af1h, af1l);

    // 1) in_proj (tcgen05, N=128/CTA)
    {
        dim3 grid(NT1 / 2, ROWS / 128);     // (19, 32)
        tc_gemm1<<<grid, 256, smem_gemm1n>>>(
            af1h, af1l, bwinh, bwinl, zx, D_IN_PROJ, D_IN_PROJ);
    }

    // 2) fused conv (vectorized) + dt/cumsum
    conv_dt_kernel<<<CONV_BLK + DT_BLK, 256>>>(
        zx, conv_w, conv_b, xbc, dt_bias, A_log, dtT, csv);

    // 3) chunked SSD
    {
        dim3 gg_(NCH, 4, B_SZ);                    // 256 blocks (was 64)
        ssd_g_kernel<<<gg_, 256, smem_g>>>(xbc, Gm);
        dim3 gi(NCH / 2, NHEADS, B_SZ);
        ssd_intra_kernel<<<gi, 256, smem_intra>>>(xbc, dtT, csv, Gm, D_skip,
                                                  y, Tm, Lam);
        ssd_inter_kernel<<<(NBH * HEADDIM * D_STATE / 4) / 256, 256>>>(Tm, Lam, Spm);
        dim3 go(16, NHEADS, B_SZ);
        ssd_out_kernel<<<go, 256, smem_out>>>(xbc, csv, Spm, y);
    }

    // 4) gate + rmsnorm -> bf16 tiles
    gate_stage_kernel<<<ROWS, 256>>>(y, zx, gnorm_w, aggh, aggl);

    // 5) out_proj + residual (tcgen05, double-buffered K-loop 8)
    {
        dim3 grid(2, ROWS / 128);
        tc_gemm<true, false, 8><<<grid, 256, smem_gemm2>>>(
            aggh, aggl, bwouth, bwoutl, res2, D_MODEL, D_MODEL,
            hidden, nullptr);
    }

    // 6) ln2 -> bf16 tiles
    ln_stage_kernel<<<ROWS / 8, 256>>>(res2, ln2_w, ln2_b, ah2h, ah2l);

    // 7) mlp (tcgen05)
    {
        dim3 grid(2, ROWS / 128);
        tc_gemm<false, true, 1><<<grid, 256, smem_gemm1>>>(
            ah2h, ah2l, bwmlph, bwmlpl, outp, D_MODEL, D_MODEL,
            nullptr, mlp_b);
    }
    (void)in_sizes; (void)n_in; (void)out_size;
}

// round 15
// speedup vs baseline: 1.0087x; 1.0087x over previous
#include <cuda_runtime.h>
#include <cuda_bf16.h>
#include <cstdint>

#define B_SZ 2
#define SEQ 2048
#define ROWS (B_SZ * SEQ)          // 4096
#define D_MODEL 128
#define D_INNER 1024
#define NHEADS 8
#define HEADDIM 128
#define D_STATE 128
#define CONV_DIM (D_INNER + 2 * D_STATE)   // 1280
#define D_IN_PROJ (2 * D_INNER + 2 * D_STATE + NHEADS)  // 2312
#define EPS 1e-5f

#define QC 64
#define NCH (SEQ / QC)             // 32
#define NBH (B_SZ * NHEADS)        // 16

#define NT1 38                     // 38*64 = 2432 >= 2312; 19 tiles of 128

// prep (wstage + ln1) fused block ranges
#define WIN_BLK  ((NT1 * 64 * 64) / 256)     // 608
#define WOUT_BLK ((2 * 64 * 512) / 256)      // 256
#define WMLP_BLK ((2 * 64 * 64) / 256)       // 32
#define W_TOTAL  (WIN_BLK + WOUT_BLK + WMLP_BLK)   // 896
#define LN1_BLK  (ROWS / 8)                  // 512

// conv+dt fused block ranges (conv: 4ch x 4t per thread)
#define CONV_BLK ((B_SZ * (SEQ / 4) * (CONV_DIM / 4)) / 256)   // 1280
#define DT_BLK   ((NBH * NCH) / 4)                              // 128

#if defined(__CUDA_ARCH_FEAT_SM103_ALL) || defined(__CUDA_ARCH_FEAT_SM100_ALL) || defined(__CUDA_ARCH_FEAT_SM101_ALL)
#define HAS_TC 1
#else
#define HAS_TC 0
#endif

// ---------------- scratch ----------------
__device__ float g_zx[ROWS * D_IN_PROJ];
__device__ float g_xbc[ROWS * CONV_DIM];
__device__ float g_dtT[NBH * SEQ];
__device__ float g_cs[NBH * SEQ];
__device__ float g_G[B_SZ * NCH * QC * QC];
__device__ float g_T[NBH * NCH * HEADDIM * D_STATE];
__device__ float g_Sp[NBH * NCH * HEADDIM * D_STATE];
__device__ float g_Lam[NBH * NCH];
__device__ float g_y[ROWS * D_INNER];
__device__ float g_res2[ROWS * D_MODEL];

__device__ __nv_bfloat16 g_af1h[ROWS * D_MODEL];
__device__ __nv_bfloat16 g_af1l[ROWS * D_MODEL];
__device__ __nv_bfloat16 g_aggh[ROWS * D_INNER];
__device__ __nv_bfloat16 g_aggl[ROWS * D_INNER];
__device__ __nv_bfloat16 g_ah2h[ROWS * D_MODEL];
__device__ __nv_bfloat16 g_ah2l[ROWS * D_MODEL];
__device__ __nv_bfloat16 g_bwinh[NT1 * 64 * D_MODEL];
__device__ __nv_bfloat16 g_bwinl[NT1 * 64 * D_MODEL];
__device__ __nv_bfloat16 g_bwouth[2 * 8 * 64 * 128];
__device__ __nv_bfloat16 g_bwoutl[2 * 8 * 64 * 128];
__device__ __nv_bfloat16 g_bwmlph[2 * 64 * 128];
__device__ __nv_bfloat16 g_bwmlpl[2 * 64 * 128];

__device__ __forceinline__ float siluf(float v) {
    return v / (1.0f + expf(-v));
}

__device__ __forceinline__ int toff128(int r, int c) {
    int off = ((r >> 3) + (c >> 6) * 16) * 1024 + (r & 7) * 128 + (c & 63) * 2;
    return off ^ ((off >> 3) & 0x70);
}
__device__ __forceinline__ int toff64(int r, int c) {
    int off = ((r >> 3) + (c >> 6) * 8) * 1024 + (r & 7) * 128 + (c & 63) * 2;
    return off ^ ((off >> 3) & 0x70);
}

__device__ __forceinline__ void bf16_split(float v, uint32_t& hb, uint32_t& lb) {
    __nv_bfloat16 h = __float2bfloat16(v);
    float hf = __bfloat162float(h);
    __nv_bfloat16 l = __float2bfloat16(v - hf);
    hb = (uint32_t)__bfloat16_as_ushort(h);
    lb = (uint32_t)__bfloat16_as_ushort(l);
}

__device__ __forceinline__ void cp_async16(void* smem_dst, const void* gsrc) {
    unsigned saddr = (unsigned)__cvta_generic_to_shared(smem_dst);
    asm volatile("cp.async.cg.shared.global [%0], [%1], 16;" :: "r"(saddr), "l"(gsrc));
}
__device__ __forceinline__ void cp_commit() {
    asm volatile("cp.async.commit_group;");
}
template<int N>
__device__ __forceinline__ void cp_wait() {
    asm volatile("cp.async.wait_group %0;" :: "n"(N));
}

#if HAS_TC
__device__ __forceinline__ bool elect1() {
    uint32_t p;
    asm volatile("{\n\t.reg .pred p;\n\telect.sync _|p, 0xFFFFFFFF;\n\t"
                 "selp.b32 %0, 1, 0, p;\n\t}" : "=r"(p));
    return p != 0;
}
__device__ __forceinline__ void tc_alloc(uint32_t smem_res, uint32_t ncols) {
    asm volatile("tcgen05.alloc.cta_group::1.sync.aligned.shared::cta.b32 [%0], %1;"
                 :: "r"(smem_res), "r"(ncols) : "memory");
}
__device__ __forceinline__ void tc_dealloc(uint32_t tmem, uint32_t ncols) {
    asm volatile("tcgen05.dealloc.cta_group::1.sync.aligned.b32 %0, %1;"
                 :: "r"(tmem), "r"(ncols));
}
__device__ __forceinline__ void mbar_init(uint32_t mbar, uint32_t cnt) {
    asm volatile("mbarrier.init.shared.b64 [%0], %1;" :: "r"(mbar), "r"(cnt) : "memory");
}
__device__ __forceinline__ void mbar_wait(uint32_t mbar, uint32_t parity) {
    uint32_t done = 0;
    while (!done) {
        asm volatile(
            "{\n\t.reg .pred p;\n\t"
            "mbarrier.try_wait.parity.acquire.cta.shared::cta.b64 p, [%1], %2, 0x989680;\n\t"
            "selp.b32 %0, 1, 0, p;\n\t}"
            : "=r"(done) : "r"(mbar), "r"(parity) : "memory");
    }
}
__device__ __forceinline__ void tc_commit(uint32_t mbar) {
    asm volatile(
        "tcgen05.commit.cta_group::1.mbarrier::arrive::one.shared::cluster.b64 [%0];"
        :: "r"(mbar) : "memory");
}
__device__ __forceinline__ void mma_f16_ss(uint32_t d, uint64_t ad, uint64_t bd,
                                           uint32_t idesc, uint32_t en) {
    asm volatile(
        "{\n\t.reg .pred p;\n\tsetp.ne.u32 p, %5, 0;\n\t"
        "tcgen05.mma.cta_group::1.kind::f16 [%0], %1, %2, %3, {%4,%4,%4,%4}, p;\n\t}"
        :: "r"(d), "l"(ad), "l"(bd), "r"(idesc), "r"(0u), "r"(en) : "memory");
}
__device__ __forceinline__ uint64_t mk_desc(uint32_t saddr) {
    return ((uint64_t)2 << 61) | ((uint64_t)1 << 46) | ((uint64_t)64 << 32)
         | ((uint64_t)1 << 16) | (uint64_t)((saddr >> 4) & 0x3FFF);
}
__device__ __forceinline__ void ldtm_x32(uint32_t* r, uint32_t addr) {
    asm volatile(
        "tcgen05.ld.sync.aligned.32x32b.x32.b32 "
        "{%0,%1,%2,%3,%4,%5,%6,%7,%8,%9,%10,%11,%12,%13,%14,%15,"
        "%16,%17,%18,%19,%20,%21,%22,%23,%24,%25,%26,%27,%28,%29,%30,%31}, [%32];"
        : "=r"(r[0]), "=r"(r[1]), "=r"(r[2]), "=r"(r[3]),
          "=r"(r[4]), "=r"(r[5]), "=r"(r[6]), "=r"(r[7]),
          "=r"(r[8]), "=r"(r[9]), "=r"(r[10]), "=r"(r[11]),
          "=r"(r[12]), "=r"(r[13]), "=r"(r[14]), "=r"(r[15]),
          "=r"(r[16]), "=r"(r[17]), "=r"(r[18]), "=r"(r[19]),
          "=r"(r[20]), "=r"(r[21]), "=r"(r[22]), "=r"(r[23]),
          "=r"(r[24]), "=r"(r[25]), "=r"(r[26]), "=r"(r[27]),
          "=r"(r[28]), "=r"(r[29]), "=r"(r[30]), "=r"(r[31])
        : "r"(addr));
}
#endif // HAS_TC

#define TC_IDESC 0x8100490u
#define BUF_STRIDE 98304

// ---- gemm1: N=128 per CTA, KT=1; shares A tile across two N=64 MMA groups -
__global__ __launch_bounds__(256) void tc_gemm1(
    const __nv_bfloat16* __restrict__ Ah_, const __nv_bfloat16* __restrict__ Al_,
    const __nv_bfloat16* __restrict__ Bh_, const __nv_bfloat16* __restrict__ Bl_,
    float* __restrict__ C, int ldc, int N)
{
    extern __shared__ char smem[];
    const int tid = threadIdx.x;
    const int ntile = blockIdx.x, mtile = blockIdx.y;
    const uint32_t sbase = (uint32_t)__cvta_generic_to_shared(smem);

    const char* gAh = (const char*)Ah_ + (size_t)mtile * 32768;
    const char* gAl = (const char*)Al_ + (size_t)mtile * 32768;
    const char* gBh = (const char*)Bh_ + (size_t)(ntile * 2) * 16384;
    const char* gBl = (const char*)Bl_ + (size_t)(ntile * 2) * 16384;

#if HAS_TC
    const int wid = tid >> 5;
    const int lane = tid & 31;
    const uint32_t mbar = sbase + 8;

    if (wid == 0) tc_alloc(sbase, 128);
    if (tid == 0) mbar_init(mbar, 1);
    __syncthreads();
    uint32_t tmem;
    asm volatile("ld.shared.b32 %0, [%1];" : "=r"(tmem) : "r"(sbase));

    char* base = smem + 1024;
    #pragma unroll 4
    for (int i = tid; i < 2048; i += 256) {
        cp_async16(base + i * 16, gAh + i * 16);
        cp_async16(base + 32768 + i * 16, gAl + i * 16);
    }
    #pragma unroll 4
    for (int i = tid; i < 2048; i += 256) {   // B0H|B0L|B1H|B1L
        int half = i >> 10;
        int j = i & 1023;
        cp_async16(base + 65536 + half * 32768 + j * 16, gBh + (half ? 16384 : 0) + j * 16);
        cp_async16(base + 81920 + half * 32768 + j * 16, gBl + (half ? 16384 : 0) + j * 16);
    }
    cp_commit();
    cp_wait<0>();
    __syncthreads();
    asm volatile("fence.proxy.async.shared::cta;" ::: "memory");

    if (wid == 0) {
        asm volatile("tcgen05.fence::after_thread_sync;" ::: "memory");
        if (elect1()) {
            uint64_t dAh = mk_desc(sbase + 1024);
            uint64_t dAl = mk_desc(sbase + 1024 + 32768);
            uint64_t dB0h = mk_desc(sbase + 1024 + 65536);
            uint64_t dB0l = mk_desc(sbase + 1024 + 81920);
            uint64_t dB1h = mk_desc(sbase + 1024 + 98304);
            uint64_t dB1l = mk_desc(sbase + 1024 + 114688);
            #pragma unroll
            for (int ks = 0; ks < 8; ks++) {
                uint64_t oA = (ks < 4) ? (uint64_t)(ks * 2) : (uint64_t)(1024 + (ks - 4) * 2);
                uint64_t oB = (ks < 4) ? (uint64_t)(ks * 2) : (uint64_t)(512 + (ks - 4) * 2);
                uint32_t en = ks ? 1u : 0u;
                mma_f16_ss(tmem, dAh + oA, dB0h + oB, TC_IDESC, en);
                mma_f16_ss(tmem, dAh + oA, dB0l + oB, TC_IDESC, 1u);
                mma_f16_ss(tmem, dAl + oA, dB0h + oB, TC_IDESC, 1u);
                mma_f16_ss(tmem + 64, dAh + oA, dB1h + oB, TC_IDESC, en);
                mma_f16_ss(tmem + 64, dAh + oA, dB1l + oB, TC_IDESC, 1u);
                mma_f16_ss(tmem + 64, dAl + oA, dB1h + oB, TC_IDESC, 1u);
            }
            tc_commit(mbar);
        }
    }
    mbar_wait(mbar, 0);
    asm volatile("tcgen05.fence::after_thread_sync;" ::: "memory");

    uint32_t d0[32], d1[32];
    int chalf = (wid >> 2) * 32;
    ldtm_x32(d0, tmem + chalf);
    ldtm_x32(d1, tmem + 64 + chalf);
    asm volatile("tcgen05.wait::ld.sync.aligned;" ::: "memory");

    int row = mtile * 128 + (wid & 3) * 32 + lane;
    #pragma unroll
    for (int g = 0; g < 2; g++) {
        uint32_t* d = g ? d1 : d0;
        int col0 = ntile * 128 + g * 64 + chalf;
        float* cp = C + (size_t)row * ldc + col0;
        #pragma unroll
        for (int c = 0; c < 32; c += 4) {
            int col = col0 + c;
            if (col < N) {
                float4 v = make_float4(__uint_as_float(d[c]), __uint_as_float(d[c + 1]),
                                       __uint_as_float(d[c + 2]), __uint_as_float(d[c + 3]));
                *(float4*)(cp + c) = v;
            }
        }
    }
    __syncthreads();
    if (wid == 0) tc_dealloc(tmem, 128);
#else
    const int half = tid >> 7;
    const int r128 = tid & 127;
    char* base = smem + 1024;
    #pragma unroll 4
    for (int i = tid; i < 2048; i += 256) {
        cp_async16(base + i * 16, gAh + i * 16);
        cp_async16(base + 32768 + i * 16, gAl + i * 16);
    }
    for (int i = tid; i < 2048; i += 256) {
        int hh = i >> 10;
        int j = i & 1023;
        cp_async16(base + 65536 + hh * 32768 + j * 16, gBh + (hh ? 16384 : 0) + j * 16);
        cp_async16(base + 81920 + hh * 32768 + j * 16, gBl + (hh ? 16384 : 0) + j * 16);
    }
    cp_commit();
    cp_wait<0>();
    __syncthreads();

    for (int g = 0; g < 2; g++) {
        float vals[32];
        #pragma unroll
        for (int c = 0; c < 32; c++) vals[c] = 0.f;
        char* bB = base + 65536 + g * 32768;
        for (int k = 0; k < 128; k++) {
            int ao = toff128(r128, k);
            float a = __bfloat162float(*(const __nv_bfloat16*)(base + ao))
                    + __bfloat162float(*(const __nv_bfloat16*)(base + 32768 + ao));
            for (int n = 0; n < 32; n++) {
                int bo = toff64(half * 32 + n, k);
                float b = __bfloat162float(*(const __nv_bfloat16*)(bB + bo))
                        + __bfloat162float(*(const __nv_bfloat16*)(bB + 16384 + bo));
                vals[n] = fmaf(a, b, vals[n]);
            }
        }
        int row = mtile * 128 + r128;
        int col0 = ntile * 128 + g * 64 + half * 32;
        float* cp = C + (size_t)row * ldc + col0;
        for (int c = 0; c < 32; c++) {
            int col = col0 + c;
            if (col < N) cp[c] = vals[c];
        }
    }
#endif
}

// ---------------- GEMM (N=64/CTA): gemm2 (KT=8, dbuf) & gemm3 (KT=1) -------
template<bool RESID, bool BIAS, int KT>
__global__ __launch_bounds__(256) void tc_gemm(
    const __nv_bfloat16* __restrict__ Ah_, const __nv_bfloat16* __restrict__ Al_,
    const __nv_bfloat16* __restrict__ Bh_, const __nv_bfloat16* __restrict__ Bl_,
    float* __restrict__ C, int ldc, int N,
    const float* __restrict__ resid, const float* __restrict__ bias)
{
    extern __shared__ char smem[];
    const int tid = threadIdx.x;
    const int ntile = blockIdx.x, mtile = blockIdx.y;
    const uint32_t sbase = (uint32_t)__cvta_generic_to_shared(smem);

    const char* gAh = (const char*)Ah_ + (size_t)(mtile * KT) * 32768;
    const char* gAl = (const char*)Al_ + (size_t)(mtile * KT) * 32768;
    const char* gBh = (const char*)Bh_ + (size_t)(ntile * KT) * 16384;
    const char* gBl = (const char*)Bl_ + (size_t)(ntile * KT) * 16384;

    auto load_tile = [&](int kt, int buf) {
        char* base = smem + 1024 + buf * BUF_STRIDE;
        const char* ah = gAh + (size_t)kt * 32768;
        const char* al = gAl + (size_t)kt * 32768;
        const char* bh = gBh + (size_t)kt * 16384;
        const char* bl = gBl + (size_t)kt * 16384;
        #pragma unroll 4
        for (int i = tid; i < 2048; i += 256) {
            cp_async16(base + i * 16, ah + i * 16);
            cp_async16(base + 32768 + i * 16, al + i * 16);
        }
        #pragma unroll 2
        for (int i = tid; i < 1024; i += 256) {
            cp_async16(base + 65536 + i * 16, bh + i * 16);
            cp_async16(base + 81920 + i * 16, bl + i * 16);
        }
        cp_commit();
    };

#if HAS_TC
    const int wid = tid >> 5;
    const int lane = tid & 31;
    const uint32_t mbar = sbase + 8;

    if (wid == 0) tc_alloc(sbase, 64);
    if (tid == 0) mbar_init(mbar, 1);
    __syncthreads();
    uint32_t tmem;
    asm volatile("ld.shared.b32 %0, [%1];" : "=r"(tmem) : "r"(sbase));

    load_tile(0, 0);
    #pragma unroll 1
    for (int kt = 0; kt < KT; kt++) {
        int buf = (KT > 1) ? (kt & 1) : 0;
        if (KT > 1 && kt + 1 < KT) {
            load_tile(kt + 1, buf ^ 1);
            cp_wait<1>();
        } else {
            cp_wait<0>();
        }
        __syncthreads();
        asm volatile("fence.proxy.async.shared::cta;" ::: "memory");

        if (wid == 0) {
            asm volatile("tcgen05.fence::after_thread_sync;" ::: "memory");
            if (elect1()) {
                uint32_t bb = sbase + 1024 + buf * BUF_STRIDE;
                uint64_t dAh = mk_desc(bb);
                uint64_t dAl = mk_desc(bb + 32768);
                uint64_t dBh = mk_desc(bb + 65536);
                uint64_t dBl = mk_desc(bb + 81920);
                #pragma unroll
                for (int ks = 0; ks < 8; ks++) {
                    uint64_t oA = (ks < 4) ? (uint64_t)(ks * 2) : (uint64_t)(1024 + (ks - 4) * 2);
                    uint64_t oB = (ks < 4) ? (uint64_t)(ks * 2) : (uint64_t)(512 + (ks - 4) * 2);
                    uint32_t en = (kt || ks) ? 1u : 0u;
                    mma_f16_ss(tmem, dAh + oA, dBh + oB, TC_IDESC, en);
                    mma_f16_ss(tmem, dAh + oA, dBl + oB, TC_IDESC, 1u);
                    mma_f16_ss(tmem, dAl + oA, dBh + oB, TC_IDESC, 1u);
                }
                tc_commit(mbar);
            }
        }
        mbar_wait(mbar, kt & 1);
    }
    asm volatile("tcgen05.fence::after_thread_sync;" ::: "memory");

    uint32_t d[32];
    int chalf = (wid >> 2) * 32;
    ldtm_x32(d, tmem + chalf);
    asm volatile("tcgen05.wait::ld.sync.aligned;" ::: "memory");

    int row = mtile * 128 + (wid & 3) * 32 + lane;
    int col0 = ntile * 64 + chalf;
    float* cp = C + (size_t)row * ldc + col0;
    #pragma unroll
    for (int c = 0; c < 32; c += 4) {
        int col = col0 + c;
        if (col < N) {
            float4 v = make_float4(__uint_as_float(d[c]), __uint_as_float(d[c + 1]),
                                   __uint_as_float(d[c + 2]), __uint_as_float(d[c + 3]));
            if (RESID) {
                float4 r = *(const float4*)(resid + (size_t)row * ldc + col);
                v.x += r.x; v.y += r.y; v.z += r.z; v.w += r.w;
            }
            if (BIAS) {
                float4 b = *(const float4*)(bias + col);
                v.x += b.x; v.y += b.y; v.z += b.z; v.w += b.w;
            }
            *(float4*)(cp + c) = v;
        }
    }
    __syncthreads();
    if (wid == 0) tc_dealloc(tmem, 64);
#else
    const int half = tid >> 7;
    const int r128 = tid & 127;
    float vals[32];
    #pragma unroll
    for (int c = 0; c < 32; c++) vals[c] = 0.f;

    for (int kt = 0; kt < KT; kt++) {
        load_tile(kt, 0);
        cp_wait<0>();
        __syncthreads();
        char* base = smem + 1024;
        for (int k = 0; k < 128; k++) {
            int ao = toff128(r128, k);
            float a = __bfloat162float(*(const __nv_bfloat16*)(base + ao))
                    + __bfloat162float(*(const __nv_bfloat16*)(base + 32768 + ao));
            for (int n = 0; n < 32; n++) {
                int bo = toff64(half * 32 + n, k);
                float b = __bfloat162float(*(const __nv_bfloat16*)(base + 65536 + bo))
                        + __bfloat162float(*(const __nv_bfloat16*)(base + 81920 + bo));
                vals[n] = fmaf(a, b, vals[n]);
            }
        }
        __syncthreads();
    }
    int row = mtile * 128 + r128;
    int col0 = ntile * 64 + half * 32;
    float* cp = C + (size_t)row * ldc + col0;
    for (int c = 0; c < 32; c++) {
        int col = col0 + c;
        if (col < N) {
            float v = vals[c];
            if (RESID) v += resid[(size_t)row * ldc + col];
            if (BIAS)  v += bias[col];
            cp[c] = v;
        }
    }
#endif
}

// ------ LayerNorm body (warp-per-row) ------
__device__ __forceinline__ void ln_row(
    const float* __restrict__ x, const float* __restrict__ w,
    const float* __restrict__ b, __nv_bfloat16* __restrict__ Ah,
    __nv_bfloat16* __restrict__ Al, int row, int lane)
{
    const int c0 = lane * 4;
    float4 v = *(const float4*)(x + (size_t)row * D_MODEL + c0);
    float s = v.x + v.y + v.z + v.w;
    #pragma unroll
    for (int o = 16; o; o >>= 1) s += __shfl_xor_sync(0xffffffffu, s, o);
    float mean = s * (1.0f / 128.0f);

    float d0 = v.x - mean, d1 = v.y - mean, d2 = v.z - mean, d3 = v.w - mean;
    float q = d0 * d0 + d1 * d1 + d2 * d2 + d3 * d3;
    #pragma unroll
    for (int o = 16; o; o >>= 1) q += __shfl_xor_sync(0xffffffffu, q, o);
    float inv = rsqrtf(q * (1.0f / 128.0f) + EPS);

    float4 wv = *(const float4*)(w + c0);
    float4 bv = *(const float4*)(b + c0);
    float o0 = fmaf(d0 * inv, wv.x, bv.x);
    float o1 = fmaf(d1 * inv, wv.y, bv.y);
    float o2 = fmaf(d2 * inv, wv.z, bv.z);
    float o3 = fmaf(d3 * inv, wv.w, bv.w);

    uint32_t h0, l0, h1, l1, h2, l2, h3, l3;
    bf16_split(o0, h0, l0);
    bf16_split(o1, h1, l1);
    bf16_split(o2, h2, l2);
    bf16_split(o3, h3, l3);

    size_t tb = (size_t)(row >> 7) * 32768;
    int r = row & 127;
    int off0 = toff128(r, c0);
    int off1 = toff128(r, c0 + 2);
    *(uint32_t*)((char*)Ah + tb + off0) = h0 | (h1 << 16);
    *(uint32_t*)((char*)Al + tb + off0) = l0 | (l1 << 16);
    *(uint32_t*)((char*)Ah + tb + off1) = h2 | (h3 << 16);
    *(uint32_t*)((char*)Al + tb + off1) = l2 | (l3 << 16);
}

__global__ __launch_bounds__(256) void ln_stage_kernel(
    const float* __restrict__ x, const float* __restrict__ w,
    const float* __restrict__ b, __nv_bfloat16* __restrict__ Ah,
    __nv_bfloat16* __restrict__ Al)
{
    ln_row(x, w, b, Ah, Al, blockIdx.x * 8 + (threadIdx.x >> 5), threadIdx.x & 31);
}

// ------- W staging helper -------
__device__ __forceinline__ void wstage_do(
    const float* __restrict__ W, int Nreal, int K, int idx,
    __nv_bfloat16* __restrict__ Bh, __nv_bfloat16* __restrict__ Bl)
{
    int pairs_per_row = K >> 1;
    int n = idx / pairs_per_row;
    int k0 = (idx - n * pairs_per_row) * 2;
    float v0 = (n < Nreal) ? W[(size_t)n * K + k0] : 0.f;
    float v1 = (n < Nreal) ? W[(size_t)n * K + k0 + 1] : 0.f;
    uint32_t h0, l0, h1, l1;
    bf16_split(v0, h0, l0);
    bf16_split(v1, h1, l1);
    int ktiles = K >> 7;
    size_t tb = (size_t)((n >> 6) * ktiles + (k0 >> 7)) * 16384;
    int off = toff64(n & 63, k0 & 127);
    *(uint32_t*)((char*)Bh + tb + off) = h0 | (h1 << 16);
    *(uint32_t*)((char*)Bl + tb + off) = l0 | (l1 << 16);
}

// ---- prep: fused wstage x3 + ln1 ----
__global__ __launch_bounds__(256) void prep_kernel(
    const float* __restrict__ w_in, const float* __restrict__ w_out,
    const float* __restrict__ mlp_w,
    __nv_bfloat16* __restrict__ winh, __nv_bfloat16* __restrict__ winl,
    __nv_bfloat16* __restrict__ wouth, __nv_bfloat16* __restrict__ woutl,
    __nv_bfloat16* __restrict__ wmlph, __nv_bfloat16* __restrict__ wmlpl,
    const float* __restrict__ hidden, const float* __restrict__ ln1_w,
    const float* __restrict__ ln1_b,
    __nv_bfloat16* __restrict__ af1h, __nv_bfloat16* __restrict__ af1l)
{
    int bx = blockIdx.x;
    if (bx < WIN_BLK) {
        wstage_do(w_in, D_IN_PROJ, D_MODEL, bx * 256 + threadIdx.x, winh, winl);
    } else if (bx < WIN_BLK + WOUT_BLK) {
        wstage_do(w_out, D_MODEL, D_INNER, (bx - WIN_BLK) * 256 + threadIdx.x,
                  wouth, woutl);
    } else if (bx < W_TOTAL) {
        wstage_do(mlp_w, D_MODEL, D_MODEL, (bx - WIN_BLK - WOUT_BLK) * 256 + threadIdx.x,
                  wmlph, wmlpl);
    } else {
        int row = (bx - W_TOTAL) * 8 + (threadIdx.x >> 5);
        ln_row(hidden, ln1_w, ln1_b, af1h, af1l, row, threadIdx.x & 31);
    }
}

// ---- fused: conv (4ch x 4t float4) + [dt softplus + chunk cumsum] ----
__global__ __launch_bounds__(256) void conv_dt_kernel(
    const float* __restrict__ zx, const float* __restrict__ cw,
    const float* __restrict__ cb, float* __restrict__ out,
    const float* __restrict__ dt_bias, const float* __restrict__ A_log,
    float* __restrict__ dt_out, float* __restrict__ cs_out)
{
    __shared__ float s[4][QC];
    int bx = blockIdx.x;
    if (bx < CONV_BLK) {
        int idx = bx * 256 + threadIdx.x;
        int c4 = (idx % (CONV_DIM / 4)) * 4;
        int r = idx / (CONV_DIM / 4);
        int tq = r & ((SEQ / 4) - 1);
        int b = r / (SEQ / 4);
        int t0 = tq * 4;

        const float* col = zx + (size_t)b * SEQ * D_IN_PROJ + D_INNER + c4;
        float4 xv[7];
        #pragma unroll
        for (int k = 0; k < 7; k++) {
            int t = t0 - 3 + k;
            xv[k] = (t >= 0) ? *(const float4*)(col + (size_t)t * D_IN_PROJ)
                             : make_float4(0.f, 0.f, 0.f, 0.f);
        }
        float4 w[4];
        #pragma unroll
        for (int l = 0; l < 4; l++) w[l] = *(const float4*)(cw + (c4 + l) * 4);
        float4 bias4 = *(const float4*)(cb + c4);

        float* ob = out + ((size_t)(b * SEQ + t0)) * CONV_DIM + c4;
        #pragma unroll
        for (int j = 0; j < 4; j++) {
            float4 o;
            #pragma unroll
            for (int l = 0; l < 4; l++) {
                float acc = (&bias4.x)[l];
                acc = fmaf(w[l].x, (&xv[j].x)[l], acc);
                acc = fmaf(w[l].y, (&xv[j + 1].x)[l], acc);
                acc = fmaf(w[l].z, (&xv[j + 2].x)[l], acc);
                acc = fmaf(w[l].w, (&xv[j + 3].x)[l], acc);
                (&o.x)[l] = siluf(acc);
            }
            *(float4*)(ob + (size_t)j * CONV_DIM) = o;
        }
    } else {
        int g = threadIdx.x >> 6;
        int t = threadIdx.x & 63;
        int blk4 = (bx - CONV_BLK) * 4 + g;
        int bh = blk4 >> 5;
        int ch = blk4 & (NCH - 1);
        int b = bh >> 3;
        int h = bh & 7;

        int row = b * SEQ + ch * QC + t;
        float raw = zx[(size_t)row * D_IN_PROJ + (D_IN_PROJ - NHEADS) + h] + dt_bias[h];
        float dt = (raw > 20.0f) ? raw : log1pf(expf(raw));
        float A = -expf(A_log[h]);
        size_t o = (size_t)bh * SEQ + ch * QC + t;
        dt_out[o] = dt;
        s[g][t] = dt * A;
        __syncthreads();
        #pragma unroll
        for (int off = 1; off < QC; off <<= 1) {
            float v = (t >= off) ? s[g][t - off] : 0.f;
            __syncthreads();
            s[g][t] += v;
            __syncthreads();
        }
        cs_out[o] = s[g][t];
    }
}

// ---------- K_G: 512 threads, 2x4 tile, grid (NCH, B_SZ) -------------------
// smem: Bn[128n][68], Cn[128n][68] transposed. 16 warps for latency hiding.
__global__ __launch_bounds__(512) void ssd_g_kernel(
    const float* __restrict__ xbc, float* __restrict__ G)
{
    extern __shared__ float sm[];
    float* Cn = sm;                  // [128][68]
    float* Bn = sm + 128 * 68;       // [128][68]

    int c = blockIdx.x, b = blockIdx.y;
    int tid = threadIdx.x;
    int t0 = c * QC;

    for (int q = tid; q < QC * 32; q += 512) {
        int t = q >> 5;
        int n4 = (q & 31) * 4;
        const float* row = xbc + (size_t)(b * SEQ + t0 + t) * CONV_DIM + D_INNER;
        float4 bv = *(const float4*)(row + n4);
        float4 cv = *(const float4*)(row + D_STATE + n4);
        #pragma unroll
        for (int l = 0; l < 4; l++) {
            Bn[(n4 + l) * 68 + t] = (&bv.x)[l];
            Cn[(n4 + l) * 68 + t] = (&cv.x)[l];
        }
    }
    __syncthreads();

    int ty = tid >> 4, tx = tid & 15;     // ty: 0..31 (i-pairs), tx: j-tile
    int i0 = ty * 2, j0 = tx * 4;
    float acc[2][4];
    #pragma unroll
    for (int i = 0; i < 2; i++)
        #pragma unroll
        for (int j = 0; j < 4; j++) acc[i][j] = 0.f;

    #pragma unroll 4
    for (int n = 0; n < D_STATE; n++) {
        float2 cv = *(const float2*)&Cn[n * 68 + i0];
        float4 bv = *(const float4*)&Bn[n * 68 + j0];
        float cf[2] = {cv.x, cv.y};
        float bf[4] = {bv.x, bv.y, bv.z, bv.w};
        #pragma unroll
        for (int i = 0; i < 2; i++)
            #pragma unroll
            for (int j = 0; j < 4; j++)
                acc[i][j] = fmaf(cf[i], bf[j], acc[i][j]);
    }

    float* Gp = G + (size_t)(b * NCH + c) * QC * QC;
    #pragma unroll
    for (int i = 0; i < 2; i++) {
        float4 v = make_float4(acc[i][0], acc[i][1], acc[i][2], acc[i][3]);
        *(float4*)(Gp + (i0 + i) * QC + j0) = v;
    }
}

// ------------ K_intra: 2 chunks per block ------------
__global__ __launch_bounds__(256) void ssd_intra_kernel(
    const float* __restrict__ xbc, const float* __restrict__ dt_t,
    const float* __restrict__ cs_g, const float* __restrict__ G,
    const float* __restrict__ D_skip,
    float* __restrict__ y_out, float* __restrict__ T_out,
    float* __restrict__ Lam_out)
{
    extern __shared__ float sm[];
    float* Wt = sm;
    float* Xj = Wt + QC * 68;
    float* Bj = Xj + QC * 132;
    float* s_cs = Bj + QC * 132;
    float* s_dt = s_cs + QC;
    float* s_el = s_dt + QC;

    int h = blockIdx.y, b = blockIdx.z;
    int tid = threadIdx.x;
    int bh = b * NHEADS + h;
    int ty = tid >> 4, tx = tid & 15;
    float Dsk = D_skip[h];

    for (int cc = 0; cc < 2; cc++) {
        int c = blockIdx.x + cc * 16;
        int t0 = c * QC;
        if (cc) __syncthreads();

        if (tid < QC) {
            s_cs[tid] = cs_g[(size_t)bh * SEQ + t0 + tid];
            s_dt[tid] = dt_t[(size_t)bh * SEQ + t0 + tid];
        }
        __syncthreads();
        if (tid < QC) s_el[tid] = __expf(s_cs[QC - 1] - s_cs[tid]) * s_dt[tid];
        if (tid == 0) Lam_out[bh * NCH + c] = __expf(s_cs[QC - 1]);

        for (int q = tid; q < QC * 32; q += 256) {
            int t = q >> 5;
            int n4 = (q & 31) * 4;
            const float* row = xbc + (size_t)(b * SEQ + t0 + t) * CONV_DIM;
            *(float4*)&Xj[t * 132 + n4] = *(const float4*)(row + h * HEADDIM + n4);
            *(float4*)&Bj[t * 132 + n4] = *(const float4*)(row + D_INNER + n4);
        }
        __syncthreads();

        {
            int i0 = ty * 4, j0 = tx * 4;
            const float* Gp = G + (size_t)(b * NCH + c) * QC * QC;
            #pragma unroll
            for (int ii = 0; ii < 4; ii++) {
                int i = i0 + ii;
                float4 gv = *(const float4*)(Gp + i * QC + j0);
                float gf[4] = {gv.x, gv.y, gv.z, gv.w};
                #pragma unroll
                for (int jj = 0; jj < 4; jj++) {
                    int j = j0 + jj;
                    float w = 0.f;
                    if (j <= i) w = __expf(s_cs[i] - s_cs[j]) * s_dt[j] * gf[jj];
                    Wt[j * 68 + i] = w;
                }
            }
        }
        __syncthreads();

        {
            int i0 = ty * 4, p0 = tx * 8;
            float acc[4][8];
            #pragma unroll
            for (int i = 0; i < 4; i++)
                #pragma unroll
                for (int p = 0; p < 8; p++) acc[i][p] = 0.f;

            int jmax = i0 + 4;
            for (int j = 0; j < jmax; j++) {
                float4 wv = *(const float4*)&Wt[j * 68 + i0];
                float4 xa = *(const float4*)&Xj[j * 132 + p0];
                float4 xb = *(const float4*)&Xj[j * 132 + p0 + 4];
                float wf[4] = {wv.x, wv.y, wv.z, wv.w};
                float xf[8] = {xa.x, xa.y, xa.z, xa.w, xb.x, xb.y, xb.z, xb.w};
                #pragma unroll
                for (int i = 0; i < 4; i++)
                    #pragma unroll
                    for (int p = 0; p < 8; p++)
                        acc[i][p] = fmaf(wf[i], xf[p], acc[i][p]);
            }
            #pragma unroll
            for (int ii = 0; ii < 4; ii++) {
                int i = i0 + ii;
                size_t row = (size_t)(b * SEQ + t0 + i);
                float* yp = y_out + row * D_INNER + h * HEADDIM + p0;
                float4 x0 = *(const float4*)&Xj[i * 132 + p0];
                float4 x1 = *(const float4*)&Xj[i * 132 + p0 + 4];
                float4 o0 = make_float4(fmaf(Dsk, x0.x, acc[ii][0]),
                                        fmaf(Dsk, x0.y, acc[ii][1]),
                                        fmaf(Dsk, x0.z, acc[ii][2]),
                                        fmaf(Dsk, x0.w, acc[ii][3]));
                float4 o1 = make_float4(fmaf(Dsk, x1.x, acc[ii][4]),
                                        fmaf(Dsk, x1.y, acc[ii][5]),
                                        fmaf(Dsk, x1.z, acc[ii][6]),
                                        fmaf(Dsk, x1.w, acc[ii][7]));
                *(float4*)yp = o0;
                *(float4*)(yp + 4) = o1;
            }
        }

        {
            int p0 = ty * 8, n0 = tx * 8;
            float acc[8][8];
            #pragma unroll
            for (int p = 0; p < 8; p++)
                #pragma unroll
                for (int n = 0; n < 8; n++) acc[p][n] = 0.f;

            #pragma unroll 2
            for (int j = 0; j < QC; j++) {
                float el = s_el[j];
                float4 xa = *(const float4*)&Xj[j * 132 + p0];
                float4 xb = *(const float4*)&Xj[j * 132 + p0 + 4];
                float4 ba = *(const float4*)&Bj[j * 132 + n0];
                float4 bb = *(const float4*)&Bj[j * 132 + n0 + 4];
                float xf[8] = {el * xa.x, el * xa.y, el * xa.z, el * xa.w,
                               el * xb.x, el * xb.y, el * xb.z, el * xb.w};
                float bf[8] = {ba.x, ba.y, ba.z, ba.w, bb.x, bb.y, bb.z, bb.w};
                #pragma unroll
                for (int p = 0; p < 8; p++)
                    #pragma unroll
                    for (int n = 0; n < 8; n++)
                        acc[p][n] = fmaf(xf[p], bf[n], acc[p][n]);
            }
            float* Tp = T_out + ((size_t)bh * NCH + c) * (HEADDIM * D_STATE);
            #pragma unroll
            for (int pp = 0; pp < 8; pp++) {
                float4 v0 = make_float4(acc[pp][0], acc[pp][1], acc[pp][2], acc[pp][3]);
                float4 v1 = make_float4(acc[pp][4], acc[pp][5], acc[pp][6], acc[pp][7]);
                *(float4*)(Tp + (p0 + pp) * D_STATE + n0) = v0;
                *(float4*)(Tp + (p0 + pp) * D_STATE + n0 + 4) = v1;
            }
        }
    }
}

// ---------------- K_inter ----------------
__global__ __launch_bounds__(256) void ssd_inter_kernel(
    const float* __restrict__ T, const float* __restrict__ Lam,
    float* __restrict__ Sp)
{
    int gid = blockIdx.x * 256 + threadIdx.x;
    int bh = gid >> 12;
    int pn = gid & 4095;
    const float4* Tb = (const float4*)(T + ((size_t)bh << 19)) + pn;
    float4* Sb = (float4*)(Sp + ((size_t)bh << 19)) + pn;
    const float* Lb = Lam + bh * NCH;

    float4 S = make_float4(0.f, 0.f, 0.f, 0.f);
    #pragma unroll 4
    for (int c = 0; c < NCH; c++) {
        if (c) Sb[(size_t)c << 12] = S;
        float4 Tv = Tb[(size_t)c << 12];
        float lam = Lb[c];
        S.x = fmaf(lam, S.x, Tv.x);
        S.y = fmaf(lam, S.y, Tv.y);
        S.z = fmaf(lam, S.z, Tv.z);
        S.w = fmaf(lam, S.w, Tv.w);
    }
}

// ------------ K_out: 2 chunks per block ------------
__global__ __launch_bounds__(256) void ssd_out_kernel(
    const float* __restrict__ xbc, const float* __restrict__ cs_g,
    const float* __restrict__ Sp, float* __restrict__ y_out)
{
    extern __shared__ float sm[];
    float* Cn = sm;
    float* Spn = Cn + 128 * 68;
    float* s_cs = Spn + 128 * 132;

    int h = blockIdx.y, b = blockIdx.z;
    int tid = threadIdx.x;
    int bh = b * NHEADS + h;
    int ty = tid >> 4, tx = tid & 15;
    int i0 = ty * 4, p0 = tx * 8;

    for (int cc = 0; cc < 2; cc++) {
        int c = blockIdx.x + 1 + cc * 16;
        if (c >= NCH) break;
        int t0 = c * QC;
        if (cc) __syncthreads();

        if (tid < QC) s_cs[tid] = cs_g[(size_t)bh * SEQ + t0 + tid];

        for (int q = tid; q < QC * 32; q += 256) {
            int t = q >> 5;
            int n4 = (q & 31) * 4;
            const float* row = xbc + (size_t)(b * SEQ + t0 + t) * CONV_DIM
                             + D_INNER + D_STATE;
            float4 v = *(const float4*)(row + n4);
            #pragma unroll
            for (int l = 0; l < 4; l++) Cn[(n4 + l) * 68 + t] = (&v.x)[l];
        }
        const float* Spsrc = Sp + ((size_t)bh * NCH + c) * (HEADDIM * D_STATE);
        for (int q = tid; q < HEADDIM * 32; q += 256) {
            int p = q >> 5;
            int n4 = (q & 31) * 4;
            float4 v = *(const float4*)(Spsrc + p * D_STATE + n4);
            #pragma unroll
            for (int l = 0; l < 4; l++) Spn[(n4 + l) * 132 + p] = (&v.x)[l];
        }
        __syncthreads();

        float acc[4][8];
        #pragma unroll
        for (int i = 0; i < 4; i++)
            #pragma unroll
            for (int p = 0; p < 8; p++) acc[i][p] = 0.f;

        #pragma unroll 2
        for (int n = 0; n < D_STATE; n++) {
            float4 cv = *(const float4*)&Cn[n * 68 + i0];
            float4 sa = *(const float4*)&Spn[n * 132 + p0];
            float4 sb = *(const float4*)&Spn[n * 132 + p0 + 4];
            float cf[4] = {cv.x, cv.y, cv.z, cv.w};
            float sf[8] = {sa.x, sa.y, sa.z, sa.w, sb.x, sb.y, sb.z, sb.w};
            #pragma unroll
            for (int i = 0; i < 4; i++)
                #pragma unroll
                for (int p = 0; p < 8; p++)
                    acc[i][p] = fmaf(cf[i], sf[p], acc[i][p]);
        }

        #pragma unroll
        for (int ii = 0; ii < 4; ii++) {
            int i = i0 + ii;
            float e = __expf(s_cs[i]);
            size_t row = (size_t)(b * SEQ + t0 + i);
            float* yp = y_out + row * D_INNER + h * HEADDIM + p0;
            float4 y0 = *(const float4*)yp;
            float4 y1 = *(const float4*)(yp + 4);
            y0.x = fmaf(e, acc[ii][0], y0.x);
            y0.y = fmaf(e, acc[ii][1], y0.y);
            y0.z = fmaf(e, acc[ii][2], y0.z);
            y0.w = fmaf(e, acc[ii][3], y0.w);
            y1.x = fmaf(e, acc[ii][4], y1.x);
            y1.y = fmaf(e, acc[ii][5], y1.y);
            y1.z = fmaf(e, acc[ii][6], y1.z);
            y1.w = fmaf(e, acc[ii][7], y1.w);
            *(float4*)yp = y0;
            *(float4*)(yp + 4) = y1;
        }
    }
}

// ---- gate + RMSNorm -> bf16 hi/lo A-tiles (K=1024) -----------
__global__ __launch_bounds__(256) void gate_stage_kernel(
    const float* __restrict__ y, const float* __restrict__ zx,
    const float* __restrict__ gw, __nv_bfloat16* __restrict__ Ah,
    __nv_bfloat16* __restrict__ Al)
{
    int row = blockIdx.x;
    int tid = threadIdx.x;
    int d = tid * 4;
    __shared__ float sm[8];

    float4 y4 = *(const float4*)(y + (size_t)row * D_INNER + d);
    float4 z4 = *(const float4*)(zx + (size_t)row * D_IN_PROJ + d);
    float g0 = y4.x * siluf(z4.x);
    float g1 = y4.y * siluf(z4.y);
    float g2 = y4.z * siluf(z4.z);
    float g3 = y4.w * siluf(z4.w);

    float ss = g0 * g0 + g1 * g1 + g2 * g2 + g3 * g3;
    #pragma unroll
    for (int o = 16; o; o >>= 1) ss += __shfl_xor_sync(0xffffffffu, ss, o);
    if ((tid & 31) == 0) sm[tid >> 5] = ss;
    __syncthreads();
    float tot = 0.f;
    #pragma unroll
    for (int i = 0; i < 8; i++) tot += sm[i];
    float scale = rsqrtf(tot * (1.0f / (float)D_INNER) + EPS);

    float4 w4 = *(const float4*)(gw + d);
    float v0 = g0 * scale * w4.x, v1 = g1 * scale * w4.y;
    float v2 = g2 * scale * w4.z, v3 = g3 * scale * w4.w;

    uint32_t h0, l0, h1, l1, h2, l2, h3, l3;
    bf16_split(v0, h0, l0);
    bf16_split(v1, h1, l1);
    bf16_split(v2, h2, l2);
    bf16_split(v3, h3, l3);

    int ktile = d >> 7;
    int cl = d & 127;
    size_t tb = (size_t)((row >> 7) * 8 + ktile) * 32768;
    int r = row & 127;
    int off0 = toff128(r, cl);
    int off1 = toff128(r, cl + 2);
    *(uint32_t*)((char*)Ah + tb + off0) = h0 | (h1 << 16);
    *(uint32_t*)((char*)Al + tb + off0) = l0 | (l1 << 16);
    *(uint32_t*)((char*)Ah + tb + off1) = h2 | (h3 << 16);
    *(uint32_t*)((char*)Al + tb + off1) = l2 | (l3 << 16);
}

// ---------------- launch ----------------
extern "C" void kernel_launch(void* const* d_in, const int* in_sizes, int n_in,
                              void* d_out, int out_size)
{
    const float* hidden  = (const float*)d_in[0];
    const float* w_in    = (const float*)d_in[1];
    const float* conv_w  = (const float*)d_in[2];
    const float* conv_b  = (const float*)d_in[3];
    const float* dt_bias = (const float*)d_in[4];
    const float* A_log   = (const float*)d_in[5];
    const float* D_skip  = (const float*)d_in[6];
    const float* gnorm_w = (const float*)d_in[7];
    const float* w_out   = (const float*)d_in[8];
    const float* ln1_w   = (const float*)d_in[9];
    const float* ln1_b   = (const float*)d_in[10];
    const float* ln2_w   = (const float*)d_in[11];
    const float* ln2_b   = (const float*)d_in[12];
    const float* mlp_w   = (const float*)d_in[13];
    const float* mlp_b   = (const float*)d_in[14];
    float* outp = (float*)d_out;

    float *zx, *xbc, *dtT, *csv, *Gm, *Tm, *Spm, *Lam, *y, *res2;
    __nv_bfloat16 *af1h, *af1l, *aggh, *aggl, *ah2h, *ah2l;
    __nv_bfloat16 *bwinh, *bwinl, *bwouth, *bwoutl, *bwmlph, *bwmlpl;
    cudaGetSymbolAddress((void**)&zx,   g_zx);
    cudaGetSymbolAddress((void**)&xbc,  g_xbc);
    cudaGetSymbolAddress((void**)&dtT,  g_dtT);
    cudaGetSymbolAddress((void**)&csv,  g_cs);
    cudaGetSymbolAddress((void**)&Gm,   g_G);
    cudaGetSymbolAddress((void**)&Tm,   g_T);
    cudaGetSymbolAddress((void**)&Spm,  g_Sp);
    cudaGetSymbolAddress((void**)&Lam,  g_Lam);
    cudaGetSymbolAddress((void**)&y,    g_y);
    cudaGetSymbolAddress((void**)&res2, g_res2);
    cudaGetSymbolAddress((void**)&af1h, g_af1h);
    cudaGetSymbolAddress((void**)&af1l, g_af1l);
    cudaGetSymbolAddress((void**)&aggh, g_aggh);
    cudaGetSymbolAddress((void**)&aggl, g_aggl);
    cudaGetSymbolAddress((void**)&ah2h, g_ah2h);
    cudaGetSymbolAddress((void**)&ah2l, g_ah2l);
    cudaGetSymbolAddress((void**)&bwinh, g_bwinh);
    cudaGetSymbolAddress((void**)&bwinl, g_bwinl);
    cudaGetSymbolAddress((void**)&bwouth, g_bwouth);
    cudaGetSymbolAddress((void**)&bwoutl, g_bwoutl);
    cudaGetSymbolAddress((void**)&bwmlph, g_bwmlph);
    cudaGetSymbolAddress((void**)&bwmlpl, g_bwmlpl);

    const int smem_gemm1n = 1024 + 65536 + 65536;    // 132096
    const int smem_gemm1  = 1024 + BUF_STRIDE;       // 99328
    const int smem_gemm2  = 1024 + 2 * BUF_STRIDE;   // 197632
    const int smem_g      = (128 * 68 * 2) * 4;      // 69632
    const int smem_intra  = (QC * 68 + QC * 132 * 2 + 3 * QC) * 4;
    const int smem_out    = (128 * 68 + 128 * 132 + QC) * 4;
    cudaFuncSetAttribute(tc_gemm1,
        cudaFuncAttributeMaxDynamicSharedMemorySize, smem_gemm1n);
    cudaFuncSetAttribute(tc_gemm<true, false, 8>,
        cudaFuncAttributeMaxDynamicSharedMemorySize, smem_gemm2);
    cudaFuncSetAttribute(tc_gemm<false, true, 1>,
        cudaFuncAttributeMaxDynamicSharedMemorySize, smem_gemm1);
    cudaFuncSetAttribute(ssd_g_kernel,
        cudaFuncAttributeMaxDynamicSharedMemorySize, smem_g);
    cudaFuncSetAttribute(ssd_intra_kernel,
        cudaFuncAttributeMaxDynamicSharedMemorySize, smem_intra);
    cudaFuncSetAttribute(ssd_out_kernel,
        cudaFuncAttributeMaxDynamicSharedMemorySize, smem_out);

    // 0) prep: fused weight stages + ln1
    prep_kernel<<<W_TOTAL + LN1_BLK, 256>>>(
        w_in, w_out, mlp_w, bwinh, bwinl, bwouth, bwoutl, bwmlph, bwmlpl,
        hidden, ln1_w, ln1_b, af1h, af1l);

    // 1) in_proj (tcgen05, N=128/CTA)
    {
        dim3 grid(NT1 / 2, ROWS / 128);     // (19, 32)
        tc_gemm1<<<grid, 256, smem_gemm1n>>>(
            af1h, af1l, bwinh, bwinl, zx, D_IN_PROJ, D_IN_PROJ);
    }

    // 2) fused conv (vectorized) + dt/cumsum
    conv_dt_kernel<<<CONV_BLK + DT_BLK, 256>>>(
        zx, conv_w, conv_b, xbc, dt_bias, A_log, dtT, csv);

    // 3) chunked SSD
    {
        dim3 gg_(NCH, B_SZ);                       // 64 blocks, 512 thr
        ssd_g_kernel<<<gg_, 512, smem_g>>>(xbc, Gm);
        dim3 gi(NCH / 2, NHEADS, B_SZ);
        ssd_intra_kernel<<<gi, 256, smem_intra>>>(xbc, dtT, csv, Gm, D_skip,
                                                  y, Tm, Lam);
        ssd_inter_kernel<<<(NBH * HEADDIM * D_STATE / 4) / 256, 256>>>(Tm, Lam, Spm);
        dim3 go(16, NHEADS, B_SZ);
        ssd_out_kernel<<<go, 256, smem_out>>>(xbc, csv, Spm, y);
    }

    // 4) gate + rmsnorm -> bf16 tiles
    gate_stage_kernel<<<ROWS, 256>>>(y, zx, gnorm_w, aggh, aggl);

    // 5) out_proj + residual (tcgen05, double-buffered K-loop 8)
    {
        dim3 grid(2, ROWS / 128);
        tc_gemm<true, false, 8><<<grid, 256, smem_gemm2>>>(
            aggh, aggl, bwouth, bwoutl, res2, D_MODEL, D_MODEL,
            hidden, nullptr);
    }

    // 6) ln2 -> bf16 tiles
    ln_stage_kernel<<<ROWS / 8, 256>>>(res2, ln2_w, ln2_b, ah2h, ah2l);

    // 7) mlp (tcgen05)
    {
        dim3 grid(2, ROWS / 128);
        tc_gemm<false, true, 1><<<grid, 256, smem_gemm1>>>(
            ah2h, ah2l, bwmlph, bwmlpl, outp, D_MODEL, D_MODEL,
            nullptr, mlp_b);
    }
    (void)in_sizes; (void)n_in; (void)out_size;
}

// round 16
// speedup vs baseline: 1.0484x; 1.0394x over previous
#include <cuda_runtime.h>
#include <cuda_bf16.h>
#include <cstdint>

#define B_SZ 2
#define SEQ 2048
#define ROWS (B_SZ * SEQ)          // 4096
#define D_MODEL 128
#define D_INNER 1024
#define NHEADS 8
#define HEADDIM 128
#define D_STATE 128
#define CONV_DIM (D_INNER + 2 * D_STATE)   // 1280
#define D_IN_PROJ (2 * D_INNER + 2 * D_STATE + NHEADS)  // 2312
#define EPS 1e-5f

#define QC 64
#define NCH (SEQ / QC)             // 32
#define NBH (B_SZ * NHEADS)        // 16

#define NT1 38                     // 38*64 = 2432 >= 2312; 19 tiles of 128

// prep (wstage + ln1) fused block ranges
#define WIN_BLK  ((NT1 * 64 * 64) / 256)     // 608
#define WOUT_BLK ((2 * 64 * 512) / 256)      // 256
#define WMLP_BLK ((2 * 64 * 64) / 256)       // 32
#define W_TOTAL  (WIN_BLK + WOUT_BLK + WMLP_BLK)   // 896
#define LN1_BLK  (ROWS / 8)                  // 512

// conv+dt fused block ranges (conv: 4ch x 4t per thread)
#define CONV_BLK ((B_SZ * (SEQ / 4) * (CONV_DIM / 4)) / 256)   // 1280
#define DT_BLK   ((NBH * NCH) / 4)                              // 128

#if defined(__CUDA_ARCH_FEAT_SM103_ALL) || defined(__CUDA_ARCH_FEAT_SM100_ALL) || defined(__CUDA_ARCH_FEAT_SM101_ALL)
#define HAS_TC 1
#else
#define HAS_TC 0
#endif

// ---------------- scratch ----------------
__device__ float g_zx[ROWS * D_IN_PROJ];
__device__ float g_xbc[ROWS * CONV_DIM];
__device__ float g_dtT[NBH * SEQ];
__device__ float g_cs[NBH * SEQ];
__device__ float g_G[B_SZ * NCH * QC * QC];
__device__ float g_T[NBH * NCH * HEADDIM * D_STATE];    // [n][p] layout
__device__ float g_Sp[NBH * NCH * HEADDIM * D_STATE];   // [n][p] layout
__device__ float g_Lam[NBH * NCH];
__device__ float g_y[ROWS * D_INNER];
__device__ float g_res2[ROWS * D_MODEL];

__device__ __nv_bfloat16 g_af1h[ROWS * D_MODEL];
__device__ __nv_bfloat16 g_af1l[ROWS * D_MODEL];
__device__ __nv_bfloat16 g_aggh[ROWS * D_INNER];
__device__ __nv_bfloat16 g_aggl[ROWS * D_INNER];
__device__ __nv_bfloat16 g_ah2h[ROWS * D_MODEL];
__device__ __nv_bfloat16 g_ah2l[ROWS * D_MODEL];
__device__ __nv_bfloat16 g_bwinh[NT1 * 64 * D_MODEL];
__device__ __nv_bfloat16 g_bwinl[NT1 * 64 * D_MODEL];
__device__ __nv_bfloat16 g_bwouth[2 * 8 * 64 * 128];
__device__ __nv_bfloat16 g_bwoutl[2 * 8 * 64 * 128];
__device__ __nv_bfloat16 g_bwmlph[2 * 64 * 128];
__device__ __nv_bfloat16 g_bwmlpl[2 * 64 * 128];

__device__ __forceinline__ float siluf(float v) {
    return v / (1.0f + expf(-v));
}

__device__ __forceinline__ int toff128(int r, int c) {
    int off = ((r >> 3) + (c >> 6) * 16) * 1024 + (r & 7) * 128 + (c & 63) * 2;
    return off ^ ((off >> 3) & 0x70);
}
__device__ __forceinline__ int toff64(int r, int c) {
    int off = ((r >> 3) + (c >> 6) * 8) * 1024 + (r & 7) * 128 + (c & 63) * 2;
    return off ^ ((off >> 3) & 0x70);
}

__device__ __forceinline__ void bf16_split(float v, uint32_t& hb, uint32_t& lb) {
    __nv_bfloat16 h = __float2bfloat16(v);
    float hf = __bfloat162float(h);
    __nv_bfloat16 l = __float2bfloat16(v - hf);
    hb = (uint32_t)__bfloat16_as_ushort(h);
    lb = (uint32_t)__bfloat16_as_ushort(l);
}

__device__ __forceinline__ void cp_async16(void* smem_dst, const void* gsrc) {
    unsigned saddr = (unsigned)__cvta_generic_to_shared(smem_dst);
    asm volatile("cp.async.cg.shared.global [%0], [%1], 16;" :: "r"(saddr), "l"(gsrc));
}
__device__ __forceinline__ void cp_commit() {
    asm volatile("cp.async.commit_group;");
}
template<int N>
__device__ __forceinline__ void cp_wait() {
    asm volatile("cp.async.wait_group %0;" :: "n"(N));
}

#if HAS_TC
__device__ __forceinline__ bool elect1() {
    uint32_t p;
    asm volatile("{\n\t.reg .pred p;\n\telect.sync _|p, 0xFFFFFFFF;\n\t"
                 "selp.b32 %0, 1, 0, p;\n\t}" : "=r"(p));
    return p != 0;
}
__device__ __forceinline__ void tc_alloc(uint32_t smem_res, uint32_t ncols) {
    asm volatile("tcgen05.alloc.cta_group::1.sync.aligned.shared::cta.b32 [%0], %1;"
                 :: "r"(smem_res), "r"(ncols) : "memory");
}
__device__ __forceinline__ void tc_dealloc(uint32_t tmem, uint32_t ncols) {
    asm volatile("tcgen05.dealloc.cta_group::1.sync.aligned.b32 %0, %1;"
                 :: "r"(tmem), "r"(ncols));
}
__device__ __forceinline__ void mbar_init(uint32_t mbar, uint32_t cnt) {
    asm volatile("mbarrier.init.shared.b64 [%0], %1;" :: "r"(mbar), "r"(cnt) : "memory");
}
__device__ __forceinline__ void mbar_wait(uint32_t mbar, uint32_t parity) {
    uint32_t done = 0;
    while (!done) {
        asm volatile(
            "{\n\t.reg .pred p;\n\t"
            "mbarrier.try_wait.parity.acquire.cta.shared::cta.b64 p, [%1], %2, 0x989680;\n\t"
            "selp.b32 %0, 1, 0, p;\n\t}"
            : "=r"(done) : "r"(mbar), "r"(parity) : "memory");
    }
}
__device__ __forceinline__ void tc_commit(uint32_t mbar) {
    asm volatile(
        "tcgen05.commit.cta_group::1.mbarrier::arrive::one.shared::cluster.b64 [%0];"
        :: "r"(mbar) : "memory");
}
__device__ __forceinline__ void mma_f16_ss(uint32_t d, uint64_t ad, uint64_t bd,
                                           uint32_t idesc, uint32_t en) {
    asm volatile(
        "{\n\t.reg .pred p;\n\tsetp.ne.u32 p, %5, 0;\n\t"
        "tcgen05.mma.cta_group::1.kind::f16 [%0], %1, %2, %3, {%4,%4,%4,%4}, p;\n\t}"
        :: "r"(d), "l"(ad), "l"(bd), "r"(idesc), "r"(0u), "r"(en) : "memory");
}
__device__ __forceinline__ uint64_t mk_desc(uint32_t saddr) {
    return ((uint64_t)2 << 61) | ((uint64_t)1 << 46) | ((uint64_t)64 << 32)
         | ((uint64_t)1 << 16) | (uint64_t)((saddr >> 4) & 0x3FFF);
}
__device__ __forceinline__ void ldtm_x32(uint32_t* r, uint32_t addr) {
    asm volatile(
        "tcgen05.ld.sync.aligned.32x32b.x32.b32 "
        "{%0,%1,%2,%3,%4,%5,%6,%7,%8,%9,%10,%11,%12,%13,%14,%15,"
        "%16,%17,%18,%19,%20,%21,%22,%23,%24,%25,%26,%27,%28,%29,%30,%31}, [%32];"
        : "=r"(r[0]), "=r"(r[1]), "=r"(r[2]), "=r"(r[3]),
          "=r"(r[4]), "=r"(r[5]), "=r"(r[6]), "=r"(r[7]),
          "=r"(r[8]), "=r"(r[9]), "=r"(r[10]), "=r"(r[11]),
          "=r"(r[12]), "=r"(r[13]), "=r"(r[14]), "=r"(r[15]),
          "=r"(r[16]), "=r"(r[17]), "=r"(r[18]), "=r"(r[19]),
          "=r"(r[20]), "=r"(r[21]), "=r"(r[22]), "=r"(r[23]),
          "=r"(r[24]), "=r"(r[25]), "=r"(r[26]), "=r"(r[27]),
          "=r"(r[28]), "=r"(r[29]), "=r"(r[30]), "=r"(r[31])
        : "r"(addr));
}
#endif // HAS_TC

#define TC_IDESC 0x8100490u
#define BUF_STRIDE 98304

// ---- gemm1: N=128 per CTA, KT=1; shares A tile across two N=64 MMA groups -
__global__ __launch_bounds__(256) void tc_gemm1(
    const __nv_bfloat16* __restrict__ Ah_, const __nv_bfloat16* __restrict__ Al_,
    const __nv_bfloat16* __restrict__ Bh_, const __nv_bfloat16* __restrict__ Bl_,
    float* __restrict__ C, int ldc, int N)
{
    extern __shared__ char smem[];
    const int tid = threadIdx.x;
    const int ntile = blockIdx.x, mtile = blockIdx.y;
    const uint32_t sbase = (uint32_t)__cvta_generic_to_shared(smem);

    const char* gAh = (const char*)Ah_ + (size_t)mtile * 32768;
    const char* gAl = (const char*)Al_ + (size_t)mtile * 32768;
    const char* gBh = (const char*)Bh_ + (size_t)(ntile * 2) * 16384;
    const char* gBl = (const char*)Bl_ + (size_t)(ntile * 2) * 16384;

#if HAS_TC
    const int wid = tid >> 5;
    const int lane = tid & 31;
    const uint32_t mbar = sbase + 8;

    if (wid == 0) tc_alloc(sbase, 128);
    if (tid == 0) mbar_init(mbar, 1);
    __syncthreads();
    uint32_t tmem;
    asm volatile("ld.shared.b32 %0, [%1];" : "=r"(tmem) : "r"(sbase));

    char* base = smem + 1024;
    #pragma unroll 4
    for (int i = tid; i < 2048; i += 256) {
        cp_async16(base + i * 16, gAh + i * 16);
        cp_async16(base + 32768 + i * 16, gAl + i * 16);
    }
    #pragma unroll 4
    for (int i = tid; i < 2048; i += 256) {   // B0H|B0L|B1H|B1L
        int half = i >> 10;
        int j = i & 1023;
        cp_async16(base + 65536 + half * 32768 + j * 16, gBh + (half ? 16384 : 0) + j * 16);
        cp_async16(base + 81920 + half * 32768 + j * 16, gBl + (half ? 16384 : 0) + j * 16);
    }
    cp_commit();
    cp_wait<0>();
    __syncthreads();
    asm volatile("fence.proxy.async.shared::cta;" ::: "memory");

    if (wid == 0) {
        asm volatile("tcgen05.fence::after_thread_sync;" ::: "memory");
        if (elect1()) {
            uint64_t dAh = mk_desc(sbase + 1024);
            uint64_t dAl = mk_desc(sbase + 1024 + 32768);
            uint64_t dB0h = mk_desc(sbase + 1024 + 65536);
            uint64_t dB0l = mk_desc(sbase + 1024 + 81920);
            uint64_t dB1h = mk_desc(sbase + 1024 + 98304);
            uint64_t dB1l = mk_desc(sbase + 1024 + 114688);
            #pragma unroll
            for (int ks = 0; ks < 8; ks++) {
                uint64_t oA = (ks < 4) ? (uint64_t)(ks * 2) : (uint64_t)(1024 + (ks - 4) * 2);
                uint64_t oB = (ks < 4) ? (uint64_t)(ks * 2) : (uint64_t)(512 + (ks - 4) * 2);
                uint32_t en = ks ? 1u : 0u;
                mma_f16_ss(tmem, dAh + oA, dB0h + oB, TC_IDESC, en);
                mma_f16_ss(tmem, dAh + oA, dB0l + oB, TC_IDESC, 1u);
                mma_f16_ss(tmem, dAl + oA, dB0h + oB, TC_IDESC, 1u);
                mma_f16_ss(tmem + 64, dAh + oA, dB1h + oB, TC_IDESC, en);
                mma_f16_ss(tmem + 64, dAh + oA, dB1l + oB, TC_IDESC, 1u);
                mma_f16_ss(tmem + 64, dAl + oA, dB1h + oB, TC_IDESC, 1u);
            }
            tc_commit(mbar);
        }
    }
    mbar_wait(mbar, 0);
    asm volatile("tcgen05.fence::after_thread_sync;" ::: "memory");

    uint32_t d0[32], d1[32];
    int chalf = (wid >> 2) * 32;
    ldtm_x32(d0, tmem + chalf);
    ldtm_x32(d1, tmem + 64 + chalf);
    asm volatile("tcgen05.wait::ld.sync.aligned;" ::: "memory");

    int row = mtile * 128 + (wid & 3) * 32 + lane;
    #pragma unroll
    for (int g = 0; g < 2; g++) {
        uint32_t* d = g ? d1 : d0;
        int col0 = ntile * 128 + g * 64 + chalf;
        float* cp = C + (size_t)row * ldc + col0;
        #pragma unroll
        for (int c = 0; c < 32; c += 4) {
            int col = col0 + c;
            if (col < N) {
                float4 v = make_float4(__uint_as_float(d[c]), __uint_as_float(d[c + 1]),
                                       __uint_as_float(d[c + 2]), __uint_as_float(d[c + 3]));
                *(float4*)(cp + c) = v;
            }
        }
    }
    __syncthreads();
    if (wid == 0) tc_dealloc(tmem, 128);
#else
    const int half = tid >> 7;
    const int r128 = tid & 127;
    char* base = smem + 1024;
    #pragma unroll 4
    for (int i = tid; i < 2048; i += 256) {
        cp_async16(base + i * 16, gAh + i * 16);
        cp_async16(base + 32768 + i * 16, gAl + i * 16);
    }
    for (int i = tid; i < 2048; i += 256) {
        int hh = i >> 10;
        int j = i & 1023;
        cp_async16(base + 65536 + hh * 32768 + j * 16, gBh + (hh ? 16384 : 0) + j * 16);
        cp_async16(base + 81920 + hh * 32768 + j * 16, gBl + (hh ? 16384 : 0) + j * 16);
    }
    cp_commit();
    cp_wait<0>();
    __syncthreads();

    for (int g = 0; g < 2; g++) {
        float vals[32];
        #pragma unroll
        for (int c = 0; c < 32; c++) vals[c] = 0.f;
        char* bB = base + 65536 + g * 32768;
        for (int k = 0; k < 128; k++) {
            int ao = toff128(r128, k);
            float a = __bfloat162float(*(const __nv_bfloat16*)(base + ao))
                    + __bfloat162float(*(const __nv_bfloat16*)(base + 32768 + ao));
            for (int n = 0; n < 32; n++) {
                int bo = toff64(half * 32 + n, k);
                float b = __bfloat162float(*(const __nv_bfloat16*)(bB + bo))
                        + __bfloat162float(*(const __nv_bfloat16*)(bB + 16384 + bo));
                vals[n] = fmaf(a, b, vals[n]);
            }
        }
        int row = mtile * 128 + r128;
        int col0 = ntile * 128 + g * 64 + half * 32;
        float* cp = C + (size_t)row * ldc + col0;
        for (int c = 0; c < 32; c++) {
            int col = col0 + c;
            if (col < N) cp[c] = vals[c];
        }
    }
#endif
}

// ---------------- GEMM (N=64/CTA): gemm2 (KT=8, dbuf) & gemm3 (KT=1) -------
template<bool RESID, bool BIAS, int KT>
__global__ __launch_bounds__(256) void tc_gemm(
    const __nv_bfloat16* __restrict__ Ah_, const __nv_bfloat16* __restrict__ Al_,
    const __nv_bfloat16* __restrict__ Bh_, const __nv_bfloat16* __restrict__ Bl_,
    float* __restrict__ C, int ldc, int N,
    const float* __restrict__ resid, const float* __restrict__ bias)
{
    extern __shared__ char smem[];
    const int tid = threadIdx.x;
    const int ntile = blockIdx.x, mtile = blockIdx.y;
    const uint32_t sbase = (uint32_t)__cvta_generic_to_shared(smem);

    const char* gAh = (const char*)Ah_ + (size_t)(mtile * KT) * 32768;
    const char* gAl = (const char*)Al_ + (size_t)(mtile * KT) * 32768;
    const char* gBh = (const char*)Bh_ + (size_t)(ntile * KT) * 16384;
    const char* gBl = (const char*)Bl_ + (size_t)(ntile * KT) * 16384;

    auto load_tile = [&](int kt, int buf) {
        char* base = smem + 1024 + buf * BUF_STRIDE;
        const char* ah = gAh + (size_t)kt * 32768;
        const char* al = gAl + (size_t)kt * 32768;
        const char* bh = gBh + (size_t)kt * 16384;
        const char* bl = gBl + (size_t)kt * 16384;
        #pragma unroll 4
        for (int i = tid; i < 2048; i += 256) {
            cp_async16(base + i * 16, ah + i * 16);
            cp_async16(base + 32768 + i * 16, al + i * 16);
        }
        #pragma unroll 2
        for (int i = tid; i < 1024; i += 256) {
            cp_async16(base + 65536 + i * 16, bh + i * 16);
            cp_async16(base + 81920 + i * 16, bl + i * 16);
        }
        cp_commit();
    };

#if HAS_TC
    const int wid = tid >> 5;
    const int lane = tid & 31;
    const uint32_t mbar = sbase + 8;

    if (wid == 0) tc_alloc(sbase, 64);
    if (tid == 0) mbar_init(mbar, 1);
    __syncthreads();
    uint32_t tmem;
    asm volatile("ld.shared.b32 %0, [%1];" : "=r"(tmem) : "r"(sbase));

    load_tile(0, 0);
    #pragma unroll 1
    for (int kt = 0; kt < KT; kt++) {
        int buf = (KT > 1) ? (kt & 1) : 0;
        if (KT > 1 && kt + 1 < KT) {
            load_tile(kt + 1, buf ^ 1);
            cp_wait<1>();
        } else {
            cp_wait<0>();
        }
        __syncthreads();
        asm volatile("fence.proxy.async.shared::cta;" ::: "memory");

        if (wid == 0) {
            asm volatile("tcgen05.fence::after_thread_sync;" ::: "memory");
            if (elect1()) {
                uint32_t bb = sbase + 1024 + buf * BUF_STRIDE;
                uint64_t dAh = mk_desc(bb);
                uint64_t dAl = mk_desc(bb + 32768);
                uint64_t dBh = mk_desc(bb + 65536);
                uint64_t dBl = mk_desc(bb + 81920);
                #pragma unroll
                for (int ks = 0; ks < 8; ks++) {
                    uint64_t oA = (ks < 4) ? (uint64_t)(ks * 2) : (uint64_t)(1024 + (ks - 4) * 2);
                    uint64_t oB = (ks < 4) ? (uint64_t)(ks * 2) : (uint64_t)(512 + (ks - 4) * 2);
                    uint32_t en = (kt || ks) ? 1u : 0u;
                    mma_f16_ss(tmem, dAh + oA, dBh + oB, TC_IDESC, en);
                    mma_f16_ss(tmem, dAh + oA, dBl + oB, TC_IDESC, 1u);
                    mma_f16_ss(tmem, dAl + oA, dBh + oB, TC_IDESC, 1u);
                }
                tc_commit(mbar);
            }
        }
        mbar_wait(mbar, kt & 1);
    }
    asm volatile("tcgen05.fence::after_thread_sync;" ::: "memory");

    uint32_t d[32];
    int chalf = (wid >> 2) * 32;
    ldtm_x32(d, tmem + chalf);
    asm volatile("tcgen05.wait::ld.sync.aligned;" ::: "memory");

    int row = mtile * 128 + (wid & 3) * 32 + lane;
    int col0 = ntile * 64 + chalf;
    float* cp = C + (size_t)row * ldc + col0;
    #pragma unroll
    for (int c = 0; c < 32; c += 4) {
        int col = col0 + c;
        if (col < N) {
            float4 v = make_float4(__uint_as_float(d[c]), __uint_as_float(d[c + 1]),
                                   __uint_as_float(d[c + 2]), __uint_as_float(d[c + 3]));
            if (RESID) {
                float4 r = *(const float4*)(resid + (size_t)row * ldc + col);
                v.x += r.x; v.y += r.y; v.z += r.z; v.w += r.w;
            }
            if (BIAS) {
                float4 b = *(const float4*)(bias + col);
                v.x += b.x; v.y += b.y; v.z += b.z; v.w += b.w;
            }
            *(float4*)(cp + c) = v;
        }
    }
    __syncthreads();
    if (wid == 0) tc_dealloc(tmem, 64);
#else
    const int half = tid >> 7;
    const int r128 = tid & 127;
    float vals[32];
    #pragma unroll
    for (int c = 0; c < 32; c++) vals[c] = 0.f;

    for (int kt = 0; kt < KT; kt++) {
        load_tile(kt, 0);
        cp_wait<0>();
        __syncthreads();
        char* base = smem + 1024;
        for (int k = 0; k < 128; k++) {
            int ao = toff128(r128, k);
            float a = __bfloat162float(*(const __nv_bfloat16*)(base + ao))
                    + __bfloat162float(*(const __nv_bfloat16*)(base + 32768 + ao));
            for (int n = 0; n < 32; n++) {
                int bo = toff64(half * 32 + n, k);
                float b = __bfloat162float(*(const __nv_bfloat16*)(base + 65536 + bo))
                        + __bfloat162float(*(const __nv_bfloat16*)(base + 81920 + bo));
                vals[n] = fmaf(a, b, vals[n]);
            }
        }
        __syncthreads();
    }
    int row = mtile * 128 + r128;
    int col0 = ntile * 64 + half * 32;
    float* cp = C + (size_t)row * ldc + col0;
    for (int c = 0; c < 32; c++) {
        int col = col0 + c;
        if (col < N) {
            float v = vals[c];
            if (RESID) v += resid[(size_t)row * ldc + col];
            if (BIAS)  v += bias[col];
            cp[c] = v;
        }
    }
#endif
}

// ------ LayerNorm body (warp-per-row) ------
__device__ __forceinline__ void ln_row(
    const float* __restrict__ x, const float* __restrict__ w,
    const float* __restrict__ b, __nv_bfloat16* __restrict__ Ah,
    __nv_bfloat16* __restrict__ Al, int row, int lane)
{
    const int c0 = lane * 4;
    float4 v = *(const float4*)(x + (size_t)row * D_MODEL + c0);
    float s = v.x + v.y + v.z + v.w;
    #pragma unroll
    for (int o = 16; o; o >>= 1) s += __shfl_xor_sync(0xffffffffu, s, o);
    float mean = s * (1.0f / 128.0f);

    float d0 = v.x - mean, d1 = v.y - mean, d2 = v.z - mean, d3 = v.w - mean;
    float q = d0 * d0 + d1 * d1 + d2 * d2 + d3 * d3;
    #pragma unroll
    for (int o = 16; o; o >>= 1) q += __shfl_xor_sync(0xffffffffu, q, o);
    float inv = rsqrtf(q * (1.0f / 128.0f) + EPS);

    float4 wv = *(const float4*)(w + c0);
    float4 bv = *(const float4*)(b + c0);
    float o0 = fmaf(d0 * inv, wv.x, bv.x);
    float o1 = fmaf(d1 * inv, wv.y, bv.y);
    float o2 = fmaf(d2 * inv, wv.z, bv.z);
    float o3 = fmaf(d3 * inv, wv.w, bv.w);

    uint32_t h0, l0, h1, l1, h2, l2, h3, l3;
    bf16_split(o0, h0, l0);
    bf16_split(o1, h1, l1);
    bf16_split(o2, h2, l2);
    bf16_split(o3, h3, l3);

    size_t tb = (size_t)(row >> 7) * 32768;
    int r = row & 127;
    int off0 = toff128(r, c0);
    int off1 = toff128(r, c0 + 2);
    *(uint32_t*)((char*)Ah + tb + off0) = h0 | (h1 << 16);
    *(uint32_t*)((char*)Al + tb + off0) = l0 | (l1 << 16);
    *(uint32_t*)((char*)Ah + tb + off1) = h2 | (h3 << 16);
    *(uint32_t*)((char*)Al + tb + off1) = l2 | (l3 << 16);
}

__global__ __launch_bounds__(256) void ln_stage_kernel(
    const float* __restrict__ x, const float* __restrict__ w,
    const float* __restrict__ b, __nv_bfloat16* __restrict__ Ah,
    __nv_bfloat16* __restrict__ Al)
{
    ln_row(x, w, b, Ah, Al, blockIdx.x * 8 + (threadIdx.x >> 5), threadIdx.x & 31);
}

// ------- W staging helper -------
__device__ __forceinline__ void wstage_do(
    const float* __restrict__ W, int Nreal, int K, int idx,
    __nv_bfloat16* __restrict__ Bh, __nv_bfloat16* __restrict__ Bl)
{
    int pairs_per_row = K >> 1;
    int n = idx / pairs_per_row;
    int k0 = (idx - n * pairs_per_row) * 2;
    float v0 = (n < Nreal) ? W[(size_t)n * K + k0] : 0.f;
    float v1 = (n < Nreal) ? W[(size_t)n * K + k0 + 1] : 0.f;
    uint32_t h0, l0, h1, l1;
    bf16_split(v0, h0, l0);
    bf16_split(v1, h1, l1);
    int ktiles = K >> 7;
    size_t tb = (size_t)((n >> 6) * ktiles + (k0 >> 7)) * 16384;
    int off = toff64(n & 63, k0 & 127);
    *(uint32_t*)((char*)Bh + tb + off) = h0 | (h1 << 16);
    *(uint32_t*)((char*)Bl + tb + off) = l0 | (l1 << 16);
}

// ---- prep: fused wstage x3 + ln1 ----
__global__ __launch_bounds__(256) void prep_kernel(
    const float* __restrict__ w_in, const float* __restrict__ w_out,
    const float* __restrict__ mlp_w,
    __nv_bfloat16* __restrict__ winh, __nv_bfloat16* __restrict__ winl,
    __nv_bfloat16* __restrict__ wouth, __nv_bfloat16* __restrict__ woutl,
    __nv_bfloat16* __restrict__ wmlph, __nv_bfloat16* __restrict__ wmlpl,
    const float* __restrict__ hidden, const float* __restrict__ ln1_w,
    const float* __restrict__ ln1_b,
    __nv_bfloat16* __restrict__ af1h, __nv_bfloat16* __restrict__ af1l)
{
    int bx = blockIdx.x;
    if (bx < WIN_BLK) {
        wstage_do(w_in, D_IN_PROJ, D_MODEL, bx * 256 + threadIdx.x, winh, winl);
    } else if (bx < WIN_BLK + WOUT_BLK) {
        wstage_do(w_out, D_MODEL, D_INNER, (bx - WIN_BLK) * 256 + threadIdx.x,
                  wouth, woutl);
    } else if (bx < W_TOTAL) {
        wstage_do(mlp_w, D_MODEL, D_MODEL, (bx - WIN_BLK - WOUT_BLK) * 256 + threadIdx.x,
                  wmlph, wmlpl);
    } else {
        int row = (bx - W_TOTAL) * 8 + (threadIdx.x >> 5);
        ln_row(hidden, ln1_w, ln1_b, af1h, af1l, row, threadIdx.x & 31);
    }
}

// ---- fused: conv (4ch x 4t float4) + [dt softplus + chunk cumsum] ----
__global__ __launch_bounds__(256) void conv_dt_kernel(
    const float* __restrict__ zx, const float* __restrict__ cw,
    const float* __restrict__ cb, float* __restrict__ out,
    const float* __restrict__ dt_bias, const float* __restrict__ A_log,
    float* __restrict__ dt_out, float* __restrict__ cs_out)
{
    __shared__ float s[4][QC];
    int bx = blockIdx.x;
    if (bx < CONV_BLK) {
        int idx = bx * 256 + threadIdx.x;
        int c4 = (idx % (CONV_DIM / 4)) * 4;
        int r = idx / (CONV_DIM / 4);
        int tq = r & ((SEQ / 4) - 1);
        int b = r / (SEQ / 4);
        int t0 = tq * 4;

        const float* col = zx + (size_t)b * SEQ * D_IN_PROJ + D_INNER + c4;
        float4 xv[7];
        #pragma unroll
        for (int k = 0; k < 7; k++) {
            int t = t0 - 3 + k;
            xv[k] = (t >= 0) ? *(const float4*)(col + (size_t)t * D_IN_PROJ)
                             : make_float4(0.f, 0.f, 0.f, 0.f);
        }
        float4 w[4];
        #pragma unroll
        for (int l = 0; l < 4; l++) w[l] = *(const float4*)(cw + (c4 + l) * 4);
        float4 bias4 = *(const float4*)(cb + c4);

        float* ob = out + ((size_t)(b * SEQ + t0)) * CONV_DIM + c4;
        #pragma unroll
        for (int j = 0; j < 4; j++) {
            float4 o;
            #pragma unroll
            for (int l = 0; l < 4; l++) {
                float acc = (&bias4.x)[l];
                acc = fmaf(w[l].x, (&xv[j].x)[l], acc);
                acc = fmaf(w[l].y, (&xv[j + 1].x)[l], acc);
                acc = fmaf(w[l].z, (&xv[j + 2].x)[l], acc);
                acc = fmaf(w[l].w, (&xv[j + 3].x)[l], acc);
                (&o.x)[l] = siluf(acc);
            }
            *(float4*)(ob + (size_t)j * CONV_DIM) = o;
        }
    } else {
        int g = threadIdx.x >> 6;
        int t = threadIdx.x & 63;
        int blk4 = (bx - CONV_BLK) * 4 + g;
        int bh = blk4 >> 5;
        int ch = blk4 & (NCH - 1);
        int b = bh >> 3;
        int h = bh & 7;

        int row = b * SEQ + ch * QC + t;
        float raw = zx[(size_t)row * D_IN_PROJ + (D_IN_PROJ - NHEADS) + h] + dt_bias[h];
        float dt = (raw > 20.0f) ? raw : log1pf(expf(raw));
        float A = -expf(A_log[h]);
        size_t o = (size_t)bh * SEQ + ch * QC + t;
        dt_out[o] = dt;
        s[g][t] = dt * A;
        __syncthreads();
        #pragma unroll
        for (int off = 1; off < QC; off <<= 1) {
            float v = (t >= off) ? s[g][t - off] : 0.f;
            __syncthreads();
            s[g][t] += v;
            __syncthreads();
        }
        cs_out[o] = s[g][t];
    }
}

// ---------------- K_G (R13 best variant: 256 thr, 4x4 tile) ----------------
__global__ __launch_bounds__(256) void ssd_g_kernel(
    const float* __restrict__ xbc, float* __restrict__ G)
{
    extern __shared__ float sm[];
    float* Cn = sm;
    float* Bn = sm + 128 * 68;

    int c = blockIdx.x, b = blockIdx.y;
    int tid = threadIdx.x;
    int t0 = c * QC;

    for (int q = tid; q < QC * 32; q += 256) {
        int t = q >> 5;
        int n4 = (q & 31) * 4;
        const float* row = xbc + (size_t)(b * SEQ + t0 + t) * CONV_DIM + D_INNER;
        float4 bv = *(const float4*)(row + n4);
        float4 cv = *(const float4*)(row + D_STATE + n4);
        #pragma unroll
        for (int l = 0; l < 4; l++) {
            Bn[(n4 + l) * 68 + t] = (&bv.x)[l];
            Cn[(n4 + l) * 68 + t] = (&cv.x)[l];
        }
    }
    __syncthreads();

    int ty = tid >> 4, tx = tid & 15;
    int i0 = ty * 4, j0 = tx * 4;
    float acc[4][4];
    #pragma unroll
    for (int i = 0; i < 4; i++)
        #pragma unroll
        for (int j = 0; j < 4; j++) acc[i][j] = 0.f;

    #pragma unroll 4
    for (int n = 0; n < D_STATE; n++) {
        float4 cv = *(const float4*)&Cn[n * 68 + i0];
        float4 bv = *(const float4*)&Bn[n * 68 + j0];
        float cf[4] = {cv.x, cv.y, cv.z, cv.w};
        float bf[4] = {bv.x, bv.y, bv.z, bv.w};
        #pragma unroll
        for (int i = 0; i < 4; i++)
            #pragma unroll
            for (int j = 0; j < 4; j++)
                acc[i][j] = fmaf(cf[i], bf[j], acc[i][j]);
    }

    float* Gp = G + (size_t)(b * NCH + c) * QC * QC;
    #pragma unroll
    for (int i = 0; i < 4; i++) {
        float4 v = make_float4(acc[i][0], acc[i][1], acc[i][2], acc[i][3]);
        *(float4*)(Gp + (i0 + i) * QC + j0) = v;
    }
}

// ------------ K_intra: 2 chunks per block; T stored [n][p] ------------
__global__ __launch_bounds__(256) void ssd_intra_kernel(
    const float* __restrict__ xbc, const float* __restrict__ dt_t,
    const float* __restrict__ cs_g, const float* __restrict__ G,
    const float* __restrict__ D_skip,
    float* __restrict__ y_out, float* __restrict__ T_out,
    float* __restrict__ Lam_out)
{
    extern __shared__ float sm[];
    float* Wt = sm;
    float* Xj = Wt + QC * 68;
    float* Bj = Xj + QC * 132;
    float* s_cs = Bj + QC * 132;
    float* s_dt = s_cs + QC;
    float* s_el = s_dt + QC;

    int h = blockIdx.y, b = blockIdx.z;
    int tid = threadIdx.x;
    int bh = b * NHEADS + h;
    int ty = tid >> 4, tx = tid & 15;
    float Dsk = D_skip[h];

    for (int cc = 0; cc < 2; cc++) {
        int c = blockIdx.x + cc * 16;
        int t0 = c * QC;
        if (cc) __syncthreads();

        if (tid < QC) {
            s_cs[tid] = cs_g[(size_t)bh * SEQ + t0 + tid];
            s_dt[tid] = dt_t[(size_t)bh * SEQ + t0 + tid];
        }
        __syncthreads();
        if (tid < QC) s_el[tid] = __expf(s_cs[QC - 1] - s_cs[tid]) * s_dt[tid];
        if (tid == 0) Lam_out[bh * NCH + c] = __expf(s_cs[QC - 1]);

        for (int q = tid; q < QC * 32; q += 256) {
            int t = q >> 5;
            int n4 = (q & 31) * 4;
            const float* row = xbc + (size_t)(b * SEQ + t0 + t) * CONV_DIM;
            *(float4*)&Xj[t * 132 + n4] = *(const float4*)(row + h * HEADDIM + n4);
            *(float4*)&Bj[t * 132 + n4] = *(const float4*)(row + D_INNER + n4);
        }
        __syncthreads();

        {
            int i0 = ty * 4, j0 = tx * 4;
            const float* Gp = G + (size_t)(b * NCH + c) * QC * QC;
            #pragma unroll
            for (int ii = 0; ii < 4; ii++) {
                int i = i0 + ii;
                float4 gv = *(const float4*)(Gp + i * QC + j0);
                float gf[4] = {gv.x, gv.y, gv.z, gv.w};
                #pragma unroll
                for (int jj = 0; jj < 4; jj++) {
                    int j = j0 + jj;
                    float w = 0.f;
                    if (j <= i) w = __expf(s_cs[i] - s_cs[j]) * s_dt[j] * gf[jj];
                    Wt[j * 68 + i] = w;
                }
            }
        }
        __syncthreads();

        {
            int i0 = ty * 4, p0 = tx * 8;
            float acc[4][8];
            #pragma unroll
            for (int i = 0; i < 4; i++)
                #pragma unroll
                for (int p = 0; p < 8; p++) acc[i][p] = 0.f;

            int jmax = i0 + 4;
            for (int j = 0; j < jmax; j++) {
                float4 wv = *(const float4*)&Wt[j * 68 + i0];
                float4 xa = *(const float4*)&Xj[j * 132 + p0];
                float4 xb = *(const float4*)&Xj[j * 132 + p0 + 4];
                float wf[4] = {wv.x, wv.y, wv.z, wv.w};
                float xf[8] = {xa.x, xa.y, xa.z, xa.w, xb.x, xb.y, xb.z, xb.w};
                #pragma unroll
                for (int i = 0; i < 4; i++)
                    #pragma unroll
                    for (int p = 0; p < 8; p++)
                        acc[i][p] = fmaf(wf[i], xf[p], acc[i][p]);
            }
            #pragma unroll
            for (int ii = 0; ii < 4; ii++) {
                int i = i0 + ii;
                size_t row = (size_t)(b * SEQ + t0 + i);
                float* yp = y_out + row * D_INNER + h * HEADDIM + p0;
                float4 x0 = *(const float4*)&Xj[i * 132 + p0];
                float4 x1 = *(const float4*)&Xj[i * 132 + p0 + 4];
                float4 o0 = make_float4(fmaf(Dsk, x0.x, acc[ii][0]),
                                        fmaf(Dsk, x0.y, acc[ii][1]),
                                        fmaf(Dsk, x0.z, acc[ii][2]),
                                        fmaf(Dsk, x0.w, acc[ii][3]));
                float4 o1 = make_float4(fmaf(Dsk, x1.x, acc[ii][4]),
                                        fmaf(Dsk, x1.y, acc[ii][5]),
                                        fmaf(Dsk, x1.z, acc[ii][6]),
                                        fmaf(Dsk, x1.w, acc[ii][7]));
                *(float4*)yp = o0;
                *(float4*)(yp + 4) = o1;
            }
        }

        {
            int p0 = ty * 8, n0 = tx * 8;
            float acc[8][8];
            #pragma unroll
            for (int p = 0; p < 8; p++)
                #pragma unroll
                for (int n = 0; n < 8; n++) acc[p][n] = 0.f;

            #pragma unroll 2
            for (int j = 0; j < QC; j++) {
                float el = s_el[j];
                float4 xa = *(const float4*)&Xj[j * 132 + p0];
                float4 xb = *(const float4*)&Xj[j * 132 + p0 + 4];
                float4 ba = *(const float4*)&Bj[j * 132 + n0];
                float4 bb = *(const float4*)&Bj[j * 132 + n0 + 4];
                float xf[8] = {el * xa.x, el * xa.y, el * xa.z, el * xa.w,
                               el * xb.x, el * xb.y, el * xb.z, el * xb.w};
                float bf[8] = {ba.x, ba.y, ba.z, ba.w, bb.x, bb.y, bb.z, bb.w};
                #pragma unroll
                for (int p = 0; p < 8; p++)
                    #pragma unroll
                    for (int n = 0; n < 8; n++)
                        acc[p][n] = fmaf(xf[p], bf[n], acc[p][n]);
            }
            // T stored transposed [n][p]: same values, column-major regroup
            float* Tp = T_out + ((size_t)bh * NCH + c) * (HEADDIM * D_STATE);
            #pragma unroll
            for (int nn = 0; nn < 8; nn++) {
                float4 v0 = make_float4(acc[0][nn], acc[1][nn], acc[2][nn], acc[3][nn]);
                float4 v1 = make_float4(acc[4][nn], acc[5][nn], acc[6][nn], acc[7][nn]);
                *(float4*)(Tp + (size_t)(n0 + nn) * HEADDIM + p0) = v0;
                *(float4*)(Tp + (size_t)(n0 + nn) * HEADDIM + p0 + 4) = v1;
            }
        }
    }
}

// ---------------- K_inter (layout-agnostic elementwise) ----------------
__global__ __launch_bounds__(256) void ssd_inter_kernel(
    const float* __restrict__ T, const float* __restrict__ Lam,
    float* __restrict__ Sp)
{
    int gid = blockIdx.x * 256 + threadIdx.x;
    int bh = gid >> 12;
    int pn = gid & 4095;
    const float4* Tb = (const float4*)(T + ((size_t)bh << 19)) + pn;
    float4* Sb = (float4*)(Sp + ((size_t)bh << 19)) + pn;
    const float* Lb = Lam + bh * NCH;

    float4 S = make_float4(0.f, 0.f, 0.f, 0.f);
    #pragma unroll 4
    for (int c = 0; c < NCH; c++) {
        if (c) Sb[(size_t)c << 12] = S;
        float4 Tv = Tb[(size_t)c << 12];
        float lam = Lb[c];
        S.x = fmaf(lam, S.x, Tv.x);
        S.y = fmaf(lam, S.y, Tv.y);
        S.z = fmaf(lam, S.z, Tv.z);
        S.w = fmaf(lam, S.w, Tv.w);
    }
}

// ------------ K_out: 2 chunks per block; Sp read [n][p] (no transpose) -----
__global__ __launch_bounds__(256) void ssd_out_kernel(
    const float* __restrict__ xbc, const float* __restrict__ cs_g,
    const float* __restrict__ Sp, float* __restrict__ y_out)
{
    extern __shared__ float sm[];
    float* Cn = sm;
    float* Spn = Cn + 128 * 68;
    float* s_cs = Spn + 128 * 132;

    int h = blockIdx.y, b = blockIdx.z;
    int tid = threadIdx.x;
    int bh = b * NHEADS + h;
    int ty = tid >> 4, tx = tid & 15;
    int i0 = ty * 4, p0 = tx * 8;

    for (int cc = 0; cc < 2; cc++) {
        int c = blockIdx.x + 1 + cc * 16;
        if (c >= NCH) break;
        int t0 = c * QC;
        if (cc) __syncthreads();

        if (tid < QC) s_cs[tid] = cs_g[(size_t)bh * SEQ + t0 + tid];

        for (int q = tid; q < QC * 32; q += 256) {
            int t = q >> 5;
            int n4 = (q & 31) * 4;
            const float* row = xbc + (size_t)(b * SEQ + t0 + t) * CONV_DIM
                             + D_INNER + D_STATE;
            float4 v = *(const float4*)(row + n4);
            #pragma unroll
            for (int l = 0; l < 4; l++) Cn[(n4 + l) * 68 + t] = (&v.x)[l];
        }
        // Sp already [n][p]: straight vector copy, no scatter
        const float* Spsrc = Sp + ((size_t)bh * NCH + c) * (HEADDIM * D_STATE);
        for (int q = tid; q < HEADDIM * 32; q += 256) {
            int n = q >> 5;
            int p4 = (q & 31) * 4;
            *(float4*)&Spn[n * 132 + p4] =
                *(const float4*)(Spsrc + (size_t)n * HEADDIM + p4);
        }
        __syncthreads();

        float acc[4][8];
        #pragma unroll
        for (int i = 0; i < 4; i++)
            #pragma unroll
            for (int p = 0; p < 8; p++) acc[i][p] = 0.f;

        #pragma unroll 2
        for (int n = 0; n < D_STATE; n++) {
            float4 cv = *(const float4*)&Cn[n * 68 + i0];
            float4 sa = *(const float4*)&Spn[n * 132 + p0];
            float4 sb = *(const float4*)&Spn[n * 132 + p0 + 4];
            float cf[4] = {cv.x, cv.y, cv.z, cv.w};
            float sf[8] = {sa.x, sa.y, sa.z, sa.w, sb.x, sb.y, sb.z, sb.w};
            #pragma unroll
            for (int i = 0; i < 4; i++)
                #pragma unroll
                for (int p = 0; p < 8; p++)
                    acc[i][p] = fmaf(cf[i], sf[p], acc[i][p]);
        }

        #pragma unroll
        for (int ii = 0; ii < 4; ii++) {
            int i = i0 + ii;
            float e = __expf(s_cs[i]);
            size_t row = (size_t)(b * SEQ + t0 + i);
            float* yp = y_out + row * D_INNER + h * HEADDIM + p0;
            float4 y0 = *(const float4*)yp;
            float4 y1 = *(const float4*)(yp + 4);
            y0.x = fmaf(e, acc[ii][0], y0.x);
            y0.y = fmaf(e, acc[ii][1], y0.y);
            y0.z = fmaf(e, acc[ii][2], y0.z);
            y0.w = fmaf(e, acc[ii][3], y0.w);
            y1.x = fmaf(e, acc[ii][4], y1.x);
            y1.y = fmaf(e, acc[ii][5], y1.y);
            y1.z = fmaf(e, acc[ii][6], y1.z);
            y1.w = fmaf(e, acc[ii][7], y1.w);
            *(float4*)yp = y0;
            *(float4*)(yp + 4) = y1;
        }
    }
}

// ---- gate + RMSNorm -> bf16 hi/lo A-tiles (K=1024) -----------
__global__ __launch_bounds__(256) void gate_stage_kernel(
    const float* __restrict__ y, const float* __restrict__ zx,
    const float* __restrict__ gw, __nv_bfloat16* __restrict__ Ah,
    __nv_bfloat16* __restrict__ Al)
{
    int row = blockIdx.x;
    int tid = threadIdx.x;
    int d = tid * 4;
    __shared__ float sm[8];

    float4 y4 = *(const float4*)(y + (size_t)row * D_INNER + d);
    float4 z4 = *(const float4*)(zx + (size_t)row * D_IN_PROJ + d);
    float g0 = y4.x * siluf(z4.x);
    float g1 = y4.y * siluf(z4.y);
    float g2 = y4.z * siluf(z4.z);
    float g3 = y4.w * siluf(z4.w);

    float ss = g0 * g0 + g1 * g1 + g2 * g2 + g3 * g3;
    #pragma unroll
    for (int o = 16; o; o >>= 1) ss += __shfl_xor_sync(0xffffffffu, ss, o);
    if ((tid & 31) == 0) sm[tid >> 5] = ss;
    __syncthreads();
    float tot = 0.f;
    #pragma unroll
    for (int i = 0; i < 8; i++) tot += sm[i];
    float scale = rsqrtf(tot * (1.0f / (float)D_INNER) + EPS);

    float4 w4 = *(const float4*)(gw + d);
    float v0 = g0 * scale * w4.x, v1 = g1 * scale * w4.y;
    float v2 = g2 * scale * w4.z, v3 = g3 * scale * w4.w;

    uint32_t h0, l0, h1, l1, h2, l2, h3, l3;
    bf16_split(v0, h0, l0);
    bf16_split(v1, h1, l1);
    bf16_split(v2, h2, l2);
    bf16_split(v3, h3, l3);

    int ktile = d >> 7;
    int cl = d & 127;
    size_t tb = (size_t)((row >> 7) * 8 + ktile) * 32768;
    int r = row & 127;
    int off0 = toff128(r, cl);
    int off1 = toff128(r, cl + 2);
    *(uint32_t*)((char*)Ah + tb + off0) = h0 | (h1 << 16);
    *(uint32_t*)((char*)Al + tb + off0) = l0 | (l1 << 16);
    *(uint32_t*)((char*)Ah + tb + off1) = h2 | (h3 << 16);
    *(uint32_t*)((char*)Al + tb + off1) = l2 | (l3 << 16);
}

// ---------------- launch ----------------
extern "C" void kernel_launch(void* const* d_in, const int* in_sizes, int n_in,
                              void* d_out, int out_size)
{
    const float* hidden  = (const float*)d_in[0];
    const float* w_in    = (const float*)d_in[1];
    const float* conv_w  = (const float*)d_in[2];
    const float* conv_b  = (const float*)d_in[3];
    const float* dt_bias = (const float*)d_in[4];
    const float* A_log   = (const float*)d_in[5];
    const float* D_skip  = (const float*)d_in[6];
    const float* gnorm_w = (const float*)d_in[7];
    const float* w_out   = (const float*)d_in[8];
    const float* ln1_w   = (const float*)d_in[9];
    const float* ln1_b   = (const float*)d_in[10];
    const float* ln2_w   = (const float*)d_in[11];
    const float* ln2_b   = (const float*)d_in[12];
    const float* mlp_w   = (const float*)d_in[13];
    const float* mlp_b   = (const float*)d_in[14];
    float* outp = (float*)d_out;

    float *zx, *xbc, *dtT, *csv, *Gm, *Tm, *Spm, *Lam, *y, *res2;
    __nv_bfloat16 *af1h, *af1l, *aggh, *aggl, *ah2h, *ah2l;
    __nv_bfloat16 *bwinh, *bwinl, *bwouth, *bwoutl, *bwmlph, *bwmlpl;
    cudaGetSymbolAddress((void**)&zx,   g_zx);
    cudaGetSymbolAddress((void**)&xbc,  g_xbc);
    cudaGetSymbolAddress((void**)&dtT,  g_dtT);
    cudaGetSymbolAddress((void**)&csv,  g_cs);
    cudaGetSymbolAddress((void**)&Gm,   g_G);
    cudaGetSymbolAddress((void**)&Tm,   g_T);
    cudaGetSymbolAddress((void**)&Spm,  g_Sp);
    cudaGetSymbolAddress((void**)&Lam,  g_Lam);
    cudaGetSymbolAddress((void**)&y,    g_y);
    cudaGetSymbolAddress((void**)&res2, g_res2);
    cudaGetSymbolAddress((void**)&af1h, g_af1h);
    cudaGetSymbolAddress((void**)&af1l, g_af1l);
    cudaGetSymbolAddress((void**)&aggh, g_aggh);
    cudaGetSymbolAddress((void**)&aggl, g_aggl);
    cudaGetSymbolAddress((void**)&ah2h, g_ah2h);
    cudaGetSymbolAddress((void**)&ah2l, g_ah2l);
    cudaGetSymbolAddress((void**)&bwinh, g_bwinh);
    cudaGetSymbolAddress((void**)&bwinl, g_bwinl);
    cudaGetSymbolAddress((void**)&bwouth, g_bwouth);
    cudaGetSymbolAddress((void**)&bwoutl, g_bwoutl);
    cudaGetSymbolAddress((void**)&bwmlph, g_bwmlph);
    cudaGetSymbolAddress((void**)&bwmlpl, g_bwmlpl);

    const int smem_gemm1n = 1024 + 65536 + 65536;    // 132096
    const int smem_gemm1  = 1024 + BUF_STRIDE;       // 99328
    const int smem_gemm2  = 1024 + 2 * BUF_STRIDE;   // 197632
    const int smem_g      = (128 * 68 * 2) * 4;      // 69632
    const int smem_intra  = (QC * 68 + QC * 132 * 2 + 3 * QC) * 4;
    const int smem_out    = (128 * 68 + 128 * 132 + QC) * 4;
    cudaFuncSetAttribute(tc_gemm1,
        cudaFuncAttributeMaxDynamicSharedMemorySize, smem_gemm1n);
    cudaFuncSetAttribute(tc_gemm<true, false, 8>,
        cudaFuncAttributeMaxDynamicSharedMemorySize, smem_gemm2);
    cudaFuncSetAttribute(tc_gemm<false, true, 1>,
        cudaFuncAttributeMaxDynamicSharedMemorySize, smem_gemm1);
    cudaFuncSetAttribute(ssd_g_kernel,
        cudaFuncAttributeMaxDynamicSharedMemorySize, smem_g);
    cudaFuncSetAttribute(ssd_intra_kernel,
        cudaFuncAttributeMaxDynamicSharedMemorySize, smem_intra);
    cudaFuncSetAttribute(ssd_out_kernel,
        cudaFuncAttributeMaxDynamicSharedMemorySize, smem_out);

    // 0) prep: fused weight stages + ln1
    prep_kernel<<<W_TOTAL + LN1_BLK, 256>>>(
        w_in, w_out, mlp_w, bwinh, bwinl, bwouth, bwoutl, bwmlph, bwmlpl,
        hidden, ln1_w, ln1_b, af1h, af1l);

    // 1) in_proj (tcgen05, N=128/CTA)
    {
        dim3 grid(NT1 / 2, ROWS / 128);     // (19, 32)
        tc_gemm1<<<grid, 256, smem_gemm1n>>>(
            af1h, af1l, bwinh, bwinl, zx, D_IN_PROJ, D_IN_PROJ);
    }

    // 2) fused conv (vectorized) + dt/cumsum
    conv_dt_kernel<<<CONV_BLK + DT_BLK, 256>>>(
        zx, conv_w, conv_b, xbc, dt_bias, A_log, dtT, csv);

    // 3) chunked SSD
    {
        dim3 gg_(NCH, B_SZ);
        ssd_g_kernel<<<gg_, 256, smem_g>>>(xbc, Gm);
        dim3 gi(NCH / 2, NHEADS, B_SZ);
        ssd_intra_kernel<<<gi, 256, smem_intra>>>(xbc, dtT, csv, Gm, D_skip,
                                                  y, Tm, Lam);
        ssd_inter_kernel<<<(NBH * HEADDIM * D_STATE / 4) / 256, 256>>>(Tm, Lam, Spm);
        dim3 go(16, NHEADS, B_SZ);
        ssd_out_kernel<<<go, 256, smem_out>>>(xbc, csv, Spm, y);
    }

    // 4) gate + rmsnorm -> bf16 tiles
    gate_stage_kernel<<<ROWS, 256>>>(y, zx, gnorm_w, aggh, aggl);

    // 5) out_proj + residual (tcgen05, double-buffered K-loop 8)
    {
        dim3 grid(2, ROWS / 128);
        tc_gemm<true, false, 8><<<grid, 256, smem_gemm2>>>(
            aggh, aggl, bwouth, bwoutl, res2, D_MODEL, D_MODEL,
            hidden, nullptr);
    }

    // 6) ln2 -> bf16 tiles
    ln_stage_kernel<<<ROWS / 8, 256>>>(res2, ln2_w, ln2_b, ah2h, ah2l);

    // 7) mlp (tcgen05)
    {
        dim3 grid(2, ROWS / 128);
        tc_gemm<false, true, 1><<<grid, 256, smem_gemm1>>>(
            ah2h, ah2l, bwmlph, bwmlpl, outp, D_MODEL, D_MODEL,
            nullptr, mlp_b);
    }
    (void)in_sizes; (void)n_in; (void)out_size;
}

// round 17
// speedup vs baseline: 1.0935x; 1.0431x over previous
#include <cuda_runtime.h>
#include <cuda_bf16.h>
#include <cstdint>

#define B_SZ 2
#define SEQ 2048
#define ROWS (B_SZ * SEQ)          // 4096
#define D_MODEL 128
#define D_INNER 1024
#define NHEADS 8
#define HEADDIM 128
#define D_STATE 128
#define CONV_DIM (D_INNER + 2 * D_STATE)   // 1280
#define D_IN_PROJ (2 * D_INNER + 2 * D_STATE + NHEADS)  // 2312
#define EPS 1e-5f

#define QC 64
#define NCH (SEQ / QC)             // 32
#define NBH (B_SZ * NHEADS)        // 16

#define NT1 38                     // 38*64 = 2432 >= 2312; 19 tiles of 128

// prep (wstage + ln1) fused block ranges
#define WIN_BLK  ((NT1 * 64 * 64) / 256)     // 608
#define WOUT_BLK ((2 * 64 * 512) / 256)      // 256
#define WMLP_BLK ((2 * 64 * 64) / 256)       // 32
#define W_TOTAL  (WIN_BLK + WOUT_BLK + WMLP_BLK)   // 896
#define LN1_BLK  (ROWS / 8)                  // 512

// conv+dt fused block ranges (conv: 4ch x 4t per thread)
#define CONV_BLK ((B_SZ * (SEQ / 4) * (CONV_DIM / 4)) / 256)   // 1280
#define DT_BLK   ((NBH * NCH) / 4)                              // 128

#if defined(__CUDA_ARCH_FEAT_SM103_ALL) || defined(__CUDA_ARCH_FEAT_SM100_ALL) || defined(__CUDA_ARCH_FEAT_SM101_ALL)
#define HAS_TC 1
#else
#define HAS_TC 0
#endif

// ---------------- scratch ----------------
__device__ float g_zx[ROWS * D_IN_PROJ];
__device__ float g_xbc[ROWS * CONV_DIM];
__device__ float g_bT[B_SZ * NCH * D_STATE * QC];   // B transposed [b][c][n][t]
__device__ float g_cT[B_SZ * NCH * D_STATE * QC];   // C transposed [b][c][n][t]
__device__ float g_dtT[NBH * SEQ];
__device__ float g_cs[NBH * SEQ];
__device__ float g_G[B_SZ * NCH * QC * QC];
__device__ float g_T[NBH * NCH * HEADDIM * D_STATE];    // [n][p] layout
__device__ float g_Sp[NBH * NCH * HEADDIM * D_STATE];   // [n][p] layout
__device__ float g_Lam[NBH * NCH];
__device__ float g_y[ROWS * D_INNER];
__device__ float g_res2[ROWS * D_MODEL];

__device__ __nv_bfloat16 g_af1h[ROWS * D_MODEL];
__device__ __nv_bfloat16 g_af1l[ROWS * D_MODEL];
__device__ __nv_bfloat16 g_aggh[ROWS * D_INNER];
__device__ __nv_bfloat16 g_aggl[ROWS * D_INNER];
__device__ __nv_bfloat16 g_ah2h[ROWS * D_MODEL];
__device__ __nv_bfloat16 g_ah2l[ROWS * D_MODEL];
__device__ __nv_bfloat16 g_bwinh[NT1 * 64 * D_MODEL];
__device__ __nv_bfloat16 g_bwinl[NT1 * 64 * D_MODEL];
__device__ __nv_bfloat16 g_bwouth[2 * 8 * 64 * 128];
__device__ __nv_bfloat16 g_bwoutl[2 * 8 * 64 * 128];
__device__ __nv_bfloat16 g_bwmlph[2 * 64 * 128];
__device__ __nv_bfloat16 g_bwmlpl[2 * 64 * 128];

__device__ __forceinline__ float siluf(float v) {
    return v / (1.0f + expf(-v));
}

__device__ __forceinline__ int toff128(int r, int c) {
    int off = ((r >> 3) + (c >> 6) * 16) * 1024 + (r & 7) * 128 + (c & 63) * 2;
    return off ^ ((off >> 3) & 0x70);
}
__device__ __forceinline__ int toff64(int r, int c) {
    int off = ((r >> 3) + (c >> 6) * 8) * 1024 + (r & 7) * 128 + (c & 63) * 2;
    return off ^ ((off >> 3) & 0x70);
}

__device__ __forceinline__ void bf16_split(float v, uint32_t& hb, uint32_t& lb) {
    __nv_bfloat16 h = __float2bfloat16(v);
    float hf = __bfloat162float(h);
    __nv_bfloat16 l = __float2bfloat16(v - hf);
    hb = (uint32_t)__bfloat16_as_ushort(h);
    lb = (uint32_t)__bfloat16_as_ushort(l);
}

__device__ __forceinline__ void cp_async16(void* smem_dst, const void* gsrc) {
    unsigned saddr = (unsigned)__cvta_generic_to_shared(smem_dst);
    asm volatile("cp.async.cg.shared.global [%0], [%1], 16;" :: "r"(saddr), "l"(gsrc));
}
__device__ __forceinline__ void cp_commit() {
    asm volatile("cp.async.commit_group;");
}
template<int N>
__device__ __forceinline__ void cp_wait() {
    asm volatile("cp.async.wait_group %0;" :: "n"(N));
}

#if HAS_TC
__device__ __forceinline__ bool elect1() {
    uint32_t p;
    asm volatile("{\n\t.reg .pred p;\n\telect.sync _|p, 0xFFFFFFFF;\n\t"
                 "selp.b32 %0, 1, 0, p;\n\t}" : "=r"(p));
    return p != 0;
}
__device__ __forceinline__ void tc_alloc(uint32_t smem_res, uint32_t ncols) {
    asm volatile("tcgen05.alloc.cta_group::1.sync.aligned.shared::cta.b32 [%0], %1;"
                 :: "r"(smem_res), "r"(ncols) : "memory");
}
__device__ __forceinline__ void tc_dealloc(uint32_t tmem, uint32_t ncols) {
    asm volatile("tcgen05.dealloc.cta_group::1.sync.aligned.b32 %0, %1;"
                 :: "r"(tmem), "r"(ncols));
}
__device__ __forceinline__ void mbar_init(uint32_t mbar, uint32_t cnt) {
    asm volatile("mbarrier.init.shared.b64 [%0], %1;" :: "r"(mbar), "r"(cnt) : "memory");
}
__device__ __forceinline__ void mbar_wait(uint32_t mbar, uint32_t parity) {
    uint32_t done = 0;
    while (!done) {
        asm volatile(
            "{\n\t.reg .pred p;\n\t"
            "mbarrier.try_wait.parity.acquire.cta.shared::cta.b64 p, [%1], %2, 0x989680;\n\t"
            "selp.b32 %0, 1, 0, p;\n\t}"
            : "=r"(done) : "r"(mbar), "r"(parity) : "memory");
    }
}
__device__ __forceinline__ void tc_commit(uint32_t mbar) {
    asm volatile(
        "tcgen05.commit.cta_group::1.mbarrier::arrive::one.shared::cluster.b64 [%0];"
        :: "r"(mbar) : "memory");
}
__device__ __forceinline__ void mma_f16_ss(uint32_t d, uint64_t ad, uint64_t bd,
                                           uint32_t idesc, uint32_t en) {
    asm volatile(
        "{\n\t.reg .pred p;\n\tsetp.ne.u32 p, %5, 0;\n\t"
        "tcgen05.mma.cta_group::1.kind::f16 [%0], %1, %2, %3, {%4,%4,%4,%4}, p;\n\t}"
        :: "r"(d), "l"(ad), "l"(bd), "r"(idesc), "r"(0u), "r"(en) : "memory");
}
__device__ __forceinline__ uint64_t mk_desc(uint32_t saddr) {
    return ((uint64_t)2 << 61) | ((uint64_t)1 << 46) | ((uint64_t)64 << 32)
         | ((uint64_t)1 << 16) | (uint64_t)((saddr >> 4) & 0x3FFF);
}
__device__ __forceinline__ void ldtm_x32(uint32_t* r, uint32_t addr) {
    asm volatile(
        "tcgen05.ld.sync.aligned.32x32b.x32.b32 "
        "{%0,%1,%2,%3,%4,%5,%6,%7,%8,%9,%10,%11,%12,%13,%14,%15,"
        "%16,%17,%18,%19,%20,%21,%22,%23,%24,%25,%26,%27,%28,%29,%30,%31}, [%32];"
        : "=r"(r[0]), "=r"(r[1]), "=r"(r[2]), "=r"(r[3]),
          "=r"(r[4]), "=r"(r[5]), "=r"(r[6]), "=r"(r[7]),
          "=r"(r[8]), "=r"(r[9]), "=r"(r[10]), "=r"(r[11]),
          "=r"(r[12]), "=r"(r[13]), "=r"(r[14]), "=r"(r[15]),
          "=r"(r[16]), "=r"(r[17]), "=r"(r[18]), "=r"(r[19]),
          "=r"(r[20]), "=r"(r[21]), "=r"(r[22]), "=r"(r[23]),
          "=r"(r[24]), "=r"(r[25]), "=r"(r[26]), "=r"(r[27]),
          "=r"(r[28]), "=r"(r[29]), "=r"(r[30]), "=r"(r[31])
        : "r"(addr));
}
#endif // HAS_TC

#define TC_IDESC 0x8100490u
#define BUF_STRIDE 98304

// ---- gemm1: N=128 per CTA, KT=1; shares A tile across two N=64 MMA groups -
__global__ __launch_bounds__(256) void tc_gemm1(
    const __nv_bfloat16* __restrict__ Ah_, const __nv_bfloat16* __restrict__ Al_,
    const __nv_bfloat16* __restrict__ Bh_, const __nv_bfloat16* __restrict__ Bl_,
    float* __restrict__ C, int ldc, int N)
{
    extern __shared__ char smem[];
    const int tid = threadIdx.x;
    const int ntile = blockIdx.x, mtile = blockIdx.y;
    const uint32_t sbase = (uint32_t)__cvta_generic_to_shared(smem);

    const char* gAh = (const char*)Ah_ + (size_t)mtile * 32768;
    const char* gAl = (const char*)Al_ + (size_t)mtile * 32768;
    const char* gBh = (const char*)Bh_ + (size_t)(ntile * 2) * 16384;
    const char* gBl = (const char*)Bl_ + (size_t)(ntile * 2) * 16384;

#if HAS_TC
    const int wid = tid >> 5;
    const int lane = tid & 31;
    const uint32_t mbar = sbase + 8;

    if (wid == 0) tc_alloc(sbase, 128);
    if (tid == 0) mbar_init(mbar, 1);
    __syncthreads();
    uint32_t tmem;
    asm volatile("ld.shared.b32 %0, [%1];" : "=r"(tmem) : "r"(sbase));

    char* base = smem + 1024;
    #pragma unroll 4
    for (int i = tid; i < 2048; i += 256) {
        cp_async16(base + i * 16, gAh + i * 16);
        cp_async16(base + 32768 + i * 16, gAl + i * 16);
    }
    #pragma unroll 4
    for (int i = tid; i < 2048; i += 256) {   // B0H|B0L|B1H|B1L
        int half = i >> 10;
        int j = i & 1023;
        cp_async16(base + 65536 + half * 32768 + j * 16, gBh + (half ? 16384 : 0) + j * 16);
        cp_async16(base + 81920 + half * 32768 + j * 16, gBl + (half ? 16384 : 0) + j * 16);
    }
    cp_commit();
    cp_wait<0>();
    __syncthreads();
    asm volatile("fence.proxy.async.shared::cta;" ::: "memory");

    if (wid == 0) {
        asm volatile("tcgen05.fence::after_thread_sync;" ::: "memory");
        if (elect1()) {
            uint64_t dAh = mk_desc(sbase + 1024);
            uint64_t dAl = mk_desc(sbase + 1024 + 32768);
            uint64_t dB0h = mk_desc(sbase + 1024 + 65536);
            uint64_t dB0l = mk_desc(sbase + 1024 + 81920);
            uint64_t dB1h = mk_desc(sbase + 1024 + 98304);
            uint64_t dB1l = mk_desc(sbase + 1024 + 114688);
            #pragma unroll
            for (int ks = 0; ks < 8; ks++) {
                uint64_t oA = (ks < 4) ? (uint64_t)(ks * 2) : (uint64_t)(1024 + (ks - 4) * 2);
                uint64_t oB = (ks < 4) ? (uint64_t)(ks * 2) : (uint64_t)(512 + (ks - 4) * 2);
                uint32_t en = ks ? 1u : 0u;
                mma_f16_ss(tmem, dAh + oA, dB0h + oB, TC_IDESC, en);
                mma_f16_ss(tmem, dAh + oA, dB0l + oB, TC_IDESC, 1u);
                mma_f16_ss(tmem, dAl + oA, dB0h + oB, TC_IDESC, 1u);
                mma_f16_ss(tmem + 64, dAh + oA, dB1h + oB, TC_IDESC, en);
                mma_f16_ss(tmem + 64, dAh + oA, dB1l + oB, TC_IDESC, 1u);
                mma_f16_ss(tmem + 64, dAl + oA, dB1h + oB, TC_IDESC, 1u);
            }
            tc_commit(mbar);
        }
    }
    mbar_wait(mbar, 0);
    asm volatile("tcgen05.fence::after_thread_sync;" ::: "memory");

    uint32_t d0[32], d1[32];
    int chalf = (wid >> 2) * 32;
    ldtm_x32(d0, tmem + chalf);
    ldtm_x32(d1, tmem + 64 + chalf);
    asm volatile("tcgen05.wait::ld.sync.aligned;" ::: "memory");

    int row = mtile * 128 + (wid & 3) * 32 + lane;
    #pragma unroll
    for (int g = 0; g < 2; g++) {
        uint32_t* d = g ? d1 : d0;
        int col0 = ntile * 128 + g * 64 + chalf;
        float* cp = C + (size_t)row * ldc + col0;
        #pragma unroll
        for (int c = 0; c < 32; c += 4) {
            int col = col0 + c;
            if (col < N) {
                float4 v = make_float4(__uint_as_float(d[c]), __uint_as_float(d[c + 1]),
                                       __uint_as_float(d[c + 2]), __uint_as_float(d[c + 3]));
                *(float4*)(cp + c) = v;
            }
        }
    }
    __syncthreads();
    if (wid == 0) tc_dealloc(tmem, 128);
#else
    const int half = tid >> 7;
    const int r128 = tid & 127;
    char* base = smem + 1024;
    #pragma unroll 4
    for (int i = tid; i < 2048; i += 256) {
        cp_async16(base + i * 16, gAh + i * 16);
        cp_async16(base + 32768 + i * 16, gAl + i * 16);
    }
    for (int i = tid; i < 2048; i += 256) {
        int hh = i >> 10;
        int j = i & 1023;
        cp_async16(base + 65536 + hh * 32768 + j * 16, gBh + (hh ? 16384 : 0) + j * 16);
        cp_async16(base + 81920 + hh * 32768 + j * 16, gBl + (hh ? 16384 : 0) + j * 16);
    }
    cp_commit();
    cp_wait<0>();
    __syncthreads();

    for (int g = 0; g < 2; g++) {
        float vals[32];
        #pragma unroll
        for (int c = 0; c < 32; c++) vals[c] = 0.f;
        char* bB = base + 65536 + g * 32768;
        for (int k = 0; k < 128; k++) {
            int ao = toff128(r128, k);
            float a = __bfloat162float(*(const __nv_bfloat16*)(base + ao))
                    + __bfloat162float(*(const __nv_bfloat16*)(base + 32768 + ao));
            for (int n = 0; n < 32; n++) {
                int bo = toff64(half * 32 + n, k);
                float b = __bfloat162float(*(const __nv_bfloat16*)(bB + bo))
                        + __bfloat162float(*(const __nv_bfloat16*)(bB + 16384 + bo));
                vals[n] = fmaf(a, b, vals[n]);
            }
        }
        int row = mtile * 128 + r128;
        int col0 = ntile * 128 + g * 64 + half * 32;
        float* cp = C + (size_t)row * ldc + col0;
        for (int c = 0; c < 32; c++) {
            int col = col0 + c;
            if (col < N) cp[c] = vals[c];
        }
    }
#endif
}

// ---------------- GEMM (N=64/CTA): gemm2 (KT=8, dbuf) & gemm3 (KT=1) -------
template<bool RESID, bool BIAS, int KT>
__global__ __launch_bounds__(256) void tc_gemm(
    const __nv_bfloat16* __restrict__ Ah_, const __nv_bfloat16* __restrict__ Al_,
    const __nv_bfloat16* __restrict__ Bh_, const __nv_bfloat16* __restrict__ Bl_,
    float* __restrict__ C, int ldc, int N,
    const float* __restrict__ resid, const float* __restrict__ bias)
{
    extern __shared__ char smem[];
    const int tid = threadIdx.x;
    const int ntile = blockIdx.x, mtile = blockIdx.y;
    const uint32_t sbase = (uint32_t)__cvta_generic_to_shared(smem);

    const char* gAh = (const char*)Ah_ + (size_t)(mtile * KT) * 32768;
    const char* gAl = (const char*)Al_ + (size_t)(mtile * KT) * 32768;
    const char* gBh = (const char*)Bh_ + (size_t)(ntile * KT) * 16384;
    const char* gBl = (const char*)Bl_ + (size_t)(ntile * KT) * 16384;

    auto load_tile = [&](int kt, int buf) {
        char* base = smem + 1024 + buf * BUF_STRIDE;
        const char* ah = gAh + (size_t)kt * 32768;
        const char* al = gAl + (size_t)kt * 32768;
        const char* bh = gBh + (size_t)kt * 16384;
        const char* bl = gBl + (size_t)kt * 16384;
        #pragma unroll 4
        for (int i = tid; i < 2048; i += 256) {
            cp_async16(base + i * 16, ah + i * 16);
            cp_async16(base + 32768 + i * 16, al + i * 16);
        }
        #pragma unroll 2
        for (int i = tid; i < 1024; i += 256) {
            cp_async16(base + 65536 + i * 16, bh + i * 16);
            cp_async16(base + 81920 + i * 16, bl + i * 16);
        }
        cp_commit();
    };

#if HAS_TC
    const int wid = tid >> 5;
    const int lane = tid & 31;
    const uint32_t mbar = sbase + 8;

    if (wid == 0) tc_alloc(sbase, 64);
    if (tid == 0) mbar_init(mbar, 1);
    __syncthreads();
    uint32_t tmem;
    asm volatile("ld.shared.b32 %0, [%1];" : "=r"(tmem) : "r"(sbase));

    load_tile(0, 0);
    #pragma unroll 1
    for (int kt = 0; kt < KT; kt++) {
        int buf = (KT > 1) ? (kt & 1) : 0;
        if (KT > 1 && kt + 1 < KT) {
            load_tile(kt + 1, buf ^ 1);
            cp_wait<1>();
        } else {
            cp_wait<0>();
        }
        __syncthreads();
        asm volatile("fence.proxy.async.shared::cta;" ::: "memory");

        if (wid == 0) {
            asm volatile("tcgen05.fence::after_thread_sync;" ::: "memory");
            if (elect1()) {
                uint32_t bb = sbase + 1024 + buf * BUF_STRIDE;
                uint64_t dAh = mk_desc(bb);
                uint64_t dAl = mk_desc(bb + 32768);
                uint64_t dBh = mk_desc(bb + 65536);
                uint64_t dBl = mk_desc(bb + 81920);
                #pragma unroll
                for (int ks = 0; ks < 8; ks++) {
                    uint64_t oA = (ks < 4) ? (uint64_t)(ks * 2) : (uint64_t)(1024 + (ks - 4) * 2);
                    uint64_t oB = (ks < 4) ? (uint64_t)(ks * 2) : (uint64_t)(512 + (ks - 4) * 2);
                    uint32_t en = (kt || ks) ? 1u : 0u;
                    mma_f16_ss(tmem, dAh + oA, dBh + oB, TC_IDESC, en);
                    mma_f16_ss(tmem, dAh + oA, dBl + oB, TC_IDESC, 1u);
                    mma_f16_ss(tmem, dAl + oA, dBh + oB, TC_IDESC, 1u);
                }
                tc_commit(mbar);
            }
        }
        mbar_wait(mbar, kt & 1);
    }
    asm volatile("tcgen05.fence::after_thread_sync;" ::: "memory");

    uint32_t d[32];
    int chalf = (wid >> 2) * 32;
    ldtm_x32(d, tmem + chalf);
    asm volatile("tcgen05.wait::ld.sync.aligned;" ::: "memory");

    int row = mtile * 128 + (wid & 3) * 32 + lane;
    int col0 = ntile * 64 + chalf;
    float* cp = C + (size_t)row * ldc + col0;
    #pragma unroll
    for (int c = 0; c < 32; c += 4) {
        int col = col0 + c;
        if (col < N) {
            float4 v = make_float4(__uint_as_float(d[c]), __uint_as_float(d[c + 1]),
                                   __uint_as_float(d[c + 2]), __uint_as_float(d[c + 3]));
            if (RESID) {
                float4 r = *(const float4*)(resid + (size_t)row * ldc + col);
                v.x += r.x; v.y += r.y; v.z += r.z; v.w += r.w;
            }
            if (BIAS) {
                float4 b = *(const float4*)(bias + col);
                v.x += b.x; v.y += b.y; v.z += b.z; v.w += b.w;
            }
            *(float4*)(cp + c) = v;
        }
    }
    __syncthreads();
    if (wid == 0) tc_dealloc(tmem, 64);
#else
    const int half = tid >> 7;
    const int r128 = tid & 127;
    float vals[32];
    #pragma unroll
    for (int c = 0; c < 32; c++) vals[c] = 0.f;

    for (int kt = 0; kt < KT; kt++) {
        load_tile(kt, 0);
        cp_wait<0>();
        __syncthreads();
        char* base = smem + 1024;
        for (int k = 0; k < 128; k++) {
            int ao = toff128(r128, k);
            float a = __bfloat162float(*(const __nv_bfloat16*)(base + ao))
                    + __bfloat162float(*(const __nv_bfloat16*)(base + 32768 + ao));
            for (int n = 0; n < 32; n++) {
                int bo = toff64(half * 32 + n, k);
                float b = __bfloat162float(*(const __nv_bfloat16*)(base + 65536 + bo))
                        + __bfloat162float(*(const __nv_bfloat16*)(base + 81920 + bo));
                vals[n] = fmaf(a, b, vals[n]);
            }
        }
        __syncthreads();
    }
    int row = mtile * 128 + r128;
    int col0 = ntile * 64 + half * 32;
    float* cp = C + (size_t)row * ldc + col0;
    for (int c = 0; c < 32; c++) {
        int col = col0 + c;
        if (col < N) {
            float v = vals[c];
            if (RESID) v += resid[(size_t)row * ldc + col];
            if (BIAS)  v += bias[col];
            cp[c] = v;
        }
    }
#endif
}

// ------ LayerNorm body (warp-per-row) ------
__device__ __forceinline__ void ln_row(
    const float* __restrict__ x, const float* __restrict__ w,
    const float* __restrict__ b, __nv_bfloat16* __restrict__ Ah,
    __nv_bfloat16* __restrict__ Al, int row, int lane)
{
    const int c0 = lane * 4;
    float4 v = *(const float4*)(x + (size_t)row * D_MODEL + c0);
    float s = v.x + v.y + v.z + v.w;
    #pragma unroll
    for (int o = 16; o; o >>= 1) s += __shfl_xor_sync(0xffffffffu, s, o);
    float mean = s * (1.0f / 128.0f);

    float d0 = v.x - mean, d1 = v.y - mean, d2 = v.z - mean, d3 = v.w - mean;
    float q = d0 * d0 + d1 * d1 + d2 * d2 + d3 * d3;
    #pragma unroll
    for (int o = 16; o; o >>= 1) q += __shfl_xor_sync(0xffffffffu, q, o);
    float inv = rsqrtf(q * (1.0f / 128.0f) + EPS);

    float4 wv = *(const float4*)(w + c0);
    float4 bv = *(const float4*)(b + c0);
    float o0 = fmaf(d0 * inv, wv.x, bv.x);
    float o1 = fmaf(d1 * inv, wv.y, bv.y);
    float o2 = fmaf(d2 * inv, wv.z, bv.z);
    float o3 = fmaf(d3 * inv, wv.w, bv.w);

    uint32_t h0, l0, h1, l1, h2, l2, h3, l3;
    bf16_split(o0, h0, l0);
    bf16_split(o1, h1, l1);
    bf16_split(o2, h2, l2);
    bf16_split(o3, h3, l3);

    size_t tb = (size_t)(row >> 7) * 32768;
    int r = row & 127;
    int off0 = toff128(r, c0);
    int off1 = toff128(r, c0 + 2);
    *(uint32_t*)((char*)Ah + tb + off0) = h0 | (h1 << 16);
    *(uint32_t*)((char*)Al + tb + off0) = l0 | (l1 << 16);
    *(uint32_t*)((char*)Ah + tb + off1) = h2 | (h3 << 16);
    *(uint32_t*)((char*)Al + tb + off1) = l2 | (l3 << 16);
}

__global__ __launch_bounds__(256) void ln_stage_kernel(
    const float* __restrict__ x, const float* __restrict__ w,
    const float* __restrict__ b, __nv_bfloat16* __restrict__ Ah,
    __nv_bfloat16* __restrict__ Al)
{
    ln_row(x, w, b, Ah, Al, blockIdx.x * 8 + (threadIdx.x >> 5), threadIdx.x & 31);
}

// ------- W staging helper -------
__device__ __forceinline__ void wstage_do(
    const float* __restrict__ W, int Nreal, int K, int idx,
    __nv_bfloat16* __restrict__ Bh, __nv_bfloat16* __restrict__ Bl)
{
    int pairs_per_row = K >> 1;
    int n = idx / pairs_per_row;
    int k0 = (idx - n * pairs_per_row) * 2;
    float v0 = (n < Nreal) ? W[(size_t)n * K + k0] : 0.f;
    float v1 = (n < Nreal) ? W[(size_t)n * K + k0 + 1] : 0.f;
    uint32_t h0, l0, h1, l1;
    bf16_split(v0, h0, l0);
    bf16_split(v1, h1, l1);
    int ktiles = K >> 7;
    size_t tb = (size_t)((n >> 6) * ktiles + (k0 >> 7)) * 16384;
    int off = toff64(n & 63, k0 & 127);
    *(uint32_t*)((char*)Bh + tb + off) = h0 | (h1 << 16);
    *(uint32_t*)((char*)Bl + tb + off) = l0 | (l1 << 16);
}

// ---- prep: fused wstage x3 + ln1 ----
__global__ __launch_bounds__(256) void prep_kernel(
    const float* __restrict__ w_in, const float* __restrict__ w_out,
    const float* __restrict__ mlp_w,
    __nv_bfloat16* __restrict__ winh, __nv_bfloat16* __restrict__ winl,
    __nv_bfloat16* __restrict__ wouth, __nv_bfloat16* __restrict__ woutl,
    __nv_bfloat16* __restrict__ wmlph, __nv_bfloat16* __restrict__ wmlpl,
    const float* __restrict__ hidden, const float* __restrict__ ln1_w,
    const float* __restrict__ ln1_b,
    __nv_bfloat16* __restrict__ af1h, __nv_bfloat16* __restrict__ af1l)
{
    int bx = blockIdx.x;
    if (bx < WIN_BLK) {
        wstage_do(w_in, D_IN_PROJ, D_MODEL, bx * 256 + threadIdx.x, winh, winl);
    } else if (bx < WIN_BLK + WOUT_BLK) {
        wstage_do(w_out, D_MODEL, D_INNER, (bx - WIN_BLK) * 256 + threadIdx.x,
                  wouth, woutl);
    } else if (bx < W_TOTAL) {
        wstage_do(mlp_w, D_MODEL, D_MODEL, (bx - WIN_BLK - WOUT_BLK) * 256 + threadIdx.x,
                  wmlph, wmlpl);
    } else {
        int row = (bx - W_TOTAL) * 8 + (threadIdx.x >> 5);
        ln_row(hidden, ln1_w, ln1_b, af1h, af1l, row, threadIdx.x & 31);
    }
}

// ---- fused: conv (4ch x 4t float4, + transposed B/C emission) + dt/cumsum -
__global__ __launch_bounds__(256) void conv_dt_kernel(
    const float* __restrict__ zx, const float* __restrict__ cw,
    const float* __restrict__ cb, float* __restrict__ out,
    float* __restrict__ bT, float* __restrict__ cT,
    const float* __restrict__ dt_bias, const float* __restrict__ A_log,
    float* __restrict__ dt_out, float* __restrict__ cs_out)
{
    __shared__ float s[4][QC];
    int bx = blockIdx.x;
    if (bx < CONV_BLK) {
        int idx = bx * 256 + threadIdx.x;
        int c4 = (idx % (CONV_DIM / 4)) * 4;
        int r = idx / (CONV_DIM / 4);
        int tq = r & ((SEQ / 4) - 1);
        int b = r / (SEQ / 4);
        int t0 = tq * 4;

        const float* col = zx + (size_t)b * SEQ * D_IN_PROJ + D_INNER + c4;
        float4 xv[7];
        #pragma unroll
        for (int k = 0; k < 7; k++) {
            int t = t0 - 3 + k;
            xv[k] = (t >= 0) ? *(const float4*)(col + (size_t)t * D_IN_PROJ)
                             : make_float4(0.f, 0.f, 0.f, 0.f);
        }
        float4 w[4];
        #pragma unroll
        for (int l = 0; l < 4; l++) w[l] = *(const float4*)(cw + (c4 + l) * 4);
        float4 bias4 = *(const float4*)(cb + c4);

        float4 oo[4];
        float* ob = out + ((size_t)(b * SEQ + t0)) * CONV_DIM + c4;
        #pragma unroll
        for (int j = 0; j < 4; j++) {
            #pragma unroll
            for (int l = 0; l < 4; l++) {
                float acc = (&bias4.x)[l];
                acc = fmaf(w[l].x, (&xv[j].x)[l], acc);
                acc = fmaf(w[l].y, (&xv[j + 1].x)[l], acc);
                acc = fmaf(w[l].z, (&xv[j + 2].x)[l], acc);
                acc = fmaf(w[l].w, (&xv[j + 3].x)[l], acc);
                (&oo[j].x)[l] = siluf(acc);
            }
            *(float4*)(ob + (size_t)j * CONV_DIM) = oo[j];
        }

        // transposed emission for B/C channels: 4x4 register transpose
        int cc = c4 - D_INNER;
        if (cc >= 0) {
            float* dstbuf = (cc < D_STATE) ? bT : cT;
            int n4 = (cc < D_STATE) ? cc : cc - D_STATE;
            int ch = t0 >> 6;
            int tl = t0 & 63;
            float* dbase = dstbuf + ((size_t)(b * NCH + ch) * D_STATE + n4) * QC + tl;
            #pragma unroll
            for (int l = 0; l < 4; l++) {
                float4 tv = make_float4((&oo[0].x)[l], (&oo[1].x)[l],
                                        (&oo[2].x)[l], (&oo[3].x)[l]);
                *(float4*)(dbase + (size_t)l * QC) = tv;
            }
        }
    } else {
        int g = threadIdx.x >> 6;
        int t = threadIdx.x & 63;
        int blk4 = (bx - CONV_BLK) * 4 + g;
        int bh = blk4 >> 5;
        int ch = blk4 & (NCH - 1);
        int b = bh >> 3;
        int h = bh & 7;

        int row = b * SEQ + ch * QC + t;
        float raw = zx[(size_t)row * D_IN_PROJ + (D_IN_PROJ - NHEADS) + h] + dt_bias[h];
        float dt = (raw > 20.0f) ? raw : log1pf(expf(raw));
        float A = -expf(A_log[h]);
        size_t o = (size_t)bh * SEQ + ch * QC + t;
        dt_out[o] = dt;
        s[g][t] = dt * A;
        __syncthreads();
        #pragma unroll
        for (int off = 1; off < QC; off <<= 1) {
            float v = (t >= off) ? s[g][t - off] : 0.f;
            __syncthreads();
            s[g][t] += v;
            __syncthreads();
        }
        cs_out[o] = s[g][t];
    }
}

// -------- K_G: reads pre-transposed B/C (straight vector copies) ----------
__global__ __launch_bounds__(256) void ssd_g_kernel(
    const float* __restrict__ bT, const float* __restrict__ cT,
    float* __restrict__ G)
{
    extern __shared__ float sm[];
    float* Cn = sm;                  // [128][68]
    float* Bn = sm + 128 * 68;       // [128][68]

    int c = blockIdx.x, b = blockIdx.y;
    int tid = threadIdx.x;
    size_t tbase = (size_t)(b * NCH + c) * D_STATE * QC;

    for (int q = tid; q < 128 * 16; q += 256) {
        int n = q >> 4;
        int t4 = (q & 15) * 4;
        *(float4*)&Bn[n * 68 + t4] = *(const float4*)(bT + tbase + (size_t)n * QC + t4);
        *(float4*)&Cn[n * 68 + t4] = *(const float4*)(cT + tbase + (size_t)n * QC + t4);
    }
    __syncthreads();

    int ty = tid >> 4, tx = tid & 15;
    int i0 = ty * 4, j0 = tx * 4;
    float acc[4][4];
    #pragma unroll
    for (int i = 0; i < 4; i++)
        #pragma unroll
        for (int j = 0; j < 4; j++) acc[i][j] = 0.f;

    #pragma unroll 4
    for (int n = 0; n < D_STATE; n++) {
        float4 cv = *(const float4*)&Cn[n * 68 + i0];
        float4 bv = *(const float4*)&Bn[n * 68 + j0];
        float cf[4] = {cv.x, cv.y, cv.z, cv.w};
        float bf[4] = {bv.x, bv.y, bv.z, bv.w};
        #pragma unroll
        for (int i = 0; i < 4; i++)
            #pragma unroll
            for (int j = 0; j < 4; j++)
                acc[i][j] = fmaf(cf[i], bf[j], acc[i][j]);
    }

    float* Gp = G + (size_t)(b * NCH + c) * QC * QC;
    #pragma unroll
    for (int i = 0; i < 4; i++) {
        float4 v = make_float4(acc[i][0], acc[i][1], acc[i][2], acc[i][3]);
        *(float4*)(Gp + (i0 + i) * QC + j0) = v;
    }
}

// ------------ K_intra: 2 chunks per block; T stored [n][p] ------------
__global__ __launch_bounds__(256) void ssd_intra_kernel(
    const float* __restrict__ xbc, const float* __restrict__ dt_t,
    const float* __restrict__ cs_g, const float* __restrict__ G,
    const float* __restrict__ D_skip,
    float* __restrict__ y_out, float* __restrict__ T_out,
    float* __restrict__ Lam_out)
{
    extern __shared__ float sm[];
    float* Wt = sm;
    float* Xj = Wt + QC * 68;
    float* Bj = Xj + QC * 132;
    float* s_cs = Bj + QC * 132;
    float* s_dt = s_cs + QC;
    float* s_el = s_dt + QC;

    int h = blockIdx.y, b = blockIdx.z;
    int tid = threadIdx.x;
    int bh = b * NHEADS + h;
    int ty = tid >> 4, tx = tid & 15;
    float Dsk = D_skip[h];

    for (int cc = 0; cc < 2; cc++) {
        int c = blockIdx.x + cc * 16;
        int t0 = c * QC;
        if (cc) __syncthreads();

        if (tid < QC) {
            s_cs[tid] = cs_g[(size_t)bh * SEQ + t0 + tid];
            s_dt[tid] = dt_t[(size_t)bh * SEQ + t0 + tid];
        }
        __syncthreads();
        if (tid < QC) s_el[tid] = __expf(s_cs[QC - 1] - s_cs[tid]) * s_dt[tid];
        if (tid == 0) Lam_out[bh * NCH + c] = __expf(s_cs[QC - 1]);

        for (int q = tid; q < QC * 32; q += 256) {
            int t = q >> 5;
            int n4 = (q & 31) * 4;
            const float* row = xbc + (size_t)(b * SEQ + t0 + t) * CONV_DIM;
            *(float4*)&Xj[t * 132 + n4] = *(const float4*)(row + h * HEADDIM + n4);
            *(float4*)&Bj[t * 132 + n4] = *(const float4*)(row + D_INNER + n4);
        }
        __syncthreads();

        {
            int i0 = ty * 4, j0 = tx * 4;
            const float* Gp = G + (size_t)(b * NCH + c) * QC * QC;
            #pragma unroll
            for (int ii = 0; ii < 4; ii++) {
                int i = i0 + ii;
                float4 gv = *(const float4*)(Gp + i * QC + j0);
                float gf[4] = {gv.x, gv.y, gv.z, gv.w};
                #pragma unroll
                for (int jj = 0; jj < 4; jj++) {
                    int j = j0 + jj;
                    float w = 0.f;
                    if (j <= i) w = __expf(s_cs[i] - s_cs[j]) * s_dt[j] * gf[jj];
                    Wt[j * 68 + i] = w;
                }
            }
        }
        __syncthreads();

        {
            int i0 = ty * 4, p0 = tx * 8;
            float acc[4][8];
            #pragma unroll
            for (int i = 0; i < 4; i++)
                #pragma unroll
                for (int p = 0; p < 8; p++) acc[i][p] = 0.f;

            int jmax = i0 + 4;
            for (int j = 0; j < jmax; j++) {
                float4 wv = *(const float4*)&Wt[j * 68 + i0];
                float4 xa = *(const float4*)&Xj[j * 132 + p0];
                float4 xb = *(const float4*)&Xj[j * 132 + p0 + 4];
                float wf[4] = {wv.x, wv.y, wv.z, wv.w};
                float xf[8] = {xa.x, xa.y, xa.z, xa.w, xb.x, xb.y, xb.z, xb.w};
                #pragma unroll
                for (int i = 0; i < 4; i++)
                    #pragma unroll
                    for (int p = 0; p < 8; p++)
                        acc[i][p] = fmaf(wf[i], xf[p], acc[i][p]);
            }
            #pragma unroll
            for (int ii = 0; ii < 4; ii++) {
                int i = i0 + ii;
                size_t row = (size_t)(b * SEQ + t0 + i);
                float* yp = y_out + row * D_INNER + h * HEADDIM + p0;
                float4 x0 = *(const float4*)&Xj[i * 132 + p0];
                float4 x1 = *(const float4*)&Xj[i * 132 + p0 + 4];
                float4 o0 = make_float4(fmaf(Dsk, x0.x, acc[ii][0]),
                                        fmaf(Dsk, x0.y, acc[ii][1]),
                                        fmaf(Dsk, x0.z, acc[ii][2]),
                                        fmaf(Dsk, x0.w, acc[ii][3]));
                float4 o1 = make_float4(fmaf(Dsk, x1.x, acc[ii][4]),
                                        fmaf(Dsk, x1.y, acc[ii][5]),
                                        fmaf(Dsk, x1.z, acc[ii][6]),
                                        fmaf(Dsk, x1.w, acc[ii][7]));
                *(float4*)yp = o0;
                *(float4*)(yp + 4) = o1;
            }
        }

        {
            int p0 = ty * 8, n0 = tx * 8;
            float acc[8][8];
            #pragma unroll
            for (int p = 0; p < 8; p++)
                #pragma unroll
                for (int n = 0; n < 8; n++) acc[p][n] = 0.f;

            #pragma unroll 2
            for (int j = 0; j < QC; j++) {
                float el = s_el[j];
                float4 xa = *(const float4*)&Xj[j * 132 + p0];
                float4 xb = *(const float4*)&Xj[j * 132 + p0 + 4];
                float4 ba = *(const float4*)&Bj[j * 132 + n0];
                float4 bb = *(const float4*)&Bj[j * 132 + n0 + 4];
                float xf[8] = {el * xa.x, el * xa.y, el * xa.z, el * xa.w,
                               el * xb.x, el * xb.y, el * xb.z, el * xb.w};
                float bf[8] = {ba.x, ba.y, ba.z, ba.w, bb.x, bb.y, bb.z, bb.w};
                #pragma unroll
                for (int p = 0; p < 8; p++)
                    #pragma unroll
                    for (int n = 0; n < 8; n++)
                        acc[p][n] = fmaf(xf[p], bf[n], acc[p][n]);
            }
            // T stored transposed [n][p]
            float* Tp = T_out + ((size_t)bh * NCH + c) * (HEADDIM * D_STATE);
            #pragma unroll
            for (int nn = 0; nn < 8; nn++) {
                float4 v0 = make_float4(acc[0][nn], acc[1][nn], acc[2][nn], acc[3][nn]);
                float4 v1 = make_float4(acc[4][nn], acc[5][nn], acc[6][nn], acc[7][nn]);
                *(float4*)(Tp + (size_t)(n0 + nn) * HEADDIM + p0) = v0;
                *(float4*)(Tp + (size_t)(n0 + nn) * HEADDIM + p0 + 4) = v1;
            }
        }
    }
}

// ---------------- K_inter (layout-agnostic elementwise) ----------------
__global__ __launch_bounds__(256) void ssd_inter_kernel(
    const float* __restrict__ T, const float* __restrict__ Lam,
    float* __restrict__ Sp)
{
    int gid = blockIdx.x * 256 + threadIdx.x;
    int bh = gid >> 12;
    int pn = gid & 4095;
    const float4* Tb = (const float4*)(T + ((size_t)bh << 19)) + pn;
    float4* Sb = (float4*)(Sp + ((size_t)bh << 19)) + pn;
    const float* Lb = Lam + bh * NCH;

    float4 S = make_float4(0.f, 0.f, 0.f, 0.f);
    #pragma unroll 4
    for (int c = 0; c < NCH; c++) {
        if (c) Sb[(size_t)c << 12] = S;
        float4 Tv = Tb[(size_t)c << 12];
        float lam = Lb[c];
        S.x = fmaf(lam, S.x, Tv.x);
        S.y = fmaf(lam, S.y, Tv.y);
        S.z = fmaf(lam, S.z, Tv.z);
        S.w = fmaf(lam, S.w, Tv.w);
    }
}

// ---- K_out: 2 chunks/block; Sp [n][p] direct; C from pre-transposed cT ----
__global__ __launch_bounds__(256) void ssd_out_kernel(
    const float* __restrict__ cT, const float* __restrict__ cs_g,
    const float* __restrict__ Sp, float* __restrict__ y_out)
{
    extern __shared__ float sm[];
    float* Cn = sm;
    float* Spn = Cn + 128 * 68;
    float* s_cs = Spn + 128 * 132;

    int h = blockIdx.y, b = blockIdx.z;
    int tid = threadIdx.x;
    int bh = b * NHEADS + h;
    int ty = tid >> 4, tx = tid & 15;
    int i0 = ty * 4, p0 = tx * 8;

    for (int cc = 0; cc < 2; cc++) {
        int c = blockIdx.x + 1 + cc * 16;
        if (c >= NCH) break;
        int t0 = c * QC;
        if (cc) __syncthreads();

        if (tid < QC) s_cs[tid] = cs_g[(size_t)bh * SEQ + t0 + tid];

        // C from pre-transposed buffer: straight vector copy
        size_t ctbase = (size_t)(b * NCH + c) * D_STATE * QC;
        for (int q = tid; q < 128 * 16; q += 256) {
            int n = q >> 4;
            int t4 = (q & 15) * 4;
            *(float4*)&Cn[n * 68 + t4] =
                *(const float4*)(cT + ctbase + (size_t)n * QC + t4);
        }
        // Sp already [n][p]: straight vector copy
        const float* Spsrc = Sp + ((size_t)bh * NCH + c) * (HEADDIM * D_STATE);
        for (int q = tid; q < HEADDIM * 32; q += 256) {
            int n = q >> 5;
            int p4 = (q & 31) * 4;
            *(float4*)&Spn[n * 132 + p4] =
                *(const float4*)(Spsrc + (size_t)n * HEADDIM + p4);
        }
        __syncthreads();

        float acc[4][8];
        #pragma unroll
        for (int i = 0; i < 4; i++)
            #pragma unroll
            for (int p = 0; p < 8; p++) acc[i][p] = 0.f;

        #pragma unroll 2
        for (int n = 0; n < D_STATE; n++) {
            float4 cv = *(const float4*)&Cn[n * 68 + i0];
            float4 sa = *(const float4*)&Spn[n * 132 + p0];
            float4 sb = *(const float4*)&Spn[n * 132 + p0 + 4];
            float cf[4] = {cv.x, cv.y, cv.z, cv.w};
            float sf[8] = {sa.x, sa.y, sa.z, sa.w, sb.x, sb.y, sb.z, sb.w};
            #pragma unroll
            for (int i = 0; i < 4; i++)
                #pragma unroll
                for (int p = 0; p < 8; p++)
                    acc[i][p] = fmaf(cf[i], sf[p], acc[i][p]);
        }

        #pragma unroll
        for (int ii = 0; ii < 4; ii++) {
            int i = i0 + ii;
            float e = __expf(s_cs[i]);
            size_t row = (size_t)(b * SEQ + t0 + i);
            float* yp = y_out + row * D_INNER + h * HEADDIM + p0;
            float4 y0 = *(const float4*)yp;
            float4 y1 = *(const float4*)(yp + 4);
            y0.x = fmaf(e, acc[ii][0], y0.x);
            y0.y = fmaf(e, acc[ii][1], y0.y);
            y0.z = fmaf(e, acc[ii][2], y0.z);
            y0.w = fmaf(e, acc[ii][3], y0.w);
            y1.x = fmaf(e, acc[ii][4], y1.x);
            y1.y = fmaf(e, acc[ii][5], y1.y);
            y1.z = fmaf(e, acc[ii][6], y1.z);
            y1.w = fmaf(e, acc[ii][7], y1.w);
            *(float4*)yp = y0;
            *(float4*)(yp + 4) = y1;
        }
    }
}

// ---- gate + RMSNorm -> bf16 hi/lo A-tiles (K=1024) -----------
__global__ __launch_bounds__(256) void gate_stage_kernel(
    const float* __restrict__ y, const float* __restrict__ zx,
    const float* __restrict__ gw, __nv_bfloat16* __restrict__ Ah,
    __nv_bfloat16* __restrict__ Al)
{
    int row = blockIdx.x;
    int tid = threadIdx.x;
    int d = tid * 4;
    __shared__ float sm[8];

    float4 y4 = *(const float4*)(y + (size_t)row * D_INNER + d);
    float4 z4 = *(const float4*)(zx + (size_t)row * D_IN_PROJ + d);
    float g0 = y4.x * siluf(z4.x);
    float g1 = y4.y * siluf(z4.y);
    float g2 = y4.z * siluf(z4.z);
    float g3 = y4.w * siluf(z4.w);

    float ss = g0 * g0 + g1 * g1 + g2 * g2 + g3 * g3;
    #pragma unroll
    for (int o = 16; o; o >>= 1) ss += __shfl_xor_sync(0xffffffffu, ss, o);
    if ((tid & 31) == 0) sm[tid >> 5] = ss;
    __syncthreads();
    float tot = 0.f;
    #pragma unroll
    for (int i = 0; i < 8; i++) tot += sm[i];
    float scale = rsqrtf(tot * (1.0f / (float)D_INNER) + EPS);

    float4 w4 = *(const float4*)(gw + d);
    float v0 = g0 * scale * w4.x, v1 = g1 * scale * w4.y;
    float v2 = g2 * scale * w4.z, v3 = g3 * scale * w4.w;

    uint32_t h0, l0, h1, l1, h2, l2, h3, l3;
    bf16_split(v0, h0, l0);
    bf16_split(v1, h1, l1);
    bf16_split(v2, h2, l2);
    bf16_split(v3, h3, l3);

    int ktile = d >> 7;
    int cl = d & 127;
    size_t tb = (size_t)((row >> 7) * 8 + ktile) * 32768;
    int r = row & 127;
    int off0 = toff128(r, cl);
    int off1 = toff128(r, cl + 2);
    *(uint32_t*)((char*)Ah + tb + off0) = h0 | (h1 << 16);
    *(uint32_t*)((char*)Al + tb + off0) = l0 | (l1 << 16);
    *(uint32_t*)((char*)Ah + tb + off1) = h2 | (h3 << 16);
    *(uint32_t*)((char*)Al + tb + off1) = l2 | (l3 << 16);
}

// ---------------- launch ----------------
extern "C" void kernel_launch(void* const* d_in, const int* in_sizes, int n_in,
                              void* d_out, int out_size)
{
    const float* hidden  = (const float*)d_in[0];
    const float* w_in    = (const float*)d_in[1];
    const float* conv_w  = (const float*)d_in[2];
    const float* conv_b  = (const float*)d_in[3];
    const float* dt_bias = (const float*)d_in[4];
    const float* A_log   = (const float*)d_in[5];
    const float* D_skip  = (const float*)d_in[6];
    const float* gnorm_w = (const float*)d_in[7];
    const float* w_out   = (const float*)d_in[8];
    const float* ln1_w   = (const float*)d_in[9];
    const float* ln1_b   = (const float*)d_in[10];
    const float* ln2_w   = (const float*)d_in[11];
    const float* ln2_b   = (const float*)d_in[12];
    const float* mlp_w   = (const float*)d_in[13];
    const float* mlp_b   = (const float*)d_in[14];
    float* outp = (float*)d_out;

    float *zx, *xbc, *bT, *cT, *dtT, *csv, *Gm, *Tm, *Spm, *Lam, *y, *res2;
    __nv_bfloat16 *af1h, *af1l, *aggh, *aggl, *ah2h, *ah2l;
    __nv_bfloat16 *bwinh, *bwinl, *bwouth, *bwoutl, *bwmlph, *bwmlpl;
    cudaGetSymbolAddress((void**)&zx,   g_zx);
    cudaGetSymbolAddress((void**)&xbc,  g_xbc);
    cudaGetSymbolAddress((void**)&bT,   g_bT);
    cudaGetSymbolAddress((void**)&cT,   g_cT);
    cudaGetSymbolAddress((void**)&dtT,  g_dtT);
    cudaGetSymbolAddress((void**)&csv,  g_cs);
    cudaGetSymbolAddress((void**)&Gm,   g_G);
    cudaGetSymbolAddress((void**)&Tm,   g_T);
    cudaGetSymbolAddress((void**)&Spm,  g_Sp);
    cudaGetSymbolAddress((void**)&Lam,  g_Lam);
    cudaGetSymbolAddress((void**)&y,    g_y);
    cudaGetSymbolAddress((void**)&res2, g_res2);
    cudaGetSymbolAddress((void**)&af1h, g_af1h);
    cudaGetSymbolAddress((void**)&af1l, g_af1l);
    cudaGetSymbolAddress((void**)&aggh, g_aggh);
    cudaGetSymbolAddress((void**)&aggl, g_aggl);
    cudaGetSymbolAddress((void**)&ah2h, g_ah2h);
    cudaGetSymbolAddress((void**)&ah2l, g_ah2l);
    cudaGetSymbolAddress((void**)&bwinh, g_bwinh);
    cudaGetSymbolAddress((void**)&bwinl, g_bwinl);
    cudaGetSymbolAddress((void**)&bwouth, g_bwouth);
    cudaGetSymbolAddress((void**)&bwoutl, g_bwoutl);
    cudaGetSymbolAddress((void**)&bwmlph, g_bwmlph);
    cudaGetSymbolAddress((void**)&bwmlpl, g_bwmlpl);

    const int smem_gemm1n = 1024 + 65536 + 65536;    // 132096
    const int smem_gemm1  = 1024 + BUF_STRIDE;       // 99328
    const int smem_gemm2  = 1024 + 2 * BUF_STRIDE;   // 197632
    const int smem_g      = (128 * 68 * 2) * 4;      // 69632
    const int smem_intra  = (QC * 68 + QC * 132 * 2 + 3 * QC) * 4;
    const int smem_out    = (128 * 68 + 128 * 132 + QC) * 4;
    cudaFuncSetAttribute(tc_gemm1,
        cudaFuncAttributeMaxDynamicSharedMemorySize, smem_gemm1n);
    cudaFuncSetAttribute(tc_gemm<true, false, 8>,
        cudaFuncAttributeMaxDynamicSharedMemorySize, smem_gemm2);
    cudaFuncSetAttribute(tc_gemm<false, true, 1>,
        cudaFuncAttributeMaxDynamicSharedMemorySize, smem_gemm1);
    cudaFuncSetAttribute(ssd_g_kernel,
        cudaFuncAttributeMaxDynamicSharedMemorySize, smem_g);
    cudaFuncSetAttribute(ssd_intra_kernel,
        cudaFuncAttributeMaxDynamicSharedMemorySize, smem_intra);
    cudaFuncSetAttribute(ssd_out_kernel,
        cudaFuncAttributeMaxDynamicSharedMemorySize, smem_out);

    // 0) prep: fused weight stages + ln1
    prep_kernel<<<W_TOTAL + LN1_BLK, 256>>>(
        w_in, w_out, mlp_w, bwinh, bwinl, bwouth, bwoutl, bwmlph, bwmlpl,
        hidden, ln1_w, ln1_b, af1h, af1l);

    // 1) in_proj (tcgen05, N=128/CTA)
    {
        dim3 grid(NT1 / 2, ROWS / 128);     // (19, 32)
        tc_gemm1<<<grid, 256, smem_gemm1n>>>(
            af1h, af1l, bwinh, bwinl, zx, D_IN_PROJ, D_IN_PROJ);
    }

    // 2) fused conv (+ transposed B/C emission) + dt/cumsum
    conv_dt_kernel<<<CONV_BLK + DT_BLK, 256>>>(
        zx, conv_w, conv_b, xbc, bT, cT, dt_bias, A_log, dtT, csv);

    // 3) chunked SSD
    {
        dim3 gg_(NCH, B_SZ);
        ssd_g_kernel<<<gg_, 256, smem_g>>>(bT, cT, Gm);
        dim3 gi(NCH / 2, NHEADS, B_SZ);
        ssd_intra_kernel<<<gi, 256, smem_intra>>>(xbc, dtT, csv, Gm, D_skip,
                                                  y, Tm, Lam);
        ssd_inter_kernel<<<(NBH * HEADDIM * D_STATE / 4) / 256, 256>>>(Tm, Lam, Spm);
        dim3 go(16, NHEADS, B_SZ);
        ssd_out_kernel<<<go, 256, smem_out>>>(cT, csv, Spm, y);
    }

    // 4) gate + rmsnorm -> bf16 tiles
    gate_stage_kernel<<<ROWS, 256>>>(y, zx, gnorm_w, aggh, aggl);

    // 5) out_proj + residual (tcgen05, double-buffered K-loop 8)
    {
        dim3 grid(2, ROWS / 128);
        tc_gemm<true, false, 8><<<grid, 256, smem_gemm2>>>(
            aggh, aggl, bwouth, bwoutl, res2, D_MODEL, D_MODEL,
            hidden, nullptr);
    }

    // 6) ln2 -> bf16 tiles
    ln_stage_kernel<<<ROWS / 8, 256>>>(res2, ln2_w, ln2_b, ah2h, ah2l);

    // 7) mlp (tcgen05)
    {
        dim3 grid(2, ROWS / 128);
        tc_gemm<false, true, 1><<<grid, 256, smem_gemm1>>>(
            ah2h, ah2l, bwmlph, bwmlpl, outp, D_MODEL, D_MODEL,
            nullptr, mlp_b);
    }
    (void)in_sizes; (void)n_in; (void)out_size;
}